// round 2
// baseline (speedup 1.0000x reference)
#include <cuda_runtime.h>
#include <math.h>
#include <stdint.h>

// ---------------- problem constants ----------------
#define Bq      8
#define Lq      2048
#define Tq      (Bq*Lq)        // 16384 tokens
#define DMv     320
#define DIv     1280
#define NST     16
#define DCONVK  8
#define DTRANK  20
#define XDv     52             // DTRANK + 2*NST
#define NBLK    4

typedef unsigned long long ull;

// ---------------- static device scratch (no allocations) ----------------
__device__ __align__(256) float g_bufA [Tq*DMv];          // inter-block activations
__device__ __align__(256) float g_u    [Tq*DMv];          // post-tanh
__device__ __align__(256) float g_xz   [(size_t)Tq*2*DIv];// inproj out (x | z)
__device__ __align__(256) float g_xconv[(size_t)Tq*DIv];  // post conv+silu
__device__ __align__(256) float g_dbc  [Tq*XDv];          // dt | B | C
__device__ __align__(256) float g_delta[(size_t)Tq*DIv];  // softplus(dt proj)
__device__ __align__(256) float g_y    [(size_t)Tq*DIv];  // scan output
__device__ float g_startmax;

// ---------------- f32x2 helpers ----------------
__device__ __forceinline__ ull ffma2q(ull a, ull b, ull c){
    ull d; asm("fma.rn.f32x2 %0, %1, %2, %3;" : "=l"(d) : "l"(a), "l"(b), "l"(c)); return d;
}
__device__ __forceinline__ ull pk2(float x, float y){
    ull r; asm("mov.b64 %0, {%1, %2};" : "=l"(r) : "f"(x), "f"(y)); return r;
}
__device__ __forceinline__ float2 upk2(ull v){
    float x, y; asm("mov.b64 {%0, %1}, %2;" : "=f"(x), "=f"(y) : "l"(v));
    return make_float2(x, y);
}

// ---------------- start_max reduction ----------------
__global__ void k_startmax(const float* __restrict__ x){
    __shared__ float red[256];
    float m = -1e30f;
    for (int i = threadIdx.x; i < Tq; i += 256) m = fmaxf(m, x[i*4 + 2]);
    red[threadIdx.x] = m; __syncthreads();
    for (int s = 128; s > 0; s >>= 1){
        if (threadIdx.x < s) red[threadIdx.x] = fmaxf(red[threadIdx.x], red[threadIdx.x + s]);
        __syncthreads();
    }
    if (threadIdx.x == 0) g_startmax = red[0];
}

// ---------------- embedding: normalize + fc (K=4) ----------------
__global__ void k_embed(const float* __restrict__ x, const float* __restrict__ fcw,
                        const float* __restrict__ fcb){
    int t = blockIdx.x, c = threadIdx.x;      // grid Tq, block DMv
    float x0 = x[t*4+0], x1 = x[t*4+1], x2 = x[t*4+2], x3 = x[t*4+3];
    float n0 = x0 * (1.0f/255.0f), n1 = x1 * (1.0f/255.0f), n2 = x2 / g_startmax, n3 = x3;
    const float* w = fcw + c*4;
    g_bufA[(size_t)t*DMv + c] = fcb[c] + n0*w[0] + n1*w[1] + n2*w[2] + n3*w[3];
}

// ---------------- tiled GEMM: C = act(A[M,K] @ W[N,K]^T (+bias)) ----------------
// ACT: 0 none, 1 tanh, 2 softplus, 3 elu
template<int ACT>
__global__ void __launch_bounds__(256, 2) k_gemm(
    const float* __restrict__ A, int lda,
    const float* __restrict__ W,
    const float* __restrict__ bias,
    float* __restrict__ C, int ldc,
    int M, int N, int K)
{
    // A duplicated as (a,a) pairs so FFMA2 operands come straight from LDS.128
    __shared__ __align__(16) float2 As2[8][128];
    __shared__ __align__(16) float  Ws_[8][128];

    int tid = threadIdx.x;
    int bm0 = blockIdx.y * 128, bn0 = blockIdx.x * 128;
    int tx = tid & 15, ty = tid >> 4;
    int arow = tid >> 1;
    int ac4  = (tid & 1) * 4;

    ull acc2[8][4];
    #pragma unroll
    for (int i = 0; i < 8; i++)
        #pragma unroll
        for (int j = 0; j < 4; j++) acc2[i][j] = 0ULL;

    for (int k0 = 0; k0 < K; k0 += 8) {
        // ---- load A tile (128 rows x 8 k) ----
        {
            int gm = bm0 + arow, gk = k0 + ac4;
            float4 av = make_float4(0.f, 0.f, 0.f, 0.f);
            if (gm < M) {
                const float* ap = A + (size_t)gm * lda;
                if (gk + 3 < K) av = *(const float4*)(ap + gk);
                else {
                    if (gk     < K) av.x = ap[gk];
                    if (gk + 1 < K) av.y = ap[gk+1];
                    if (gk + 2 < K) av.z = ap[gk+2];
                    if (gk + 3 < K) av.w = ap[gk+3];
                }
            }
            As2[ac4+0][arow] = make_float2(av.x, av.x);
            As2[ac4+1][arow] = make_float2(av.y, av.y);
            As2[ac4+2][arow] = make_float2(av.z, av.z);
            As2[ac4+3][arow] = make_float2(av.w, av.w);
        }
        // ---- load W tile (128 rows x 8 k) ----
        {
            int gn = bn0 + arow, gk = k0 + ac4;
            float4 wv = make_float4(0.f, 0.f, 0.f, 0.f);
            if (gn < N) {
                const float* wp = W + (size_t)gn * K;
                if (gk + 3 < K) wv = *(const float4*)(wp + gk);
                else {
                    if (gk     < K) wv.x = wp[gk];
                    if (gk + 1 < K) wv.y = wp[gk+1];
                    if (gk + 2 < K) wv.z = wp[gk+2];
                    if (gk + 3 < K) wv.w = wp[gk+3];
                }
            }
            Ws_[ac4+0][arow] = wv.x;
            Ws_[ac4+1][arow] = wv.y;
            Ws_[ac4+2][arow] = wv.z;
            Ws_[ac4+3][arow] = wv.w;
        }
        __syncthreads();

        #pragma unroll
        for (int kk = 0; kk < 8; kk++) {
            ull aa[8];
            *(ulonglong2*)&aa[0] = *(ulonglong2*)&As2[kk][ty*8 + 0];
            *(ulonglong2*)&aa[2] = *(ulonglong2*)&As2[kk][ty*8 + 2];
            *(ulonglong2*)&aa[4] = *(ulonglong2*)&As2[kk][ty*8 + 4];
            *(ulonglong2*)&aa[6] = *(ulonglong2*)&As2[kk][ty*8 + 6];
            float4 w0 = *(float4*)&Ws_[kk][tx*8];
            float4 w1 = *(float4*)&Ws_[kk][tx*8 + 4];
            ull bp0 = pk2(w0.x, w0.y), bp1 = pk2(w0.z, w0.w);
            ull bp2 = pk2(w1.x, w1.y), bp3 = pk2(w1.z, w1.w);
            #pragma unroll
            for (int i = 0; i < 8; i++) {
                acc2[i][0] = ffma2q(aa[i], bp0, acc2[i][0]);
                acc2[i][1] = ffma2q(aa[i], bp1, acc2[i][1]);
                acc2[i][2] = ffma2q(aa[i], bp2, acc2[i][2]);
                acc2[i][3] = ffma2q(aa[i], bp3, acc2[i][3]);
            }
        }
        __syncthreads();
    }

    // ---- epilogue ----
    #pragma unroll
    for (int i = 0; i < 8; i++) {
        int m = bm0 + ty*8 + i;
        if (m >= M) continue;
        float* crow = C + (size_t)m * ldc;
        #pragma unroll
        for (int j = 0; j < 4; j++) {
            float2 p = upk2(acc2[i][j]);
            int n0 = bn0 + tx*8 + j*2;
            #pragma unroll
            for (int h = 0; h < 2; h++) {
                int n = n0 + h;
                if (n >= N) continue;
                float v = (h == 0) ? p.x : p.y;
                if (bias) v += bias[n];
                if (ACT == 1)       v = tanhf(v);
                else if (ACT == 2)  v = (v > 20.f) ? v : log1pf(expf(v));
                else if (ACT == 3)  v = (v > 0.f) ? v : expm1f(v);
                crow[n] = v;
            }
        }
    }
}

// ---------------- depthwise causal conv (k=8) + bias + silu ----------------
// grid: (Tq/16, DIv/256), block 256. Each thread: 1 channel, 16 timesteps.
__global__ void k_conv(const float* __restrict__ cw, const float* __restrict__ cb){
    int ch = blockIdx.y * 256 + threadIdx.x;
    int t0 = blockIdx.x * 16;
    int l0 = t0 & (Lq - 1);          // Lq % 16 == 0, so group never crosses batch
    int tb = t0 - l0;                // batch base token

    float w[8];
    #pragma unroll
    for (int j = 0; j < 8; j++) w[j] = cw[ch*8 + j];
    float bv = cb[ch];

    float v[23];
    #pragma unroll
    for (int j = 0; j < 23; j++) {
        int l = l0 - 7 + j;
        v[j] = (l >= 0) ? g_xz[(size_t)(tb + l) * (2*DIv) + ch] : 0.f;
    }
    #pragma unroll
    for (int o = 0; o < 16; o++) {
        float s = bv;
        #pragma unroll
        for (int j = 0; j < 8; j++) s = fmaf(v[o + j], w[j], s);
        float sil = s / (1.f + __expf(-s));
        g_xconv[(size_t)(t0 + o) * DIv + ch] = sil;
    }
}

// ---------------- selective scan (serial over L) ----------------
// grid: (DIv/128, Bq), block 128. One thread per (b, ch).
__global__ void __launch_bounds__(128) k_scan(const float* __restrict__ Alog,
                                              const float* __restrict__ Dw){
    int b  = blockIdx.y;
    int ch = blockIdx.x * 128 + threadIdx.x;

    __shared__ float sBC[64][32];   // 64-step window of B(16)|C(16), shared per b

    float a[NST];
    #pragma unroll
    for (int n = 0; n < NST; n++) a[n] = -expf(Alog[ch*NST + n]);
    float Dd = Dw[ch];

    float h[NST];
    #pragma unroll
    for (int n = 0; n < NST; n++) h[n] = 0.f;

    const float* dbc = g_dbc + (size_t)b * Lq * XDv;

    for (int w = 0; w < Lq/64; w++) {
        __syncthreads();
        for (int idx = threadIdx.x; idx < 64*32; idx += 128) {
            int s = idx >> 5, c = idx & 31;
            sBC[s][c] = dbc[(w*64 + s) * XDv + DTRANK + c];
        }
        __syncthreads();

        for (int s = 0; s < 64; s++) {
            size_t t = (size_t)(b * Lq + w*64 + s);
            float delta = g_delta[t*DIv + ch];
            float xv    = g_xconv[t*DIv + ch];
            float dx = delta * xv;
            float y = 0.f;
            #pragma unroll
            for (int n = 0; n < NST; n++) {
                float dA = __expf(delta * a[n]);
                h[n] = fmaf(dA, h[n], dx * sBC[s][n]);
                y = fmaf(h[n], sBC[s][NST + n], y);
            }
            float z = g_xz[t*(2*DIv) + DIv + ch];
            float yy = fmaf(xv, Dd, y);
            g_y[t*DIv + ch] = yy * (z / (1.f + __expf(-z)));
        }
    }
}

// ---------------- head MLP (M=8): 320 -> 512 -> 512 -> 1 ----------------
__global__ void __launch_bounds__(512) k_head(
    const float* __restrict__ w1, const float* __restrict__ b1,
    const float* __restrict__ w2, const float* __restrict__ b2,
    const float* __restrict__ w3, const float* __restrict__ b3,
    float* __restrict__ out)
{
    __shared__ float sh [8][320];
    __shared__ float sh1[8][512];
    __shared__ float sh2[8][512];
    int tid = threadIdx.x;

    for (int idx = tid; idx < 8*320; idx += 512) {
        int bb = idx / 320, c = idx % 320;
        sh[bb][c] = g_bufA[((size_t)bb * Lq + Lq - 1) * DMv + c];
    }
    __syncthreads();

    {   // layer 1: 320 -> 512, relu
        int n = tid;
        float acc[8];
        #pragma unroll
        for (int bb = 0; bb < 8; bb++) acc[bb] = 0.f;
        const float* wr = w1 + (size_t)n * 320;
        for (int k = 0; k < 320; k++) {
            float wv = wr[k];
            #pragma unroll
            for (int bb = 0; bb < 8; bb++) acc[bb] = fmaf(wv, sh[bb][k], acc[bb]);
        }
        #pragma unroll
        for (int bb = 0; bb < 8; bb++) sh1[bb][n] = fmaxf(acc[bb] + b1[n], 0.f);
    }
    __syncthreads();

    {   // layer 2: 512 -> 512, relu
        int n = tid;
        float acc[8];
        #pragma unroll
        for (int bb = 0; bb < 8; bb++) acc[bb] = 0.f;
        const float* wr = w2 + (size_t)n * 512;
        for (int k = 0; k < 512; k++) {
            float wv = wr[k];
            #pragma unroll
            for (int bb = 0; bb < 8; bb++) acc[bb] = fmaf(wv, sh1[bb][k], acc[bb]);
        }
        #pragma unroll
        for (int bb = 0; bb < 8; bb++) sh2[bb][n] = fmaxf(acc[bb] + b2[n], 0.f);
    }
    __syncthreads();

    if (tid < 8) {
        float acc = 0.f;
        for (int k = 0; k < 512; k++) acc = fmaf(w3[k], sh2[tid][k], acc);
        acc += b3[0];
        float scale = g_startmax / (1.f + logf((float)Lq));
        out[tid] = fmaxf(acc * scale, 0.f);
    }
}

// ---------------- host launch ----------------
extern "C" void kernel_launch(void* const* d_in, const int* in_sizes, int n_in,
                              void* d_out, int out_size)
{
    const float* x            = (const float*)d_in[0];
    const float* fc_w         = (const float*)d_in[1];
    const float* fc_b         = (const float*)d_in[2];
    const float* blk_lin_w    = (const float*)d_in[3];
    const float* blk_lin_b    = (const float*)d_in[4];
    const float* blk_inproj_w = (const float*)d_in[5];
    const float* blk_conv_w   = (const float*)d_in[6];
    const float* blk_conv_b   = (const float*)d_in[7];
    const float* blk_xproj_w  = (const float*)d_in[8];
    const float* blk_dtproj_w = (const float*)d_in[9];
    const float* blk_dtproj_b = (const float*)d_in[10];
    const float* blk_A_log    = (const float*)d_in[11];
    const float* blk_D        = (const float*)d_in[12];
    const float* blk_outproj_w= (const float*)d_in[13];
    const float* s1_w1        = (const float*)d_in[14];
    const float* s1_b1        = (const float*)d_in[15];
    const float* s1_w2        = (const float*)d_in[16];
    const float* s1_b2        = (const float*)d_in[17];
    const float* s1_w3        = (const float*)d_in[18];
    const float* s1_b3        = (const float*)d_in[19];

    void* p;
    cudaGetSymbolAddress(&p, g_bufA);  float* bufA  = (float*)p;
    cudaGetSymbolAddress(&p, g_u);     float* u     = (float*)p;
    cudaGetSymbolAddress(&p, g_xz);    float* xz    = (float*)p;
    cudaGetSymbolAddress(&p, g_xconv); float* xconv = (float*)p;
    cudaGetSymbolAddress(&p, g_dbc);   float* dbc   = (float*)p;
    cudaGetSymbolAddress(&p, g_delta); float* delta = (float*)p;
    cudaGetSymbolAddress(&p, g_y);     float* y     = (float*)p;

    k_startmax<<<1, 256>>>(x);
    k_embed<<<Tq, DMv>>>(x, fc_w, fc_b);

    for (int i = 0; i < NBLK; i++) {
        // lin: tanh(bufA @ lin_w^T + lin_b) -> u   [Tq,320] K=320
        k_gemm<1><<<dim3(3, Tq/128), 256>>>(
            bufA, DMv,
            blk_lin_w + (size_t)i*DMv*DMv,
            blk_lin_b + (size_t)i*DMv,
            u, DMv, Tq, DMv, DMv);

        // inproj: u @ inproj_w^T -> xz   [Tq,2560] K=320
        k_gemm<0><<<dim3(20, Tq/128), 256>>>(
            u, DMv,
            blk_inproj_w + (size_t)i*2*DIv*DMv,
            (const float*)nullptr,
            xz, 2*DIv, Tq, 2*DIv, DMv);

        // depthwise causal conv + silu -> xconv
        k_conv<<<dim3(Tq/16, DIv/256), 256>>>(
            blk_conv_w + (size_t)i*DIv*DCONVK,
            blk_conv_b + (size_t)i*DIv);

        // xproj: xconv @ xproj_w^T -> dbc   [Tq,52] K=1280
        k_gemm<0><<<dim3(1, Tq/128), 256>>>(
            xconv, DIv,
            blk_xproj_w + (size_t)i*XDv*DIv,
            (const float*)nullptr,
            dbc, XDv, Tq, XDv, DIv);

        // dtproj: softplus(dbc[:, :20] @ dtproj_w^T + dtproj_b) -> delta   [Tq,1280] K=20
        k_gemm<2><<<dim3(10, Tq/128), 256>>>(
            dbc, XDv,
            blk_dtproj_w + (size_t)i*DIv*DTRANK,
            blk_dtproj_b + (size_t)i*DIv,
            delta, DIv, Tq, DIv, DTRANK);

        // selective scan -> y
        k_scan<<<dim3(DIv/128, Bq), 128>>>(
            blk_A_log + (size_t)i*DIv*NST,
            blk_D + (size_t)i*DIv);

        // outproj: elu(y @ outproj_w^T) -> bufA   [Tq,320] K=1280
        k_gemm<3><<<dim3(3, Tq/128), 256>>>(
            y, DIv,
            blk_outproj_w + (size_t)i*DMv*DIv,
            (const float*)nullptr,
            bufA, DMv, Tq, DMv, DIv);
    }

    k_head<<<1, 512>>>(s1_w1, s1_b1, s1_w2, s1_b2, s1_w3, s1_b3, (float*)d_out);
}

// round 4
// speedup vs baseline: 1.5917x; 1.5917x over previous
#include <cuda_runtime.h>
#include <math.h>
#include <stdint.h>

// ---------------- problem constants ----------------
#define Bq      8
#define Lq      2048
#define Tq      (Bq*Lq)        // 16384 tokens
#define DMv     320
#define DIv     1280
#define NST     16
#define DCONVK  8
#define DTRANK  20
#define XDv     52             // DTRANK + 2*NST
#define NBLK    4

typedef uint32_t u32;

// ---------------- static device scratch (no allocations) ----------------
__device__ __align__(256) float g_bufA [Tq*DMv];
__device__ __align__(256) float g_u    [Tq*DMv];
__device__ __align__(256) float g_xz   [(size_t)Tq*2*DIv];
__device__ __align__(256) float g_xconv[(size_t)Tq*DIv];
__device__ __align__(256) float g_dbc  [Tq*XDv];
__device__ __align__(256) float g_delta[(size_t)Tq*DIv];
__device__ __align__(256) float g_y    [(size_t)Tq*DIv];
__device__ float g_startmax;

// ---------------- helpers ----------------
__device__ __forceinline__ float tf32r(float x){
    u32 o; asm("cvt.rna.tf32.f32 %0, %1;" : "=r"(o) : "f"(x));
    return __uint_as_float(o);
}
__device__ __forceinline__ void mma8(float* c, const u32* a, const u32* b){
    asm volatile("mma.sync.aligned.m16n8k8.row.col.f32.tf32.tf32.f32 "
        "{%0,%1,%2,%3}, {%4,%5,%6,%7}, {%8,%9}, {%0,%1,%2,%3};"
        : "+f"(c[0]), "+f"(c[1]), "+f"(c[2]), "+f"(c[3])
        : "r"(a[0]), "r"(a[1]), "r"(a[2]), "r"(a[3]), "r"(b[0]), "r"(b[1]));
}

// ---------------- start_max reduction ----------------
__global__ void k_startmax(const float* __restrict__ x){
    __shared__ float red[256];
    float m = -1e30f;
    for (int i = threadIdx.x; i < Tq; i += 256) m = fmaxf(m, x[i*4 + 2]);
    red[threadIdx.x] = m; __syncthreads();
    for (int s = 128; s > 0; s >>= 1){
        if (threadIdx.x < s) red[threadIdx.x] = fmaxf(red[threadIdx.x], red[threadIdx.x + s]);
        __syncthreads();
    }
    if (threadIdx.x == 0) g_startmax = red[0];
}

// ---------------- embedding: normalize + fc (K=4) ----------------
__global__ void k_embed(const float* __restrict__ x, const float* __restrict__ fcw,
                        const float* __restrict__ fcb){
    int t = blockIdx.x, c = threadIdx.x;      // grid Tq, block DMv
    float x0 = x[t*4+0], x1 = x[t*4+1], x2 = x[t*4+2], x3 = x[t*4+3];
    float n0 = x0 * (1.0f/255.0f), n1 = x1 * (1.0f/255.0f), n2 = x2 / g_startmax, n3 = x3;
    const float* w = fcw + c*4;
    g_bufA[(size_t)t*DMv + c] = fcb[c] + n0*w[0] + n1*w[1] + n2*w[2] + n3*w[3];
}

// ---------------- epilogue activation ----------------
template<int ACT> __device__ __forceinline__ float actf(float v){
    if (ACT == 1) return tanhf(v);
    if (ACT == 2) return (v > 20.f) ? v : log1pf(expf(v));
    if (ACT == 3) return (v > 0.f) ? v : expm1f(v);
    return v;
}

// ---------------- tf32 mma.sync GEMM: C = act(A[M,K] @ W[N,K]^T (+bias)) ----------------
// CTA tile 128x64, BK=16, 128 threads (4 warps, 2x2 layout, each 64x32).
// Smem k-major, strides 136/72 (== 8 mod 32 -> conflict-free fragment LDS).
// M % 128 == 0 required; N, K arbitrary (zero-padded).
#define AS_STR 136
#define BS_STR 72

template<int ACT>
__global__ void __launch_bounds__(128) k_mgemm(
    const float* __restrict__ A, int lda,
    const float* __restrict__ W,
    const float* __restrict__ bias,
    float* __restrict__ C, int ldc,
    int M, int N, int K)
{
    __shared__ float As[2][16][AS_STR];
    __shared__ float Bs[2][16][BS_STR];

    int tid  = threadIdx.x;
    int lane = tid & 31, w = tid >> 5;
    int wm = (w >> 1) * 64, wn = (w & 1) * 32;
    int g = lane >> 2, ti = lane & 3;
    int bm0 = blockIdx.y * 128, bn0 = blockIdx.x * 64;

    float acc[4][4][4];
    #pragma unroll
    for (int i = 0; i < 4; i++)
        #pragma unroll
        for (int j = 0; j < 4; j++)
            #pragma unroll
            for (int r = 0; r < 4; r++) acc[i][j][r] = 0.f;

    int nit = (K + 15) / 16;

    float4 av[4], bv[4];

    // ---- load tile 'it' into registers ----
    auto ldg = [&](int it){
        int k0 = it * 16, rem = K - k0;
        const float* ap = A + (size_t)(bm0 + tid) * lda + k0;
        if (rem >= 16) {
            av[0] = *(const float4*)(ap + 0);
            av[1] = *(const float4*)(ap + 4);
            av[2] = *(const float4*)(ap + 8);
            av[3] = *(const float4*)(ap + 12);
        } else {
            #pragma unroll
            for (int j = 0; j < 4; j++) {
                int kc = j * 4;
                av[j].x = (kc   < rem) ? ap[kc]   : 0.f;
                av[j].y = (kc+1 < rem) ? ap[kc+1] : 0.f;
                av[j].z = (kc+2 < rem) ? ap[kc+2] : 0.f;
                av[j].w = (kc+3 < rem) ? ap[kc+3] : 0.f;
            }
        }
        if (tid < 64) {
            int gn = bn0 + tid;
            if (gn < N) {
                const float* wp = W + (size_t)gn * K + k0;
                if (rem >= 16) {
                    bv[0] = *(const float4*)(wp + 0);
                    bv[1] = *(const float4*)(wp + 4);
                    bv[2] = *(const float4*)(wp + 8);
                    bv[3] = *(const float4*)(wp + 12);
                } else {
                    #pragma unroll
                    for (int j = 0; j < 4; j++) {
                        int kc = j * 4;
                        bv[j].x = (kc   < rem) ? wp[kc]   : 0.f;
                        bv[j].y = (kc+1 < rem) ? wp[kc+1] : 0.f;
                        bv[j].z = (kc+2 < rem) ? wp[kc+2] : 0.f;
                        bv[j].w = (kc+3 < rem) ? wp[kc+3] : 0.f;
                    }
                }
            } else {
                #pragma unroll
                for (int j = 0; j < 4; j++) bv[j] = make_float4(0.f,0.f,0.f,0.f);
            }
        }
    };

    // ---- store registers into smem buffer (with tf32 rounding, k-major) ----
    auto sts = [&](int buf){
        #pragma unroll
        for (int j = 0; j < 4; j++) {
            As[buf][4*j+0][tid] = tf32r(av[j].x);
            As[buf][4*j+1][tid] = tf32r(av[j].y);
            As[buf][4*j+2][tid] = tf32r(av[j].z);
            As[buf][4*j+3][tid] = tf32r(av[j].w);
        }
        if (tid < 64) {
            #pragma unroll
            for (int j = 0; j < 4; j++) {
                Bs[buf][4*j+0][tid] = tf32r(bv[j].x);
                Bs[buf][4*j+1][tid] = tf32r(bv[j].y);
                Bs[buf][4*j+2][tid] = tf32r(bv[j].z);
                Bs[buf][4*j+3][tid] = tf32r(bv[j].w);
            }
        }
    };

    ldg(0); sts(0); __syncthreads();

    for (int it = 0; it < nit; it++) {
        int buf = it & 1;
        bool more = (it + 1 < nit);
        if (more) ldg(it + 1);

        #pragma unroll
        for (int ks = 0; ks < 2; ks++) {
            int kk = ks * 8;
            u32 afr[4][4];
            #pragma unroll
            for (int mf = 0; mf < 4; mf++) {
                int m0 = wm + mf*16;
                afr[mf][0] = __float_as_uint(As[buf][kk+ti  ][m0+g  ]);
                afr[mf][1] = __float_as_uint(As[buf][kk+ti  ][m0+g+8]);
                afr[mf][2] = __float_as_uint(As[buf][kk+ti+4][m0+g  ]);
                afr[mf][3] = __float_as_uint(As[buf][kk+ti+4][m0+g+8]);
            }
            u32 bfr[4][2];
            #pragma unroll
            for (int nf = 0; nf < 4; nf++) {
                int n0 = wn + nf*8;
                bfr[nf][0] = __float_as_uint(Bs[buf][kk+ti  ][n0+g]);
                bfr[nf][1] = __float_as_uint(Bs[buf][kk+ti+4][n0+g]);
            }
            #pragma unroll
            for (int mf = 0; mf < 4; mf++)
                #pragma unroll
                for (int nf = 0; nf < 4; nf++)
                    mma8(acc[mf][nf], afr[mf], bfr[nf]);
        }

        if (more) sts(buf ^ 1);
        __syncthreads();
    }

    // ---- epilogue: bias + act + store ----
    #pragma unroll
    for (int mf = 0; mf < 4; mf++) {
        int mrow0 = bm0 + wm + mf*16 + g;       // and +8
        #pragma unroll
        for (int nf = 0; nf < 4; nf++) {
            int col = bn0 + wn + nf*8 + 2*ti;
            float b0 = 0.f, b1 = 0.f;
            if (bias) {
                if (col   < N) b0 = bias[col];
                if (col+1 < N) b1 = bias[col+1];
            }
            #pragma unroll
            for (int h = 0; h < 2; h++) {
                int m = mrow0 + h*8;
                float v0 = actf<ACT>(acc[mf][nf][2*h+0] + b0);
                float v1 = actf<ACT>(acc[mf][nf][2*h+1] + b1);
                float* crow = C + (size_t)m * ldc;
                if (col + 1 < N) {
                    *(float2*)(crow + col) = make_float2(v0, v1);
                } else if (col < N) {
                    crow[col] = v0;
                }
            }
        }
    }
}

// ---------------- depthwise causal conv (k=8) + bias + silu ----------------
__global__ void k_conv(const float* __restrict__ cw, const float* __restrict__ cb){
    int ch = blockIdx.y * 256 + threadIdx.x;
    int t0 = blockIdx.x * 16;
    int l0 = t0 & (Lq - 1);
    int tb = t0 - l0;

    float w[8];
    #pragma unroll
    for (int j = 0; j < 8; j++) w[j] = cw[ch*8 + j];
    float bv = cb[ch];

    float v[23];
    #pragma unroll
    for (int j = 0; j < 23; j++) {
        int l = l0 - 7 + j;
        v[j] = (l >= 0) ? g_xz[(size_t)(tb + l) * (2*DIv) + ch] : 0.f;
    }
    #pragma unroll
    for (int o = 0; o < 16; o++) {
        float s = bv;
        #pragma unroll
        for (int j = 0; j < 8; j++) s = fmaf(v[o + j], w[j], s);
        g_xconv[(size_t)(t0 + o) * DIv + ch] = s / (1.f + __expf(-s));
    }
}

// ---------------- selective scan (serial over L) ----------------
__global__ void __launch_bounds__(128) k_scan(const float* __restrict__ Alog,
                                              const float* __restrict__ Dw){
    int b  = blockIdx.y;
    int ch = blockIdx.x * 128 + threadIdx.x;

    __shared__ float sBC[64][32];

    float a[NST];
    bool fast = true;
    #pragma unroll
    for (int n = 0; n < NST; n++) {
        a[n] = -expf(Alog[ch*NST + n]);
        fast = fast && (fabsf(a[n] + (float)(n+1)) < 1e-4f * (float)(n+1));
    }
    float Dd = Dw[ch];

    float h[NST];
    #pragma unroll
    for (int n = 0; n < NST; n++) h[n] = 0.f;

    const float* dbc = g_dbc + (size_t)b * Lq * XDv;
    const size_t tb0 = (size_t)b * Lq;

    float d_nx = g_delta[tb0*DIv + ch];
    float x_nx = g_xconv[tb0*DIv + ch];
    float z_nx = g_xz[tb0*(2*DIv) + DIv + ch];

    for (int w = 0; w < Lq/64; w++) {
        __syncthreads();
        for (int idx = threadIdx.x; idx < 64*32; idx += 128) {
            int s = idx >> 5, c = idx & 31;
            sBC[s][c] = dbc[(w*64 + s) * XDv + DTRANK + c];
        }
        __syncthreads();

        for (int s = 0; s < 64; s++) {
            int t = w*64 + s;
            float delta = d_nx, xv = x_nx, zv = z_nx;
            int tn = t + 1;
            if (tn < Lq) {
                d_nx = g_delta[(tb0 + tn)*DIv + ch];
                x_nx = g_xconv[(tb0 + tn)*DIv + ch];
                z_nx = g_xz[(tb0 + tn)*(2*DIv) + DIv + ch];
            }
            float dx = delta * xv;
            float y0 = 0.f, y1 = 0.f;
            if (fast) {
                // A_n = -(n+1): exp(delta*A_n) = p^(n+1), p = exp(-delta)
                float p  = __expf(-delta);
                float p2 = p*p, p4 = p2*p2, p8 = p4*p4;
                float p3 = p2*p, p5 = p4*p, p6 = p4*p2, p7 = p4*p3;
                float pw[NST] = {p, p2, p3, p4, p5, p6, p7, p8,
                                 p8*p, p8*p2, p8*p3, p8*p4, p8*p5, p8*p6, p8*p7, p8*p8};
                #pragma unroll
                for (int n = 0; n < NST; n += 2) {
                    h[n]   = fmaf(pw[n],   h[n],   dx * sBC[s][n]);
                    h[n+1] = fmaf(pw[n+1], h[n+1], dx * sBC[s][n+1]);
                    y0 = fmaf(h[n],   sBC[s][NST + n],   y0);
                    y1 = fmaf(h[n+1], sBC[s][NST + n+1], y1);
                }
            } else {
                #pragma unroll
                for (int n = 0; n < NST; n += 2) {
                    float dA0 = __expf(delta * a[n]);
                    float dA1 = __expf(delta * a[n+1]);
                    h[n]   = fmaf(dA0, h[n],   dx * sBC[s][n]);
                    h[n+1] = fmaf(dA1, h[n+1], dx * sBC[s][n+1]);
                    y0 = fmaf(h[n],   sBC[s][NST + n],   y0);
                    y1 = fmaf(h[n+1], sBC[s][NST + n+1], y1);
                }
            }
            float yy = fmaf(xv, Dd, y0 + y1);
            g_y[(tb0 + t)*DIv + ch] = yy * (zv / (1.f + __expf(-zv)));
        }
    }
}

// ---------------- head MLP (M=8): 320 -> 512 -> 512 -> 1 ----------------
__global__ void __launch_bounds__(512) k_head(
    const float* __restrict__ w1, const float* __restrict__ b1,
    const float* __restrict__ w2, const float* __restrict__ b2,
    const float* __restrict__ w3, const float* __restrict__ b3,
    float* __restrict__ out)
{
    __shared__ float sh [8][320];
    __shared__ float sh1[8][512];
    __shared__ float sh2[8][512];
    int tid = threadIdx.x;

    for (int idx = tid; idx < 8*320; idx += 512) {
        int bb = idx / 320, c = idx % 320;
        sh[bb][c] = g_bufA[((size_t)bb * Lq + Lq - 1) * DMv + c];
    }
    __syncthreads();

    {
        int n = tid;
        float acc[8];
        #pragma unroll
        for (int bb = 0; bb < 8; bb++) acc[bb] = 0.f;
        const float* wr = w1 + (size_t)n * 320;
        for (int k = 0; k < 320; k++) {
            float wv = wr[k];
            #pragma unroll
            for (int bb = 0; bb < 8; bb++) acc[bb] = fmaf(wv, sh[bb][k], acc[bb]);
        }
        #pragma unroll
        for (int bb = 0; bb < 8; bb++) sh1[bb][n] = fmaxf(acc[bb] + b1[n], 0.f);
    }
    __syncthreads();

    {
        int n = tid;
        float acc[8];
        #pragma unroll
        for (int bb = 0; bb < 8; bb++) acc[bb] = 0.f;
        const float* wr = w2 + (size_t)n * 512;
        for (int k = 0; k < 512; k++) {
            float wv = wr[k];
            #pragma unroll
            for (int bb = 0; bb < 8; bb++) acc[bb] = fmaf(wv, sh1[bb][k], acc[bb]);
        }
        #pragma unroll
        for (int bb = 0; bb < 8; bb++) sh2[bb][n] = fmaxf(acc[bb] + b2[n], 0.f);
    }
    __syncthreads();

    if (tid < 8) {
        float acc = 0.f;
        for (int k = 0; k < 512; k++) acc = fmaf(w3[k], sh2[tid][k], acc);
        acc += b3[0];
        float scale = g_startmax / (1.f + logf((float)Lq));
        out[tid] = fmaxf(acc * scale, 0.f);
    }
}

// ---------------- host launch ----------------
extern "C" void kernel_launch(void* const* d_in, const int* in_sizes, int n_in,
                              void* d_out, int out_size)
{
    const float* x            = (const float*)d_in[0];
    const float* fc_w         = (const float*)d_in[1];
    const float* fc_b         = (const float*)d_in[2];
    const float* blk_lin_w    = (const float*)d_in[3];
    const float* blk_lin_b    = (const float*)d_in[4];
    const float* blk_inproj_w = (const float*)d_in[5];
    const float* blk_conv_w   = (const float*)d_in[6];
    const float* blk_conv_b   = (const float*)d_in[7];
    const float* blk_xproj_w  = (const float*)d_in[8];
    const float* blk_dtproj_w = (const float*)d_in[9];
    const float* blk_dtproj_b = (const float*)d_in[10];
    const float* blk_A_log    = (const float*)d_in[11];
    const float* blk_D        = (const float*)d_in[12];
    const float* blk_outproj_w= (const float*)d_in[13];
    const float* s1_w1        = (const float*)d_in[14];
    const float* s1_b1        = (const float*)d_in[15];
    const float* s1_w2        = (const float*)d_in[16];
    const float* s1_b2        = (const float*)d_in[17];
    const float* s1_w3        = (const float*)d_in[18];
    const float* s1_b3        = (const float*)d_in[19];

    void* p;
    cudaGetSymbolAddress(&p, g_bufA);  float* bufA  = (float*)p;
    cudaGetSymbolAddress(&p, g_u);     float* u     = (float*)p;
    cudaGetSymbolAddress(&p, g_xz);    float* xz    = (float*)p;
    cudaGetSymbolAddress(&p, g_xconv); float* xconv = (float*)p;
    cudaGetSymbolAddress(&p, g_dbc);   float* dbc   = (float*)p;
    cudaGetSymbolAddress(&p, g_delta); float* delta = (float*)p;
    cudaGetSymbolAddress(&p, g_y);     float* y     = (float*)p;

    k_startmax<<<1, 256>>>(x);
    k_embed<<<Tq, DMv>>>(x, fc_w, fc_b);

    for (int i = 0; i < NBLK; i++) {
        // lin: tanh(bufA @ lin_w^T + lin_b) -> u   [Tq,320] K=320
        k_mgemm<1><<<dim3(5, Tq/128), 128>>>(
            bufA, DMv, blk_lin_w + (size_t)i*DMv*DMv, blk_lin_b + (size_t)i*DMv,
            u, DMv, Tq, DMv, DMv);

        // inproj: u @ inproj_w^T -> xz   [Tq,2560] K=320
        k_mgemm<0><<<dim3(40, Tq/128), 128>>>(
            u, DMv, blk_inproj_w + (size_t)i*2*DIv*DMv, (const float*)nullptr,
            xz, 2*DIv, Tq, 2*DIv, DMv);

        // depthwise causal conv + silu -> xconv
        k_conv<<<dim3(Tq/16, DIv/256), 256>>>(
            blk_conv_w + (size_t)i*DIv*DCONVK, blk_conv_b + (size_t)i*DIv);

        // xproj: xconv @ xproj_w^T -> dbc   [Tq,52] K=1280
        k_mgemm<0><<<dim3(1, Tq/128), 128>>>(
            xconv, DIv, blk_xproj_w + (size_t)i*XDv*DIv, (const float*)nullptr,
            dbc, XDv, Tq, XDv, DIv);

        // dtproj: softplus(dbc[:, :20] @ dtproj_w^T + dtproj_b) -> delta   [Tq,1280] K=20
        k_mgemm<2><<<dim3(20, Tq/128), 128>>>(
            dbc, XDv, blk_dtproj_w + (size_t)i*DIv*DTRANK, blk_dtproj_b + (size_t)i*DIv,
            delta, DIv, Tq, DIv, DTRANK);

        // selective scan -> y
        k_scan<<<dim3(DIv/128, Bq), 128>>>(
            blk_A_log + (size_t)i*DIv*NST, blk_D + (size_t)i*DIv);

        // outproj: elu(y @ outproj_w^T) -> bufA   [Tq,320] K=1280
        k_mgemm<3><<<dim3(5, Tq/128), 128>>>(
            y, DIv, blk_outproj_w + (size_t)i*DMv*DIv, (const float*)nullptr,
            bufA, DMv, Tq, DMv, DIv);
    }

    k_head<<<1, 512>>>(s1_w1, s1_b1, s1_w2, s1_b2, s1_w3, s1_b3, (float*)d_out);
}

// round 5
// speedup vs baseline: 2.9302x; 1.8409x over previous
#include <cuda_runtime.h>
#include <math.h>
#include <stdint.h>

// ---------------- problem constants ----------------
#define Bq      8
#define Lq      2048
#define Tq      (Bq*Lq)        // 16384 tokens
#define DMv     320
#define DIv     1280
#define NST     16
#define DCONVK  8
#define DTRANK  20
#define XDv     52             // DTRANK + 2*NST
#define NBLK    4

typedef uint32_t u32;

// ---------------- static device scratch (no allocations) ----------------
__device__ __align__(256) float g_bufA [Tq*DMv];
__device__ __align__(256) float g_u    [Tq*DMv];
__device__ __align__(256) float g_xz   [(size_t)Tq*2*DIv];
__device__ __align__(256) float g_xconv[(size_t)Tq*DIv];
__device__ __align__(256) float g_dbc  [Tq*XDv];
__device__ __align__(256) float g_delta[(size_t)Tq*DIv];
__device__ __align__(256) float g_y    [(size_t)Tq*DIv];
__device__ float g_startmax;

// ---------------- helpers ----------------
__device__ __forceinline__ u32 sptr(const void* p){
    return (u32)__cvta_generic_to_shared(p);
}
__device__ __forceinline__ void cpa16(u32 dst, const void* src, int sz){
    asm volatile("cp.async.ca.shared.global [%0], [%1], 16, %2;"
                 :: "r"(dst), "l"(src), "r"(sz) : "memory");
}
#define CP_COMMIT() asm volatile("cp.async.commit_group;" ::: "memory")
#define CP_WAIT0()  asm volatile("cp.async.wait_group 0;" ::: "memory")

__device__ __forceinline__ void mma8(float* c, const u32* a, const u32* b){
    asm volatile("mma.sync.aligned.m16n8k8.row.col.f32.tf32.tf32.f32 "
        "{%0,%1,%2,%3}, {%4,%5,%6,%7}, {%8,%9}, {%0,%1,%2,%3};"
        : "+f"(c[0]), "+f"(c[1]), "+f"(c[2]), "+f"(c[3])
        : "r"(a[0]), "r"(a[1]), "r"(a[2]), "r"(a[3]), "r"(b[0]), "r"(b[1]));
}

// ---------------- start_max reduction ----------------
__global__ void k_startmax(const float* __restrict__ x){
    __shared__ float red[256];
    float m = -1e30f;
    for (int i = threadIdx.x; i < Tq; i += 256) m = fmaxf(m, x[i*4 + 2]);
    red[threadIdx.x] = m; __syncthreads();
    for (int s = 128; s > 0; s >>= 1){
        if (threadIdx.x < s) red[threadIdx.x] = fmaxf(red[threadIdx.x], red[threadIdx.x + s]);
        __syncthreads();
    }
    if (threadIdx.x == 0) g_startmax = red[0];
}

// ---------------- embedding: normalize + fc (K=4) ----------------
__global__ void k_embed(const float* __restrict__ x, const float* __restrict__ fcw,
                        const float* __restrict__ fcb){
    int t = blockIdx.x, c = threadIdx.x;      // grid Tq, block DMv
    float x0 = x[t*4+0], x1 = x[t*4+1], x2 = x[t*4+2], x3 = x[t*4+3];
    float n0 = x0 * (1.0f/255.0f), n1 = x1 * (1.0f/255.0f), n2 = x2 / g_startmax, n3 = x3;
    const float* w = fcw + c*4;
    g_bufA[(size_t)t*DMv + c] = fcb[c] + n0*w[0] + n1*w[1] + n2*w[2] + n3*w[3];
}

// ---------------- epilogue activation ----------------
template<int ACT> __device__ __forceinline__ float actf(float v){
    if (ACT == 1) return tanhf(v);
    if (ACT == 2) return (v > 20.f) ? v : log1pf(expf(v));
    if (ACT == 3) return (v > 0.f) ? v : expm1f(v);
    return v;
}

// ---------------- tf32 mma.sync GEMM: C = act(A[M,K] @ W[N,K]^T (+bias)) ----------------
// CTA tile 128x128, BK=16, 128 threads (4 warps 2x2, each 64x64: mf=4, nf=8).
// cp.async double-buffered tiles; smem row-major, row stride 20 floats
// (bank = 20g + ti mod 32 -> conflict-free fragment LDS).
// M % 128 == 0 required; N, K arbitrary (zero-filled via cp.async src-size).
#define PADK 20

template<int ACT>
__global__ void __launch_bounds__(128) k_mgemm(
    const float* __restrict__ A, int lda,
    const float* __restrict__ W,
    const float* __restrict__ bias,
    float* __restrict__ C, int ldc,
    int M, int N, int K)
{
    __shared__ float As[2][128][PADK];
    __shared__ float Bs[2][128][PADK];

    int tid  = threadIdx.x;
    int lane = tid & 31, w = tid >> 5;
    int wm = (w >> 1) * 64, wn = (w & 1) * 64;
    int g = lane >> 2, ti = lane & 3;
    int bm0 = blockIdx.y * 128, bn0 = blockIdx.x * 128;

    float acc[4][8][4];
    #pragma unroll
    for (int i = 0; i < 4; i++)
        #pragma unroll
        for (int j = 0; j < 8; j++)
            #pragma unroll
            for (int r = 0; r < 4; r++) acc[i][j][r] = 0.f;

    int nit = (K + 15) / 16;

    // per-thread fixed sources: one A row and one B row
    const float* arow = A + (size_t)(bm0 + tid) * lda;
    int gn = bn0 + tid;
    const float* brow = (gn < N) ? (W + (size_t)gn * K) : W;
    int bvalid = (gn < N);

    auto stage = [&](int it){
        int buf = it & 1;
        int k0 = it * 16;
        int remB = (K - k0) * 4;                 // bytes of valid k
        u32 adst = sptr(&As[buf][tid][0]);
        u32 bdst = sptr(&Bs[buf][tid][0]);
        #pragma unroll
        for (int c2 = 0; c2 < 4; c2++) {
            int off = c2 * 16;
            int sv = remB - off; sv = sv < 0 ? 0 : (sv > 16 ? 16 : sv);
            cpa16(adst + off, arow + k0 + c2*4, sv);
            cpa16(bdst + off, brow + k0 + c2*4, bvalid ? sv : 0);
        }
        CP_COMMIT();
    };

    stage(0);

    for (int it = 0; it < nit; it++) {
        int buf = it & 1;
        CP_WAIT0();
        __syncthreads();
        if (it + 1 < nit) stage(it + 1);

        #pragma unroll
        for (int ks = 0; ks < 2; ks++) {
            int kk = ks * 8;
            u32 afr[4][4];
            #pragma unroll
            for (int mf = 0; mf < 4; mf++) {
                int m0 = wm + mf*16;
                afr[mf][0] = __float_as_uint(As[buf][m0+g  ][kk+ti  ]);
                afr[mf][1] = __float_as_uint(As[buf][m0+g+8][kk+ti  ]);
                afr[mf][2] = __float_as_uint(As[buf][m0+g  ][kk+ti+4]);
                afr[mf][3] = __float_as_uint(As[buf][m0+g+8][kk+ti+4]);
            }
            u32 bfr[8][2];
            #pragma unroll
            for (int nf = 0; nf < 8; nf++) {
                int n0 = wn + nf*8;
                bfr[nf][0] = __float_as_uint(Bs[buf][n0+g][kk+ti  ]);
                bfr[nf][1] = __float_as_uint(Bs[buf][n0+g][kk+ti+4]);
            }
            #pragma unroll
            for (int mf = 0; mf < 4; mf++)
                #pragma unroll
                for (int nf = 0; nf < 8; nf++)
                    mma8(acc[mf][nf], afr[mf], bfr[nf]);
        }
        __syncthreads();
    }

    // ---- epilogue: bias + act + store ----
    #pragma unroll
    for (int mf = 0; mf < 4; mf++) {
        int mrow0 = bm0 + wm + mf*16 + g;       // and +8
        #pragma unroll
        for (int nf = 0; nf < 8; nf++) {
            int col = bn0 + wn + nf*8 + 2*ti;
            float b0 = 0.f, b1 = 0.f;
            if (bias) {
                if (col   < N) b0 = bias[col];
                if (col+1 < N) b1 = bias[col+1];
            }
            #pragma unroll
            for (int h = 0; h < 2; h++) {
                int m = mrow0 + h*8;
                float v0 = actf<ACT>(acc[mf][nf][2*h+0] + b0);
                float v1 = actf<ACT>(acc[mf][nf][2*h+1] + b1);
                float* crow = C + (size_t)m * ldc;
                if (col + 1 < N) {
                    *(float2*)(crow + col) = make_float2(v0, v1);
                } else if (col < N) {
                    crow[col] = v0;
                }
            }
        }
    }
}

// ---------------- depthwise causal conv (k=8) + bias + silu ----------------
__global__ void k_conv(const float* __restrict__ cw, const float* __restrict__ cb){
    int ch = blockIdx.y * 256 + threadIdx.x;
    int t0 = blockIdx.x * 16;
    int l0 = t0 & (Lq - 1);
    int tb = t0 - l0;

    float w[8];
    #pragma unroll
    for (int j = 0; j < 8; j++) w[j] = cw[ch*8 + j];
    float bv = cb[ch];

    float v[23];
    #pragma unroll
    for (int j = 0; j < 23; j++) {
        int l = l0 - 7 + j;
        v[j] = (l >= 0) ? g_xz[(size_t)(tb + l) * (2*DIv) + ch] : 0.f;
    }
    #pragma unroll
    for (int o = 0; o < 16; o++) {
        float s = bv;
        #pragma unroll
        for (int j = 0; j < 8; j++) s = fmaf(v[o + j], w[j], s);
        g_xconv[(size_t)(t0 + o) * DIv + ch] = s / (1.f + __expf(-s));
    }
}

// ---------------- selective scan (serial over L, smem-windowed inputs) ----------------
// grid (DIv/128, Bq), block 128. 8-step double-buffered cp.async windows.
#define SW 8
__global__ void __launch_bounds__(128) k_scan(const float* __restrict__ Alog,
                                              const float* __restrict__ Dw){
    int b   = blockIdx.y;
    int ch0 = blockIdx.x * 128;
    int tid = threadIdx.x;
    int ch  = ch0 + tid;

    __shared__ float  sD[2][SW][128];
    __shared__ float  sX[2][SW][128];
    __shared__ float  sZ[2][SW][128];
    __shared__ __align__(16) float sBC[2][SW][32];

    float a[NST];
    bool fast = true;
    #pragma unroll
    for (int n = 0; n < NST; n++) {
        a[n] = -expf(Alog[ch*NST + n]);
        fast = fast && (fabsf(a[n] + (float)(n+1)) < 1e-4f * (float)(n+1));
    }
    float Dd = Dw[ch];

    float h[NST];
    #pragma unroll
    for (int n = 0; n < NST; n++) h[n] = 0.f;

    const size_t tb0 = (size_t)b * Lq;

    auto stage = [&](int wnd){
        int buf = wnd & 1;
        int t0 = wnd * SW;
        // 3 arrays: SW rows x 128 floats = SW*32 16B-chunks each; 2 chunks/thread
        #pragma unroll
        for (int q = 0; q < 2; q++) {
            int idx = tid + q*128;               // 0..255
            int s = idx >> 5, cc = (idx & 31) * 4;
            size_t t = tb0 + t0 + s;
            cpa16(sptr(&sD[buf][s][cc]), &g_delta[t*DIv + cc + ch0], 16);
            cpa16(sptr(&sX[buf][s][cc]), &g_xconv[t*DIv + cc + ch0], 16);
            cpa16(sptr(&sZ[buf][s][cc]), &g_xz[t*(2*DIv) + DIv + cc + ch0], 16);
        }
        // BC: SW rows x 32 floats = SW*8 chunks (threads 0..SW*8-1)
        if (tid < SW*8) {
            int s = tid >> 3, cc = (tid & 7) * 4;
            cpa16(sptr(&sBC[buf][s][cc]),
                  &g_dbc[(tb0 + t0 + s)*XDv + DTRANK + cc], 16);
        }
        CP_COMMIT();
    };

    stage(0);

    for (int wnd = 0; wnd < Lq/SW; wnd++) {
        int buf = wnd & 1;
        CP_WAIT0();
        __syncthreads();
        if (wnd + 1 < Lq/SW) stage(wnd + 1);

        #pragma unroll
        for (int s = 0; s < SW; s++) {
            float delta = sD[buf][s][tid];
            float xv    = sX[buf][s][tid];
            float zv    = sZ[buf][s][tid];
            const float4* bcq = (const float4*)&sBC[buf][s][0];
            float4 q0 = bcq[0], q1 = bcq[1], q2 = bcq[2], q3 = bcq[3];
            float4 q4 = bcq[4], q5 = bcq[5], q6 = bcq[6], q7 = bcq[7];
            float Bv[NST] = {q0.x,q0.y,q0.z,q0.w, q1.x,q1.y,q1.z,q1.w,
                             q2.x,q2.y,q2.z,q2.w, q3.x,q3.y,q3.z,q3.w};
            float Cv[NST] = {q4.x,q4.y,q4.z,q4.w, q5.x,q5.y,q5.z,q5.w,
                             q6.x,q6.y,q6.z,q6.w, q7.x,q7.y,q7.z,q7.w};

            float dx = delta * xv;
            float y0 = 0.f, y1 = 0.f;
            if (fast) {
                // A_n = -(n+1): exp(delta*A_n) = p^(n+1), p = exp(-delta)
                float p  = __expf(-delta);
                float p2 = p*p, p4 = p2*p2, p8 = p4*p4;
                float p3 = p2*p, p5 = p4*p, p6 = p4*p2, p7 = p4*p3;
                float pw[NST] = {p, p2, p3, p4, p5, p6, p7, p8,
                                 p8*p, p8*p2, p8*p3, p8*p4, p8*p5, p8*p6, p8*p7, p8*p8};
                #pragma unroll
                for (int n = 0; n < NST; n += 2) {
                    h[n]   = fmaf(pw[n],   h[n],   dx * Bv[n]);
                    h[n+1] = fmaf(pw[n+1], h[n+1], dx * Bv[n+1]);
                    y0 = fmaf(h[n],   Cv[n],   y0);
                    y1 = fmaf(h[n+1], Cv[n+1], y1);
                }
            } else {
                #pragma unroll
                for (int n = 0; n < NST; n += 2) {
                    float dA0 = __expf(delta * a[n]);
                    float dA1 = __expf(delta * a[n+1]);
                    h[n]   = fmaf(dA0, h[n],   dx * Bv[n]);
                    h[n+1] = fmaf(dA1, h[n+1], dx * Bv[n+1]);
                    y0 = fmaf(h[n],   Cv[n],   y0);
                    y1 = fmaf(h[n+1], Cv[n+1], y1);
                }
            }
            float yy = fmaf(xv, Dd, y0 + y1);
            g_y[(tb0 + wnd*SW + s)*DIv + ch] = yy * (zv / (1.f + __expf(-zv)));
        }
    }
}

// ---------------- head MLP (M=8): 320 -> 512 -> 512 -> 1 ----------------
__global__ void __launch_bounds__(512) k_head(
    const float* __restrict__ w1, const float* __restrict__ b1,
    const float* __restrict__ w2, const float* __restrict__ b2,
    const float* __restrict__ w3, const float* __restrict__ b3,
    float* __restrict__ out)
{
    __shared__ float sh [8][320];
    __shared__ float sh1[8][512];
    __shared__ float sh2[8][512];
    int tid = threadIdx.x;

    for (int idx = tid; idx < 8*320; idx += 512) {
        int bb = idx / 320, c = idx % 320;
        sh[bb][c] = g_bufA[((size_t)bb * Lq + Lq - 1) * DMv + c];
    }
    __syncthreads();

    {
        int n = tid;
        float acc[8];
        #pragma unroll
        for (int bb = 0; bb < 8; bb++) acc[bb] = 0.f;
        const float* wr = w1 + (size_t)n * 320;
        for (int k = 0; k < 320; k++) {
            float wv = wr[k];
            #pragma unroll
            for (int bb = 0; bb < 8; bb++) acc[bb] = fmaf(wv, sh[bb][k], acc[bb]);
        }
        #pragma unroll
        for (int bb = 0; bb < 8; bb++) sh1[bb][n] = fmaxf(acc[bb] + b1[n], 0.f);
    }
    __syncthreads();

    {
        int n = tid;
        float acc[8];
        #pragma unroll
        for (int bb = 0; bb < 8; bb++) acc[bb] = 0.f;
        const float* wr = w2 + (size_t)n * 512;
        for (int k = 0; k < 512; k++) {
            float wv = wr[k];
            #pragma unroll
            for (int bb = 0; bb < 8; bb++) acc[bb] = fmaf(wv, sh1[bb][k], acc[bb]);
        }
        #pragma unroll
        for (int bb = 0; bb < 8; bb++) sh2[bb][n] = fmaxf(acc[bb] + b2[n], 0.f);
    }
    __syncthreads();

    if (tid < 8) {
        float acc = 0.f;
        for (int k = 0; k < 512; k++) acc = fmaf(w3[k], sh2[tid][k], acc);
        acc += b3[0];
        float scale = g_startmax / (1.f + logf((float)Lq));
        out[tid] = fmaxf(acc * scale, 0.f);
    }
}

// ---------------- host launch ----------------
extern "C" void kernel_launch(void* const* d_in, const int* in_sizes, int n_in,
                              void* d_out, int out_size)
{
    const float* x            = (const float*)d_in[0];
    const float* fc_w         = (const float*)d_in[1];
    const float* fc_b         = (const float*)d_in[2];
    const float* blk_lin_w    = (const float*)d_in[3];
    const float* blk_lin_b    = (const float*)d_in[4];
    const float* blk_inproj_w = (const float*)d_in[5];
    const float* blk_conv_w   = (const float*)d_in[6];
    const float* blk_conv_b   = (const float*)d_in[7];
    const float* blk_xproj_w  = (const float*)d_in[8];
    const float* blk_dtproj_w = (const float*)d_in[9];
    const float* blk_dtproj_b = (const float*)d_in[10];
    const float* blk_A_log    = (const float*)d_in[11];
    const float* blk_D        = (const float*)d_in[12];
    const float* blk_outproj_w= (const float*)d_in[13];
    const float* s1_w1        = (const float*)d_in[14];
    const float* s1_b1        = (const float*)d_in[15];
    const float* s1_w2        = (const float*)d_in[16];
    const float* s1_b2        = (const float*)d_in[17];
    const float* s1_w3        = (const float*)d_in[18];
    const float* s1_b3        = (const float*)d_in[19];

    void* p;
    cudaGetSymbolAddress(&p, g_bufA);  float* bufA  = (float*)p;
    cudaGetSymbolAddress(&p, g_u);     float* u     = (float*)p;
    cudaGetSymbolAddress(&p, g_xz);    float* xz    = (float*)p;
    cudaGetSymbolAddress(&p, g_xconv); float* xconv = (float*)p;
    cudaGetSymbolAddress(&p, g_dbc);   float* dbc   = (float*)p;
    cudaGetSymbolAddress(&p, g_delta); float* delta = (float*)p;
    cudaGetSymbolAddress(&p, g_y);     float* y     = (float*)p;

    k_startmax<<<1, 256>>>(x);
    k_embed<<<Tq, DMv>>>(x, fc_w, fc_b);

    for (int i = 0; i < NBLK; i++) {
        // lin: tanh(bufA @ lin_w^T + lin_b) -> u   [Tq,320] K=320
        k_mgemm<1><<<dim3(3, Tq/128), 128>>>(
            bufA, DMv, blk_lin_w + (size_t)i*DMv*DMv, blk_lin_b + (size_t)i*DMv,
            u, DMv, Tq, DMv, DMv);

        // inproj: u @ inproj_w^T -> xz   [Tq,2560] K=320
        k_mgemm<0><<<dim3(20, Tq/128), 128>>>(
            u, DMv, blk_inproj_w + (size_t)i*2*DIv*DMv, (const float*)nullptr,
            xz, 2*DIv, Tq, 2*DIv, DMv);

        // depthwise causal conv + silu -> xconv
        k_conv<<<dim3(Tq/16, DIv/256), 256>>>(
            blk_conv_w + (size_t)i*DIv*DCONVK, blk_conv_b + (size_t)i*DIv);

        // xproj: xconv @ xproj_w^T -> dbc   [Tq,52] K=1280
        k_mgemm<0><<<dim3(1, Tq/128), 128>>>(
            xconv, DIv, blk_xproj_w + (size_t)i*XDv*DIv, (const float*)nullptr,
            dbc, XDv, Tq, XDv, DIv);

        // dtproj: softplus(dbc[:, :20] @ dtproj_w^T + dtproj_b) -> delta   [Tq,1280] K=20
        k_mgemm<2><<<dim3(10, Tq/128), 128>>>(
            dbc, XDv, blk_dtproj_w + (size_t)i*DIv*DTRANK, blk_dtproj_b + (size_t)i*DIv,
            delta, DIv, Tq, DIv, DTRANK);

        // selective scan -> y
        k_scan<<<dim3(DIv/128, Bq), 128>>>(
            blk_A_log + (size_t)i*DIv*NST, blk_D + (size_t)i*DIv);

        // outproj: elu(y @ outproj_w^T) -> bufA   [Tq,320] K=1280
        k_mgemm<3><<<dim3(3, Tq/128), 128>>>(
            y, DIv, blk_outproj_w + (size_t)i*DMv*DIv, (const float*)nullptr,
            bufA, DMv, Tq, DMv, DIv);
    }

    k_head<<<1, 512>>>(s1_w1, s1_b1, s1_w2, s1_b2, s1_w3, s1_b3, (float*)d_out);
}

// round 6
// speedup vs baseline: 3.7873x; 1.2925x over previous
#include <cuda_runtime.h>
#include <cuda_bf16.h>
#include <math.h>
#include <stdint.h>

// ---------------- problem constants ----------------
#define Bq      8
#define Lq      2048
#define Tq      (Bq*Lq)        // 16384 tokens
#define DMv     320
#define DIv     1280
#define NST     16
#define DCONVK  8
#define DTRANK  20
#define XDv     52             // DTRANK + 2*NST
#define NBLK    4

typedef uint32_t u32;
typedef __nv_bfloat16 bf16;

// ---------------- static device scratch (no allocations) ----------------
__device__ __align__(256) float g_bufA [Tq*DMv];          // fp32 (head input)
__device__ __align__(256) float g_xz   [(size_t)Tq*2*DIv];
__device__ __align__(256) float g_xconv[(size_t)Tq*DIv];
__device__ __align__(256) float g_dbc  [Tq*XDv];
__device__ __align__(256) float g_delta[(size_t)Tq*DIv];
__device__ float g_startmax;

// bf16 activation copies (GEMM A-operands)
__device__ __align__(256) bf16 g_bufAbf [Tq*DMv];
__device__ __align__(256) bf16 g_ubf    [Tq*DMv];
__device__ __align__(256) bf16 g_xconvbf[(size_t)Tq*DIv];
__device__ __align__(256) bf16 g_dbcbf  [Tq*56];          // stride 56 (16B-aligned rows)
__device__ __align__(256) bf16 g_ybf    [(size_t)Tq*DIv];

// bf16 weights (converted once per launch)
__device__ __align__(256) bf16 g_wlin[NBLK*320*320];
__device__ __align__(256) bf16 g_win [NBLK*2560*320];
__device__ __align__(256) bf16 g_wxp [NBLK*52*1280];
__device__ __align__(256) bf16 g_wdt [NBLK*1280*24];      // stride 24 (K=20 padded)
__device__ __align__(256) bf16 g_wout[NBLK*320*1280];

// ---------------- helpers ----------------
__device__ __forceinline__ u32 sptr(const void* p){
    return (u32)__cvta_generic_to_shared(p);
}
__device__ __forceinline__ void cpa16(u32 dst, const void* src, int sz){
    asm volatile("cp.async.ca.shared.global [%0], [%1], 16, %2;"
                 :: "r"(dst), "l"(src), "r"(sz) : "memory");
}
#define CP_COMMIT() asm volatile("cp.async.commit_group;" ::: "memory")
#define CP_WAIT0()  asm volatile("cp.async.wait_group 0;" ::: "memory")

__device__ __forceinline__ void mma16(float* c, const u32* a, const u32* b){
    asm volatile("mma.sync.aligned.m16n8k16.row.col.f32.bf16.bf16.f32 "
        "{%0,%1,%2,%3}, {%4,%5,%6,%7}, {%8,%9}, {%0,%1,%2,%3};"
        : "+f"(c[0]), "+f"(c[1]), "+f"(c[2]), "+f"(c[3])
        : "r"(a[0]), "r"(a[1]), "r"(a[2]), "r"(a[3]), "r"(b[0]), "r"(b[1]));
}

// ---------------- weight conversion ----------------
__global__ void k_cvt(const float* __restrict__ s, bf16* __restrict__ d, int n){
    int i = (blockIdx.x * 256 + threadIdx.x) * 4;
    if (i < n) {
        float4 v = *(const float4*)(s + i);
        d[i+0] = __float2bfloat16(v.x);
        d[i+1] = __float2bfloat16(v.y);
        d[i+2] = __float2bfloat16(v.z);
        d[i+3] = __float2bfloat16(v.w);
    }
}
// dtproj: [rows, 20] -> [rows, 24] zero-padded
__global__ void k_cvtp(const float* __restrict__ s, bf16* __restrict__ d, int rows){
    int idx = blockIdx.x * 256 + threadIdx.x;
    if (idx < rows * 24) {
        int r = idx / 24, c = idx % 24;
        d[idx] = (c < 20) ? __float2bfloat16(s[r*20 + c]) : __float2bfloat16(0.f);
    }
}

// ---------------- start_max reduction ----------------
__global__ void k_startmax(const float* __restrict__ x){
    __shared__ float red[256];
    float m = -1e30f;
    for (int i = threadIdx.x; i < Tq; i += 256) m = fmaxf(m, x[i*4 + 2]);
    red[threadIdx.x] = m; __syncthreads();
    for (int s = 128; s > 0; s >>= 1){
        if (threadIdx.x < s) red[threadIdx.x] = fmaxf(red[threadIdx.x], red[threadIdx.x + s]);
        __syncthreads();
    }
    if (threadIdx.x == 0) g_startmax = red[0];
}

// ---------------- embedding: normalize + fc (K=4) -> bf16 ----------------
__global__ void k_embed(const float* __restrict__ x, const float* __restrict__ fcw,
                        const float* __restrict__ fcb){
    int t = blockIdx.x, c = threadIdx.x;      // grid Tq, block DMv
    float x0 = x[t*4+0], x1 = x[t*4+1], x2 = x[t*4+2], x3 = x[t*4+3];
    float n0 = x0 * (1.0f/255.0f), n1 = x1 * (1.0f/255.0f), n2 = x2 / g_startmax, n3 = x3;
    const float* w = fcw + c*4;
    float v = fcb[c] + n0*w[0] + n1*w[1] + n2*w[2] + n3*w[3];
    g_bufAbf[(size_t)t*DMv + c] = __float2bfloat16(v);
}

// ---------------- epilogue activation ----------------
template<int ACT> __device__ __forceinline__ float actf(float v){
    if (ACT == 1) return tanhf(v);
    if (ACT == 2) return (v > 20.f) ? v : log1pf(expf(v));
    if (ACT == 3) return (v > 0.f) ? v : expm1f(v);
    return v;
}

// ---------------- bf16 mma.sync GEMM ----------------
// C = act(A[M,K](bf16) @ W[N,K](bf16)^T (+bias)); outputs f32 Cf and/or bf16 Cb.
// CTA tile 128xBN, BK=32, 128 threads.
// BN=128: 4 warps 2x2, each 64x64 (MF=4). BN=64: 4 warps 4x1, each 32x64 (MF=2).
// Smem row stride 40 bf16 (80B): bank = 20g+ti mod 32, conflict-free.
#define SBK 40

template<int ACT, int BN>
__global__ void __launch_bounds__(128) k_bgemm(
    const bf16* __restrict__ A, int lda,
    const bf16* __restrict__ W, int ldw,
    const float* __restrict__ bias,
    float* __restrict__ Cf, int ldc,
    bf16* __restrict__ Cb, int ldcb,
    int M, int N, int K)
{
    constexpr int MF = (BN == 128) ? 4 : 2;
    __shared__ __align__(16) uint16_t As[2][128][SBK];
    __shared__ __align__(16) uint16_t Bs[2][BN][SBK];

    int tid  = threadIdx.x;
    int lane = tid & 31, w = tid >> 5;
    int wm = (BN == 128) ? ((w >> 1) * 64) : (w * 32);
    int wn = (BN == 128) ? ((w & 1) * 64) : 0;
    int g = lane >> 2, ti = lane & 3;
    int bm0 = blockIdx.y * 128, bn0 = blockIdx.x * BN;

    float acc[MF][8][4];
    #pragma unroll
    for (int i = 0; i < MF; i++)
        #pragma unroll
        for (int j = 0; j < 8; j++)
            #pragma unroll
            for (int r = 0; r < 4; r++) acc[i][j][r] = 0.f;

    int nit = (K + 31) / 32;

    const bf16* arow = A + (size_t)(bm0 + tid) * lda;
    int gn = bn0 + tid;
    const bf16* brow = (tid < BN && gn < N) ? (W + (size_t)gn * ldw) : W;
    int bvalid = (tid < BN && gn < N);

    auto stage = [&](int it){
        int buf = it & 1;
        int k0 = it * 32;
        int remB = (K - k0) * 2;                 // valid bytes
        u32 adst = sptr(&As[buf][tid][0]);
        const bf16* asrc = arow + k0;
        #pragma unroll
        for (int c = 0; c < 4; c++) {
            int sv = remB - c*16; sv = sv < 0 ? 0 : (sv > 16 ? 16 : sv);
            cpa16(adst + c*16, asrc + c*8, sv);
        }
        if (tid < BN) {
            u32 bdst = sptr(&Bs[buf][tid][0]);
            const bf16* bsrc = brow + k0;
            #pragma unroll
            for (int c = 0; c < 4; c++) {
                int sv = remB - c*16; sv = sv < 0 ? 0 : (sv > 16 ? 16 : sv);
                cpa16(bdst + c*16, bsrc + c*8, bvalid ? sv : 0);
            }
        }
        CP_COMMIT();
    };

    stage(0);

    for (int it = 0; it < nit; it++) {
        int buf = it & 1;
        CP_WAIT0();
        __syncthreads();
        if (it + 1 < nit) stage(it + 1);

        #pragma unroll
        for (int ks = 0; ks < 2; ks++) {
            int kk = ks * 16;
            u32 afr[MF][4];
            #pragma unroll
            for (int mf = 0; mf < MF; mf++) {
                int m0 = wm + mf*16;
                afr[mf][0] = *(const u32*)&As[buf][m0+g  ][kk + 2*ti    ];
                afr[mf][1] = *(const u32*)&As[buf][m0+g+8][kk + 2*ti    ];
                afr[mf][2] = *(const u32*)&As[buf][m0+g  ][kk + 2*ti + 8];
                afr[mf][3] = *(const u32*)&As[buf][m0+g+8][kk + 2*ti + 8];
            }
            u32 bfr[8][2];
            #pragma unroll
            for (int nf = 0; nf < 8; nf++) {
                int n0 = wn + nf*8;
                bfr[nf][0] = *(const u32*)&Bs[buf][n0+g][kk + 2*ti    ];
                bfr[nf][1] = *(const u32*)&Bs[buf][n0+g][kk + 2*ti + 8];
            }
            #pragma unroll
            for (int mf = 0; mf < MF; mf++)
                #pragma unroll
                for (int nf = 0; nf < 8; nf++)
                    mma16(acc[mf][nf], afr[mf], bfr[nf]);
        }
        __syncthreads();
    }

    // ---- epilogue: bias + act + dual store ----
    #pragma unroll
    for (int mf = 0; mf < MF; mf++) {
        int mrow0 = bm0 + wm + mf*16 + g;       // and +8
        #pragma unroll
        for (int nf = 0; nf < 8; nf++) {
            int col = bn0 + wn + nf*8 + 2*ti;
            float b0 = 0.f, b1 = 0.f;
            if (bias) {
                if (col   < N) b0 = bias[col];
                if (col+1 < N) b1 = bias[col+1];
            }
            #pragma unroll
            for (int h = 0; h < 2; h++) {
                int m = mrow0 + h*8;
                float v0 = actf<ACT>(acc[mf][nf][2*h+0] + b0);
                float v1 = actf<ACT>(acc[mf][nf][2*h+1] + b1);
                if (Cf) {
                    float* crow = Cf + (size_t)m * ldc;
                    if (col + 1 < N)      *(float2*)(crow + col) = make_float2(v0, v1);
                    else if (col < N)     crow[col] = v0;
                }
                if (Cb) {
                    bf16* brow2 = Cb + (size_t)m * ldcb;
                    if (col + 1 < N)      *(__nv_bfloat162*)(brow2 + col) = __floats2bfloat162_rn(v0, v1);
                    else if (col < N)     brow2[col] = __float2bfloat16(v0);
                }
            }
        }
    }
}

// ---------------- depthwise causal conv (k=8) + bias + silu ----------------
__global__ void k_conv(const float* __restrict__ cw, const float* __restrict__ cb){
    int ch = blockIdx.y * 256 + threadIdx.x;
    int t0 = blockIdx.x * 16;
    int l0 = t0 & (Lq - 1);
    int tb = t0 - l0;

    float w[8];
    #pragma unroll
    for (int j = 0; j < 8; j++) w[j] = cw[ch*8 + j];
    float bv = cb[ch];

    float v[23];
    #pragma unroll
    for (int j = 0; j < 23; j++) {
        int l = l0 - 7 + j;
        v[j] = (l >= 0) ? g_xz[(size_t)(tb + l) * (2*DIv) + ch] : 0.f;
    }
    #pragma unroll
    for (int o = 0; o < 16; o++) {
        float s = bv;
        #pragma unroll
        for (int j = 0; j < 8; j++) s = fmaf(v[o + j], w[j], s);
        float sil = s / (1.f + __expf(-s));
        size_t idx = (size_t)(t0 + o) * DIv + ch;
        g_xconv[idx]   = sil;
        g_xconvbf[idx] = __float2bfloat16(sil);
    }
}

// ---------------- selective scan (serial over L, smem-windowed inputs) ----------------
#define SW 8
__global__ void __launch_bounds__(128) k_scan(const float* __restrict__ Alog,
                                              const float* __restrict__ Dw){
    int b   = blockIdx.y;
    int ch0 = blockIdx.x * 128;
    int tid = threadIdx.x;
    int ch  = ch0 + tid;

    __shared__ float  sD[2][SW][128];
    __shared__ float  sX[2][SW][128];
    __shared__ float  sZ[2][SW][128];
    __shared__ __align__(16) float sBC[2][SW][32];

    float a[NST];
    bool fast = true;
    #pragma unroll
    for (int n = 0; n < NST; n++) {
        a[n] = -expf(Alog[ch*NST + n]);
        fast = fast && (fabsf(a[n] + (float)(n+1)) < 1e-4f * (float)(n+1));
    }
    float Dd = Dw[ch];

    float h[NST];
    #pragma unroll
    for (int n = 0; n < NST; n++) h[n] = 0.f;

    const size_t tb0 = (size_t)b * Lq;

    auto stage = [&](int wnd){
        int buf = wnd & 1;
        int t0 = wnd * SW;
        #pragma unroll
        for (int q = 0; q < 2; q++) {
            int idx = tid + q*128;
            int s = idx >> 5, cc = (idx & 31) * 4;
            size_t t = tb0 + t0 + s;
            cpa16(sptr(&sD[buf][s][cc]), &g_delta[t*DIv + cc + ch0], 16);
            cpa16(sptr(&sX[buf][s][cc]), &g_xconv[t*DIv + cc + ch0], 16);
            cpa16(sptr(&sZ[buf][s][cc]), &g_xz[t*(2*DIv) + DIv + cc + ch0], 16);
        }
        if (tid < SW*8) {
            int s = tid >> 3, cc = (tid & 7) * 4;
            cpa16(sptr(&sBC[buf][s][cc]),
                  &g_dbc[(tb0 + t0 + s)*XDv + DTRANK + cc], 16);
        }
        CP_COMMIT();
    };

    stage(0);

    for (int wnd = 0; wnd < Lq/SW; wnd++) {
        int buf = wnd & 1;
        CP_WAIT0();
        __syncthreads();
        if (wnd + 1 < Lq/SW) stage(wnd + 1);

        #pragma unroll
        for (int s = 0; s < SW; s++) {
            float delta = sD[buf][s][tid];
            float xv    = sX[buf][s][tid];
            float zv    = sZ[buf][s][tid];
            const float4* bcq = (const float4*)&sBC[buf][s][0];
            float4 q0 = bcq[0], q1 = bcq[1], q2 = bcq[2], q3 = bcq[3];
            float4 q4 = bcq[4], q5 = bcq[5], q6 = bcq[6], q7 = bcq[7];
            float Bv[NST] = {q0.x,q0.y,q0.z,q0.w, q1.x,q1.y,q1.z,q1.w,
                             q2.x,q2.y,q2.z,q2.w, q3.x,q3.y,q3.z,q3.w};
            float Cv[NST] = {q4.x,q4.y,q4.z,q4.w, q5.x,q5.y,q5.z,q5.w,
                             q6.x,q6.y,q6.z,q6.w, q7.x,q7.y,q7.z,q7.w};

            float dx = delta * xv;
            float y0 = 0.f, y1 = 0.f;
            if (fast) {
                float p  = __expf(-delta);
                float p2 = p*p, p4 = p2*p2, p8 = p4*p4;
                float p3 = p2*p, p5 = p4*p, p6 = p4*p2, p7 = p4*p3;
                float pw[NST] = {p, p2, p3, p4, p5, p6, p7, p8,
                                 p8*p, p8*p2, p8*p3, p8*p4, p8*p5, p8*p6, p8*p7, p8*p8};
                #pragma unroll
                for (int n = 0; n < NST; n += 2) {
                    h[n]   = fmaf(pw[n],   h[n],   dx * Bv[n]);
                    h[n+1] = fmaf(pw[n+1], h[n+1], dx * Bv[n+1]);
                    y0 = fmaf(h[n],   Cv[n],   y0);
                    y1 = fmaf(h[n+1], Cv[n+1], y1);
                }
            } else {
                #pragma unroll
                for (int n = 0; n < NST; n += 2) {
                    float dA0 = __expf(delta * a[n]);
                    float dA1 = __expf(delta * a[n+1]);
                    h[n]   = fmaf(dA0, h[n],   dx * Bv[n]);
                    h[n+1] = fmaf(dA1, h[n+1], dx * Bv[n+1]);
                    y0 = fmaf(h[n],   Cv[n],   y0);
                    y1 = fmaf(h[n+1], Cv[n+1], y1);
                }
            }
            float yy = fmaf(xv, Dd, y0 + y1);
            float sil = zv / (1.f + __expf(-zv));
            g_ybf[(tb0 + wnd*SW + s)*DIv + ch] = __float2bfloat16(yy * sil);
        }
    }
}

// ---------------- head MLP (M=8): 320 -> 512 -> 512 -> 1 ----------------
__global__ void __launch_bounds__(512) k_head(
    const float* __restrict__ w1, const float* __restrict__ b1,
    const float* __restrict__ w2, const float* __restrict__ b2,
    const float* __restrict__ w3, const float* __restrict__ b3,
    float* __restrict__ out)
{
    __shared__ float sh [8][320];
    __shared__ float sh1[8][512];
    __shared__ float sh2[8][512];
    int tid = threadIdx.x;

    for (int idx = tid; idx < 8*320; idx += 512) {
        int bb = idx / 320, c = idx % 320;
        sh[bb][c] = g_bufA[((size_t)bb * Lq + Lq - 1) * DMv + c];
    }
    __syncthreads();

    {
        int n = tid;
        float acc[8];
        #pragma unroll
        for (int bb = 0; bb < 8; bb++) acc[bb] = 0.f;
        const float* wr = w1 + (size_t)n * 320;
        for (int k = 0; k < 320; k++) {
            float wv = wr[k];
            #pragma unroll
            for (int bb = 0; bb < 8; bb++) acc[bb] = fmaf(wv, sh[bb][k], acc[bb]);
        }
        #pragma unroll
        for (int bb = 0; bb < 8; bb++) sh1[bb][n] = fmaxf(acc[bb] + b1[n], 0.f);
    }
    __syncthreads();

    {
        int n = tid;
        float acc[8];
        #pragma unroll
        for (int bb = 0; bb < 8; bb++) acc[bb] = 0.f;
        const float* wr = w2 + (size_t)n * 512;
        for (int k = 0; k < 512; k++) {
            float wv = wr[k];
            #pragma unroll
            for (int bb = 0; bb < 8; bb++) acc[bb] = fmaf(wv, sh1[bb][k], acc[bb]);
        }
        #pragma unroll
        for (int bb = 0; bb < 8; bb++) sh2[bb][n] = fmaxf(acc[bb] + b2[n], 0.f);
    }
    __syncthreads();

    if (tid < 8) {
        float acc = 0.f;
        for (int k = 0; k < 512; k++) acc = fmaf(w3[k], sh2[tid][k], acc);
        acc += b3[0];
        float scale = g_startmax / (1.f + logf((float)Lq));
        out[tid] = fmaxf(acc * scale, 0.f);
    }
}

// ---------------- host launch ----------------
extern "C" void kernel_launch(void* const* d_in, const int* in_sizes, int n_in,
                              void* d_out, int out_size)
{
    const float* x            = (const float*)d_in[0];
    const float* fc_w         = (const float*)d_in[1];
    const float* fc_b         = (const float*)d_in[2];
    const float* blk_lin_w    = (const float*)d_in[3];
    const float* blk_lin_b    = (const float*)d_in[4];
    const float* blk_inproj_w = (const float*)d_in[5];
    const float* blk_conv_w   = (const float*)d_in[6];
    const float* blk_conv_b   = (const float*)d_in[7];
    const float* blk_xproj_w  = (const float*)d_in[8];
    const float* blk_dtproj_w = (const float*)d_in[9];
    const float* blk_dtproj_b = (const float*)d_in[10];
    const float* blk_A_log    = (const float*)d_in[11];
    const float* blk_D        = (const float*)d_in[12];
    const float* blk_outproj_w= (const float*)d_in[13];
    const float* s1_w1        = (const float*)d_in[14];
    const float* s1_b1        = (const float*)d_in[15];
    const float* s1_w2        = (const float*)d_in[16];
    const float* s1_b2        = (const float*)d_in[17];
    const float* s1_w3        = (const float*)d_in[18];
    const float* s1_b3        = (const float*)d_in[19];

    void* p;
    cudaGetSymbolAddress(&p, g_xz);      float* xz      = (float*)p;
    cudaGetSymbolAddress(&p, g_dbc);     float* dbc     = (float*)p;
    cudaGetSymbolAddress(&p, g_delta);   float* delta   = (float*)p;
    cudaGetSymbolAddress(&p, g_bufA);    float* bufA    = (float*)p;
    cudaGetSymbolAddress(&p, g_bufAbf);  bf16* bufAbf   = (bf16*)p;
    cudaGetSymbolAddress(&p, g_ubf);     bf16* ubf      = (bf16*)p;
    cudaGetSymbolAddress(&p, g_xconvbf); bf16* xconvbf  = (bf16*)p;
    cudaGetSymbolAddress(&p, g_dbcbf);   bf16* dbcbf    = (bf16*)p;
    cudaGetSymbolAddress(&p, g_ybf);     bf16* ybf      = (bf16*)p;
    cudaGetSymbolAddress(&p, g_wlin);    bf16* wlin     = (bf16*)p;
    cudaGetSymbolAddress(&p, g_win);     bf16* win      = (bf16*)p;
    cudaGetSymbolAddress(&p, g_wxp);     bf16* wxp      = (bf16*)p;
    cudaGetSymbolAddress(&p, g_wdt);     bf16* wdt      = (bf16*)p;
    cudaGetSymbolAddress(&p, g_wout);    bf16* wout     = (bf16*)p;

    // weight conversions (once per launch)
    k_cvt<<<(NBLK*320*320/4 + 255)/256, 256>>>(blk_lin_w, wlin, NBLK*320*320);
    k_cvt<<<(NBLK*2560*320/4 + 255)/256, 256>>>(blk_inproj_w, win, NBLK*2560*320);
    k_cvt<<<(NBLK*52*1280/4 + 255)/256, 256>>>(blk_xproj_w, wxp, NBLK*52*1280);
    k_cvtp<<<(NBLK*1280*24 + 255)/256, 256>>>(blk_dtproj_w, wdt, NBLK*1280);
    k_cvt<<<(NBLK*320*1280/4 + 255)/256, 256>>>(blk_outproj_w, wout, NBLK*320*1280);

    k_startmax<<<1, 256>>>(x);
    k_embed<<<Tq, DMv>>>(x, fc_w, fc_b);

    for (int i = 0; i < NBLK; i++) {
        // lin: tanh(bufA @ lin_w^T + b) -> u(bf16)   [Tq,320] K=320
        k_bgemm<1,128><<<dim3(3, Tq/128), 128>>>(
            bufAbf, DMv, wlin + (size_t)i*DMv*DMv, DMv,
            blk_lin_b + (size_t)i*DMv,
            (float*)nullptr, 0, ubf, DMv, Tq, DMv, DMv);

        // inproj: u @ inproj_w^T -> xz(f32)   [Tq,2560] K=320
        k_bgemm<0,128><<<dim3(20, Tq/128), 128>>>(
            ubf, DMv, win + (size_t)i*2*DIv*DMv, DMv,
            (const float*)nullptr,
            xz, 2*DIv, (bf16*)nullptr, 0, Tq, 2*DIv, DMv);

        // depthwise causal conv + silu -> xconv (f32 + bf16)
        k_conv<<<dim3(Tq/16, DIv/256), 256>>>(
            blk_conv_w + (size_t)i*DIv*DCONVK, blk_conv_b + (size_t)i*DIv);

        // xproj: xconv @ xproj_w^T -> dbc (f32, ld 52) + dbcbf (bf16, ld 56)   [Tq,52] K=1280
        k_bgemm<0,64><<<dim3(1, Tq/128), 128>>>(
            xconvbf, DIv, wxp + (size_t)i*XDv*DIv, DIv,
            (const float*)nullptr,
            dbc, XDv, dbcbf, 56, Tq, XDv, DIv);

        // dtproj: softplus(dbc[:, :20] @ dtproj_w^T + b) -> delta(f32)   [Tq,1280] K=20
        k_bgemm<2,128><<<dim3(10, Tq/128), 128>>>(
            dbcbf, 56, wdt + (size_t)i*DIv*24, 24,
            blk_dtproj_b + (size_t)i*DIv,
            delta, DIv, (bf16*)nullptr, 0, Tq, DIv, DTRANK);

        // selective scan -> y(bf16)
        k_scan<<<dim3(DIv/128, Bq), 128>>>(
            blk_A_log + (size_t)i*DIv*NST, blk_D + (size_t)i*DIv);

        // outproj: elu(y @ outproj_w^T) -> bufA (f32 + bf16)   [Tq,320] K=1280
        k_bgemm<3,128><<<dim3(3, Tq/128), 128>>>(
            ybf, DIv, wout + (size_t)i*DMv*DIv, DIv,
            (const float*)nullptr,
            bufA, DMv, bufAbf, DMv, Tq, DMv, DIv);
    }

    k_head<<<1, 512>>>(s1_w1, s1_b1, s1_w2, s1_b2, s1_w3, s1_b3, (float*)d_out);
}

// round 8
// speedup vs baseline: 3.8323x; 1.0119x over previous
#include <cuda_runtime.h>
#include <cuda_bf16.h>
#include <math.h>
#include <stdint.h>

// ---------------- problem constants ----------------
#define Bq      8
#define Lq      2048
#define Tq      (Bq*Lq)        // 16384 tokens
#define DMv     320
#define DIv     1280
#define NST     16
#define DCONVK  8
#define DTRANK  20
#define XDv     52             // DTRANK + 2*NST
#define NBLK    4

typedef uint32_t u32;
typedef __nv_bfloat16 bf16;

// ---------------- static device scratch (no allocations) ----------------
__device__ __align__(256) float g_bufA [Tq*DMv];          // fp32 (head input)
__device__ __align__(256) float g_dbc  [Tq*XDv];
__device__ __align__(256) float g_delta[(size_t)Tq*DIv];
__device__ float g_startmax;

// bf16 activations
__device__ __align__(256) bf16 g_bufAbf [Tq*DMv];
__device__ __align__(256) bf16 g_ubf    [Tq*DMv];
__device__ __align__(256) bf16 g_xzbf   [(size_t)Tq*2*DIv];  // inproj out (x | z)
__device__ __align__(256) bf16 g_xconvbf[(size_t)Tq*DIv];
__device__ __align__(256) bf16 g_dbcbf  [Tq*56];             // stride 56
__device__ __align__(256) bf16 g_ybf    [(size_t)Tq*DIv];

// bf16 weights (converted once per launch)
__device__ __align__(256) bf16 g_wlin[NBLK*320*320];
__device__ __align__(256) bf16 g_win [NBLK*2560*320];
__device__ __align__(256) bf16 g_wxp [NBLK*52*1280];
__device__ __align__(256) bf16 g_wdt [NBLK*1280*24];         // stride 24 (K=20 padded)
__device__ __align__(256) bf16 g_wout[NBLK*320*1280];

// ---------------- helpers ----------------
__device__ __forceinline__ u32 sptr(const void* p){
    return (u32)__cvta_generic_to_shared(p);
}
__device__ __forceinline__ void cpa16(u32 dst, const void* src, int sz){
    asm volatile("cp.async.ca.shared.global [%0], [%1], 16, %2;"
                 :: "r"(dst), "l"(src), "r"(sz) : "memory");
}
#define CP_COMMIT() asm volatile("cp.async.commit_group;" ::: "memory")
#define CP_WAIT0()  asm volatile("cp.async.wait_group 0;" ::: "memory")
#define CP_WAIT1()  asm volatile("cp.async.wait_group 1;" ::: "memory")

__device__ __forceinline__ void mma16(float* c, const u32* a, const u32* b){
    asm volatile("mma.sync.aligned.m16n8k16.row.col.f32.bf16.bf16.f32 "
        "{%0,%1,%2,%3}, {%4,%5,%6,%7}, {%8,%9}, {%0,%1,%2,%3};"
        : "+f"(c[0]), "+f"(c[1]), "+f"(c[2]), "+f"(c[3])
        : "r"(a[0]), "r"(a[1]), "r"(a[2]), "r"(a[3]), "r"(b[0]), "r"(b[1]));
}

// ---------------- weight conversion ----------------
__global__ void k_cvt(const float* __restrict__ s, bf16* __restrict__ d, int n){
    int i = (blockIdx.x * 256 + threadIdx.x) * 4;
    if (i < n) {
        float4 v = *(const float4*)(s + i);
        d[i+0] = __float2bfloat16(v.x);
        d[i+1] = __float2bfloat16(v.y);
        d[i+2] = __float2bfloat16(v.z);
        d[i+3] = __float2bfloat16(v.w);
    }
}
// dtproj: [rows, 20] -> [rows, 24] zero-padded
__global__ void k_cvtp(const float* __restrict__ s, bf16* __restrict__ d, int rows){
    int idx = blockIdx.x * 256 + threadIdx.x;
    if (idx < rows * 24) {
        int r = idx / 24, c = idx % 24;
        d[idx] = (c < 20) ? __float2bfloat16(s[r*20 + c]) : __float2bfloat16(0.f);
    }
}

// ---------------- start_max reduction ----------------
__global__ void k_startmax(const float* __restrict__ x){
    __shared__ float red[256];
    float m = -1e30f;
    for (int i = threadIdx.x; i < Tq; i += 256) m = fmaxf(m, x[i*4 + 2]);
    red[threadIdx.x] = m; __syncthreads();
    for (int s = 128; s > 0; s >>= 1){
        if (threadIdx.x < s) red[threadIdx.x] = fmaxf(red[threadIdx.x], red[threadIdx.x + s]);
        __syncthreads();
    }
    if (threadIdx.x == 0) g_startmax = red[0];
}

// ---------------- embedding: normalize + fc (K=4) -> bf16 ----------------
__global__ void k_embed(const float* __restrict__ x, const float* __restrict__ fcw,
                        const float* __restrict__ fcb){
    int t = blockIdx.x, c = threadIdx.x;      // grid Tq, block DMv
    float x0 = x[t*4+0], x1 = x[t*4+1], x2 = x[t*4+2], x3 = x[t*4+3];
    float n0 = x0 * (1.0f/255.0f), n1 = x1 * (1.0f/255.0f), n2 = x2 / g_startmax, n3 = x3;
    const float* w = fcw + c*4;
    float v = fcb[c] + n0*w[0] + n1*w[1] + n2*w[2] + n3*w[3];
    g_bufAbf[(size_t)t*DMv + c] = __float2bfloat16(v);
}

// ---------------- epilogue activation ----------------
template<int ACT> __device__ __forceinline__ float actf(float v){
    if (ACT == 1) return tanhf(v);
    if (ACT == 2) return (v > 20.f) ? v : log1pf(expf(v));
    if (ACT == 3) return (v > 0.f) ? v : expm1f(v);
    return v;
}

// ---------------- bf16 mma.sync GEMM, 3-stage cp.async pipeline ----------------
// C = act(A[M,K](bf16) @ W[N,K](bf16)^T (+bias)); outputs f32 Cf and/or bf16 Cb.
// CTA tile 128xBN, BK=32, 128 threads. One __syncthreads per iteration
// (3 buffers: stage(it+2) writes the buffer last read by mma(it-1), which all
// threads finished before this iteration's barrier).
#define SBK 40

template<int ACT, int BN>
__global__ void __launch_bounds__(128) k_bgemm(
    const bf16* __restrict__ A, int lda,
    const bf16* __restrict__ W, int ldw,
    const float* __restrict__ bias,
    float* __restrict__ Cf, int ldc,
    bf16* __restrict__ Cb, int ldcb,
    int M, int N, int K)
{
    constexpr int MF = (BN == 128) ? 4 : 2;
    __shared__ __align__(16) uint16_t As[3][128][SBK];
    __shared__ __align__(16) uint16_t Bs[3][BN][SBK];

    int tid  = threadIdx.x;
    int lane = tid & 31, w = tid >> 5;
    int wm = (BN == 128) ? ((w >> 1) * 64) : (w * 32);
    int wn = (BN == 128) ? ((w & 1) * 64) : 0;
    int g = lane >> 2, ti = lane & 3;
    int bm0 = blockIdx.y * 128, bn0 = blockIdx.x * BN;

    float acc[MF][8][4];
    #pragma unroll
    for (int i = 0; i < MF; i++)
        #pragma unroll
        for (int j = 0; j < 8; j++)
            #pragma unroll
            for (int r = 0; r < 4; r++) acc[i][j][r] = 0.f;

    int nit = (K + 31) / 32;

    const bf16* arow = A + (size_t)(bm0 + tid) * lda;
    int gn = bn0 + tid;
    const bf16* brow = (tid < BN && gn < N) ? (W + (size_t)gn * ldw) : W;
    int bvalid = (tid < BN && gn < N);

    auto stage = [&](int it){
        int buf = it % 3;
        int k0 = it * 32;
        int remB = (K - k0) * 2;                 // valid bytes (may be <=0 -> zero-fill)
        u32 adst = sptr(&As[buf][tid][0]);
        const bf16* asrc = arow + k0;
        #pragma unroll
        for (int c = 0; c < 4; c++) {
            int sv = remB - c*16; sv = sv < 0 ? 0 : (sv > 16 ? 16 : sv);
            cpa16(adst + c*16, asrc + c*8, sv);
        }
        if (tid < BN) {
            u32 bdst = sptr(&Bs[buf][tid][0]);
            const bf16* bsrc = brow + k0;
            #pragma unroll
            for (int c = 0; c < 4; c++) {
                int sv = remB - c*16; sv = sv < 0 ? 0 : (sv > 16 ? 16 : sv);
                cpa16(bdst + c*16, bsrc + c*8, bvalid ? sv : 0);
            }
        }
        CP_COMMIT();
    };

    stage(0);
    stage(1);

    for (int it = 0; it < nit; it++) {
        int buf = it % 3;
        CP_WAIT1();                 // completes group 'it' (one group committed per iter)
        __syncthreads();

        #pragma unroll
        for (int ks = 0; ks < 2; ks++) {
            int kk = ks * 16;
            u32 afr[MF][4];
            #pragma unroll
            for (int mf = 0; mf < MF; mf++) {
                int m0 = wm + mf*16;
                afr[mf][0] = *(const u32*)&As[buf][m0+g  ][kk + 2*ti    ];
                afr[mf][1] = *(const u32*)&As[buf][m0+g+8][kk + 2*ti    ];
                afr[mf][2] = *(const u32*)&As[buf][m0+g  ][kk + 2*ti + 8];
                afr[mf][3] = *(const u32*)&As[buf][m0+g+8][kk + 2*ti + 8];
            }
            u32 bfr[8][2];
            #pragma unroll
            for (int nf = 0; nf < 8; nf++) {
                int n0 = wn + nf*8;
                bfr[nf][0] = *(const u32*)&Bs[buf][n0+g][kk + 2*ti    ];
                bfr[nf][1] = *(const u32*)&Bs[buf][n0+g][kk + 2*ti + 8];
            }
            #pragma unroll
            for (int mf = 0; mf < MF; mf++)
                #pragma unroll
                for (int nf = 0; nf < 8; nf++)
                    mma16(acc[mf][nf], afr[mf], bfr[nf]);
        }

        if (it + 2 < nit) stage(it + 2);
        else CP_COMMIT();           // dummy group keeps wait_group numbering valid
    }

    // ---- epilogue: bias + act + dual store ----
    #pragma unroll
    for (int mf = 0; mf < MF; mf++) {
        int mrow0 = bm0 + wm + mf*16 + g;       // and +8
        #pragma unroll
        for (int nf = 0; nf < 8; nf++) {
            int col = bn0 + wn + nf*8 + 2*ti;
            float b0 = 0.f, b1 = 0.f;
            if (bias) {
                if (col   < N) b0 = bias[col];
                if (col+1 < N) b1 = bias[col+1];
            }
            #pragma unroll
            for (int h = 0; h < 2; h++) {
                int m = mrow0 + h*8;
                float v0 = actf<ACT>(acc[mf][nf][2*h+0] + b0);
                float v1 = actf<ACT>(acc[mf][nf][2*h+1] + b1);
                if (Cf) {
                    float* crow = Cf + (size_t)m * ldc;
                    if (col + 1 < N)      *(float2*)(crow + col) = make_float2(v0, v1);
                    else if (col < N)     crow[col] = v0;
                }
                if (Cb) {
                    bf16* brow2 = Cb + (size_t)m * ldcb;
                    if (col + 1 < N)      *(__nv_bfloat162*)(brow2 + col) = __floats2bfloat162_rn(v0, v1);
                    else if (col < N)     brow2[col] = __float2bfloat16(v0);
                }
            }
        }
    }
}

// ---------------- depthwise causal conv (k=8) + bias + silu ----------------
// reads bf16 x-half of g_xzbf; writes bf16 xconv only
__global__ void k_conv(const float* __restrict__ cw, const float* __restrict__ cb){
    int ch = blockIdx.y * 256 + threadIdx.x;
    int t0 = blockIdx.x * 16;
    int l0 = t0 & (Lq - 1);
    int tb = t0 - l0;

    float w[8];
    #pragma unroll
    for (int j = 0; j < 8; j++) w[j] = cw[ch*8 + j];
    float bv = cb[ch];

    float v[23];
    #pragma unroll
    for (int j = 0; j < 23; j++) {
        int l = l0 - 7 + j;
        v[j] = (l >= 0) ? __bfloat162float(g_xzbf[(size_t)(tb + l) * (2*DIv) + ch]) : 0.f;
    }
    #pragma unroll
    for (int o = 0; o < 16; o++) {
        float s = bv;
        #pragma unroll
        for (int j = 0; j < 8; j++) s = fmaf(v[o + j], w[j], s);
        float sil = s / (1.f + __expf(-s));
        g_xconvbf[(size_t)(t0 + o) * DIv + ch] = __float2bfloat16(sil);
    }
}

// ---------------- selective scan (serial over L, smem-windowed inputs) ----------------
#define SW 8
__global__ void __launch_bounds__(128) k_scan(const float* __restrict__ Alog,
                                              const float* __restrict__ Dw){
    int b   = blockIdx.y;
    int ch0 = blockIdx.x * 128;
    int tid = threadIdx.x;
    int ch  = ch0 + tid;

    __shared__ float    sD[2][SW][128];
    __shared__ __align__(16) uint16_t sXh[2][SW][128];
    __shared__ __align__(16) uint16_t sZh[2][SW][128];
    __shared__ __align__(16) float sBC[2][SW][32];

    float a[NST];
    bool fast = true;
    #pragma unroll
    for (int n = 0; n < NST; n++) {
        a[n] = -expf(Alog[ch*NST + n]);
        fast = fast && (fabsf(a[n] + (float)(n+1)) < 1e-4f * (float)(n+1));
    }
    float Dd = Dw[ch];

    float h[NST];
    #pragma unroll
    for (int n = 0; n < NST; n++) h[n] = 0.f;

    const size_t tb0 = (size_t)b * Lq;

    auto stage = [&](int wnd){
        int buf = wnd & 1;
        int t0 = wnd * SW;
        // delta (f32): SW rows x 32 chunks = 256 slots, 2/thread
        #pragma unroll
        for (int q = 0; q < 2; q++) {
            int idx = tid + q*128;
            int s = idx >> 5, cc = (idx & 31) * 4;
            cpa16(sptr(&sD[buf][s][cc]), &g_delta[(tb0 + t0 + s)*DIv + cc + ch0], 16);
        }
        // x (bf16): SW rows x 16 chunks = 128 slots, 1/thread
        {
            int s = tid >> 4, cc = (tid & 15) * 8;
            cpa16(sptr(&sXh[buf][s][cc]), &g_xconvbf[(tb0 + t0 + s)*DIv + cc + ch0], 16);
        }
        // z (bf16): 128 slots, 1/thread
        {
            int s = tid >> 4, cc = (tid & 15) * 8;
            cpa16(sptr(&sZh[buf][s][cc]),
                  &g_xzbf[(tb0 + t0 + s)*(2*DIv) + DIv + cc + ch0], 16);
        }
        // BC (f32): SW rows x 8 chunks = 64 slots
        if (tid < SW*8) {
            int s = tid >> 3, cc = (tid & 7) * 4;
            cpa16(sptr(&sBC[buf][s][cc]),
                  &g_dbc[(tb0 + t0 + s)*XDv + DTRANK + cc], 16);
        }
        CP_COMMIT();
    };

    stage(0);

    for (int wnd = 0; wnd < Lq/SW; wnd++) {
        int buf = wnd & 1;
        CP_WAIT0();
        __syncthreads();
        if (wnd + 1 < Lq/SW) stage(wnd + 1);

        #pragma unroll
        for (int s = 0; s < SW; s++) {
            float delta = sD[buf][s][tid];
            float xv, zv;
            {
                __nv_bfloat16 xb, zb;
                *(uint16_t*)&xb = sXh[buf][s][tid];
                *(uint16_t*)&zb = sZh[buf][s][tid];
                xv = __bfloat162float(xb);
                zv = __bfloat162float(zb);
            }
            const float4* bcq = (const float4*)&sBC[buf][s][0];
            float4 q0 = bcq[0], q1 = bcq[1], q2 = bcq[2], q3 = bcq[3];
            float4 q4 = bcq[4], q5 = bcq[5], q6 = bcq[6], q7 = bcq[7];
            float Bv[NST] = {q0.x,q0.y,q0.z,q0.w, q1.x,q1.y,q1.z,q1.w,
                             q2.x,q2.y,q2.z,q2.w, q3.x,q3.y,q3.z,q3.w};
            float Cv[NST] = {q4.x,q4.y,q4.z,q4.w, q5.x,q5.y,q5.z,q5.w,
                             q6.x,q6.y,q6.z,q6.w, q7.x,q7.y,q7.z,q7.w};

            float dx = delta * xv;
            float y0 = 0.f, y1 = 0.f;
            if (fast) {
                float p  = __expf(-delta);
                float p2 = p*p, p4 = p2*p2, p8 = p4*p4;
                float p3 = p2*p, p5 = p4*p, p6 = p4*p2, p7 = p4*p3;
                float pw[NST] = {p, p2, p3, p4, p5, p6, p7, p8,
                                 p8*p, p8*p2, p8*p3, p8*p4, p8*p5, p8*p6, p8*p7, p8*p8};
                #pragma unroll
                for (int n = 0; n < NST; n += 2) {
                    h[n]   = fmaf(pw[n],   h[n],   dx * Bv[n]);
                    h[n+1] = fmaf(pw[n+1], h[n+1], dx * Bv[n+1]);
                    y0 = fmaf(h[n],   Cv[n],   y0);
                    y1 = fmaf(h[n+1], Cv[n+1], y1);
                }
            } else {
                #pragma unroll
                for (int n = 0; n < NST; n += 2) {
                    float dA0 = __expf(delta * a[n]);
                    float dA1 = __expf(delta * a[n+1]);
                    h[n]   = fmaf(dA0, h[n],   dx * Bv[n]);
                    h[n+1] = fmaf(dA1, h[n+1], dx * Bv[n+1]);
                    y0 = fmaf(h[n],   Cv[n],   y0);
                    y1 = fmaf(h[n+1], Cv[n+1], y1);
                }
            }
            float yy = fmaf(xv, Dd, y0 + y1);
            float sil = zv / (1.f + __expf(-zv));
            g_ybf[(tb0 + wnd*SW + s)*DIv + ch] = __float2bfloat16(yy * sil);
        }
    }
}

// ---------------- head MLP (M=8): 320 -> 512 -> 512 -> 1 ----------------
__global__ void __launch_bounds__(512) k_head(
    const float* __restrict__ w1, const float* __restrict__ b1,
    const float* __restrict__ w2, const float* __restrict__ b2,
    const float* __restrict__ w3, const float* __restrict__ b3,
    float* __restrict__ out)
{
    __shared__ float sh [8][320];
    __shared__ float sh1[8][512];
    __shared__ float sh2[8][512];
    int tid = threadIdx.x;

    for (int idx = tid; idx < 8*320; idx += 512) {
        int bb = idx / 320, c = idx % 320;
        sh[bb][c] = g_bufA[((size_t)bb * Lq + Lq - 1) * DMv + c];
    }
    __syncthreads();

    {
        int n = tid;
        float acc[8];
        #pragma unroll
        for (int bb = 0; bb < 8; bb++) acc[bb] = 0.f;
        const float* wr = w1 + (size_t)n * 320;
        for (int k = 0; k < 320; k++) {
            float wv = wr[k];
            #pragma unroll
            for (int bb = 0; bb < 8; bb++) acc[bb] = fmaf(wv, sh[bb][k], acc[bb]);
        }
        #pragma unroll
        for (int bb = 0; bb < 8; bb++) sh1[bb][n] = fmaxf(acc[bb] + b1[n], 0.f);
    }
    __syncthreads();

    {
        int n = tid;
        float acc[8];
        #pragma unroll
        for (int bb = 0; bb < 8; bb++) acc[bb] = 0.f;
        const float* wr = w2 + (size_t)n * 512;
        for (int k = 0; k < 512; k++) {
            float wv = wr[k];
            #pragma unroll
            for (int bb = 0; bb < 8; bb++) acc[bb] = fmaf(wv, sh1[bb][k], acc[bb]);
        }
        #pragma unroll
        for (int bb = 0; bb < 8; bb++) sh2[bb][n] = fmaxf(acc[bb] + b2[n], 0.f);
    }
    __syncthreads();

    if (tid < 8) {
        float acc = 0.f;
        for (int k = 0; k < 512; k++) acc = fmaf(w3[k], sh2[tid][k], acc);
        acc += b3[0];
        float scale = g_startmax / (1.f + logf((float)Lq));
        out[tid] = fmaxf(acc * scale, 0.f);
    }
}

// ---------------- host launch ----------------
extern "C" void kernel_launch(void* const* d_in, const int* in_sizes, int n_in,
                              void* d_out, int out_size)
{
    const float* x            = (const float*)d_in[0];
    const float* fc_w         = (const float*)d_in[1];
    const float* fc_b         = (const float*)d_in[2];
    const float* blk_lin_w    = (const float*)d_in[3];
    const float* blk_lin_b    = (const float*)d_in[4];
    const float* blk_inproj_w = (const float*)d_in[5];
    const float* blk_conv_w   = (const float*)d_in[6];
    const float* blk_conv_b   = (const float*)d_in[7];
    const float* blk_xproj_w  = (const float*)d_in[8];
    const float* blk_dtproj_w = (const float*)d_in[9];
    const float* blk_dtproj_b = (const float*)d_in[10];
    const float* blk_A_log    = (const float*)d_in[11];
    const float* blk_D        = (const float*)d_in[12];
    const float* blk_outproj_w= (const float*)d_in[13];
    const float* s1_w1        = (const float*)d_in[14];
    const float* s1_b1        = (const float*)d_in[15];
    const float* s1_w2        = (const float*)d_in[16];
    const float* s1_b2        = (const float*)d_in[17];
    const float* s1_w3        = (const float*)d_in[18];
    const float* s1_b3        = (const float*)d_in[19];

    void* p;
    cudaGetSymbolAddress(&p, g_dbc);     float* dbc     = (float*)p;
    cudaGetSymbolAddress(&p, g_delta);   float* delta   = (float*)p;
    cudaGetSymbolAddress(&p, g_bufA);    float* bufA    = (float*)p;
    cudaGetSymbolAddress(&p, g_bufAbf);  bf16* bufAbf   = (bf16*)p;
    cudaGetSymbolAddress(&p, g_ubf);     bf16* ubf      = (bf16*)p;
    cudaGetSymbolAddress(&p, g_xzbf);    bf16* xzbf     = (bf16*)p;
    cudaGetSymbolAddress(&p, g_xconvbf); bf16* xconvbf  = (bf16*)p;
    cudaGetSymbolAddress(&p, g_dbcbf);   bf16* dbcbf    = (bf16*)p;
    cudaGetSymbolAddress(&p, g_ybf);     bf16* ybf      = (bf16*)p;
    cudaGetSymbolAddress(&p, g_wlin);    bf16* wlin     = (bf16*)p;
    cudaGetSymbolAddress(&p, g_win);     bf16* win      = (bf16*)p;
    cudaGetSymbolAddress(&p, g_wxp);     bf16* wxp      = (bf16*)p;
    cudaGetSymbolAddress(&p, g_wdt);     bf16* wdt      = (bf16*)p;
    cudaGetSymbolAddress(&p, g_wout);    bf16* wout     = (bf16*)p;

    // weight conversions (once per launch)
    k_cvt<<<(NBLK*320*320/4 + 255)/256, 256>>>(blk_lin_w, wlin, NBLK*320*320);
    k_cvt<<<(NBLK*2560*320/4 + 255)/256, 256>>>(blk_inproj_w, win, NBLK*2560*320);
    k_cvt<<<(NBLK*52*1280/4 + 255)/256, 256>>>(blk_xproj_w, wxp, NBLK*52*1280);
    k_cvtp<<<(NBLK*1280*24 + 255)/256, 256>>>(blk_dtproj_w, wdt, NBLK*1280);
    k_cvt<<<(NBLK*320*1280/4 + 255)/256, 256>>>(blk_outproj_w, wout, NBLK*320*1280);

    k_startmax<<<1, 256>>>(x);
    k_embed<<<Tq, DMv>>>(x, fc_w, fc_b);

    for (int i = 0; i < NBLK; i++) {
        // lin: tanh(bufA @ lin_w^T + b) -> u(bf16)   [Tq,320] K=320
        k_bgemm<1,128><<<dim3(3, Tq/128), 128>>>(
            bufAbf, DMv, wlin + (size_t)i*DMv*DMv, DMv,
            blk_lin_b + (size_t)i*DMv,
            (float*)nullptr, 0, ubf, DMv, Tq, DMv, DMv);

        // inproj: u @ inproj_w^T -> xz(bf16)   [Tq,2560] K=320
        k_bgemm<0,128><<<dim3(20, Tq/128), 128>>>(
            ubf, DMv, win + (size_t)i*2*DIv*DMv, DMv,
            (const float*)nullptr,
            (float*)nullptr, 0, xzbf, 2*DIv, Tq, 2*DIv, DMv);

        // depthwise causal conv + silu -> xconv(bf16)
        k_conv<<<dim3(Tq/16, DIv/256), 256>>>(
            blk_conv_w + (size_t)i*DIv*DCONVK, blk_conv_b + (size_t)i*DIv);

        // xproj: xconv @ xproj_w^T -> dbc (f32) + dbcbf (bf16)   [Tq,52] K=1280
        k_bgemm<0,64><<<dim3(1, Tq/128), 128>>>(
            xconvbf, DIv, wxp + (size_t)i*XDv*DIv, DIv,
            (const float*)nullptr,
            dbc, XDv, dbcbf, 56, Tq, XDv, DIv);

        // dtproj: softplus(dbc[:, :20] @ dtproj_w^T + b) -> delta(f32)   [Tq,1280] K=20
        k_bgemm<2,128><<<dim3(10, Tq/128), 128>>>(
            dbcbf, 56, wdt + (size_t)i*DIv*24, 24,
            blk_dtproj_b + (size_t)i*DIv,
            delta, DIv, (bf16*)nullptr, 0, Tq, DIv, DTRANK);

        // selective scan -> y(bf16)
        k_scan<<<dim3(DIv/128, Bq), 128>>>(
            blk_A_log + (size_t)i*DIv*NST, blk_D + (size_t)i*DIv);

        // outproj: elu(y @ outproj_w^T) -> bufA (f32 + bf16)   [Tq,320] K=1280
        k_bgemm<3,128><<<dim3(3, Tq/128), 128>>>(
            ybf, DIv, wout + (size_t)i*DMv*DIv, DIv,
            (const float*)nullptr,
            bufA, DMv, bufAbf, DMv, Tq, DMv, DIv);
    }

    k_head<<<1, 512>>>(s1_w1, s1_b1, s1_w2, s1_b2, s1_w3, s1_b3, (float*)d_out);
}

// round 9
// speedup vs baseline: 4.0457x; 1.0557x over previous
#include <cuda_runtime.h>
#include <cuda_bf16.h>
#include <math.h>
#include <stdint.h>

// ---------------- problem constants ----------------
#define Bq      8
#define Lq      2048
#define Tq      (Bq*Lq)        // 16384 tokens
#define DMv     320
#define DIv     1280
#define NST     16
#define DCONVK  8
#define DTRANK  20
#define XDv     52             // DTRANK + 2*NST
#define NBLK    4

typedef uint32_t u32;
typedef __nv_bfloat16 bf16;

// ---------------- static device scratch (no allocations) ----------------
__device__ __align__(256) float g_bufA [Tq*DMv];          // fp32 (head input)
__device__ __align__(256) float g_dbc  [Tq*XDv];
__device__ __align__(256) float g_delta[(size_t)Tq*DIv];
__device__ float g_startmax;

// bf16 activations
__device__ __align__(256) bf16 g_bufAbf [Tq*DMv];
__device__ __align__(256) bf16 g_ubf    [Tq*DMv];
__device__ __align__(256) bf16 g_xzbf   [(size_t)Tq*2*DIv];  // inproj out (x | z)
__device__ __align__(256) bf16 g_xconvbf[(size_t)Tq*DIv];
__device__ __align__(256) bf16 g_dbcbf  [Tq*56];             // stride 56
__device__ __align__(256) bf16 g_ybf    [(size_t)Tq*DIv];

// bf16 weights (converted once per launch)
__device__ __align__(256) bf16 g_wlin[NBLK*320*320];
__device__ __align__(256) bf16 g_win [NBLK*2560*320];
__device__ __align__(256) bf16 g_wxp [NBLK*52*1280];
__device__ __align__(256) bf16 g_wdt [NBLK*1280*24];         // stride 24 (K=20 padded)
__device__ __align__(256) bf16 g_wout[NBLK*320*1280];

// ---------------- helpers ----------------
__device__ __forceinline__ u32 sptr(const void* p){
    return (u32)__cvta_generic_to_shared(p);
}
__device__ __forceinline__ void cpa16(u32 dst, const void* src, int sz){
    asm volatile("cp.async.ca.shared.global [%0], [%1], 16, %2;"
                 :: "r"(dst), "l"(src), "r"(sz) : "memory");
}
#define CP_COMMIT() asm volatile("cp.async.commit_group;" ::: "memory")
#define CP_WAIT0()  asm volatile("cp.async.wait_group 0;" ::: "memory")
#define CP_WAIT1()  asm volatile("cp.async.wait_group 1;" ::: "memory")

__device__ __forceinline__ void mma16(float* c, const u32* a, const u32* b){
    asm volatile("mma.sync.aligned.m16n8k16.row.col.f32.bf16.bf16.f32 "
        "{%0,%1,%2,%3}, {%4,%5,%6,%7}, {%8,%9}, {%0,%1,%2,%3};"
        : "+f"(c[0]), "+f"(c[1]), "+f"(c[2]), "+f"(c[3])
        : "r"(a[0]), "r"(a[1]), "r"(a[2]), "r"(a[3]), "r"(b[0]), "r"(b[1]));
}
__device__ __forceinline__ void ldsm4(u32& r0, u32& r1, u32& r2, u32& r3, u32 addr){
    asm volatile("ldmatrix.sync.aligned.m8n8.x4.shared.b16 {%0,%1,%2,%3}, [%4];"
        : "=r"(r0), "=r"(r1), "=r"(r2), "=r"(r3) : "r"(addr));
}

// ---------------- merged weight conversion ----------------
#define NQ1 (NBLK*320*320/4)      // wlin quads
#define NQ2 (NBLK*2560*320/4)     // win
#define NQ3 (NBLK*52*1280/4)      // wxp
#define NQ5 (NBLK*320*1280/4)     // wout
#define NQA (NQ1+NQ2+NQ3+NQ5)
#define NDT (NBLK*1280*24)        // wdt padded elems
__global__ void k_cvtall(const float* __restrict__ lw, const float* __restrict__ iw,
                         const float* __restrict__ xw, const float* __restrict__ dw,
                         const float* __restrict__ ow){
    int i = blockIdx.x * 256 + threadIdx.x;
    if (i < NQA) {
        const float* s; bf16* d; int q = i;
        if (q < NQ1)                { s = lw; d = g_wlin; }
        else if ((q -= NQ1) < NQ2)  { s = iw; d = g_win;  }
        else if ((q -= NQ2) < NQ3)  { s = xw; d = g_wxp;  }
        else                        { q -= NQ3; s = ow; d = g_wout; }
        float4 v = *(const float4*)(s + q*4);
        d[q*4+0] = __float2bfloat16(v.x);
        d[q*4+1] = __float2bfloat16(v.y);
        d[q*4+2] = __float2bfloat16(v.z);
        d[q*4+3] = __float2bfloat16(v.w);
    } else if (i < NQA + NDT) {
        int idx = i - NQA;
        int r = idx / 24, c = idx % 24;
        g_wdt[idx] = (c < 20) ? __float2bfloat16(dw[r*20 + c]) : __float2bfloat16(0.f);
    }
}

// ---------------- start_max reduction ----------------
__global__ void k_startmax(const float* __restrict__ x){
    __shared__ float red[256];
    float m = -1e30f;
    for (int i = threadIdx.x; i < Tq; i += 256) m = fmaxf(m, x[i*4 + 2]);
    red[threadIdx.x] = m; __syncthreads();
    for (int s = 128; s > 0; s >>= 1){
        if (threadIdx.x < s) red[threadIdx.x] = fmaxf(red[threadIdx.x], red[threadIdx.x + s]);
        __syncthreads();
    }
    if (threadIdx.x == 0) g_startmax = red[0];
}

// ---------------- embedding: normalize + fc (K=4) -> bf16 ----------------
__global__ void k_embed(const float* __restrict__ x, const float* __restrict__ fcw,
                        const float* __restrict__ fcb){
    int t = blockIdx.x, c = threadIdx.x;      // grid Tq, block DMv
    float x0 = x[t*4+0], x1 = x[t*4+1], x2 = x[t*4+2], x3 = x[t*4+3];
    float n0 = x0 * (1.0f/255.0f), n1 = x1 * (1.0f/255.0f), n2 = x2 / g_startmax, n3 = x3;
    const float* w = fcw + c*4;
    float v = fcb[c] + n0*w[0] + n1*w[1] + n2*w[2] + n3*w[3];
    g_bufAbf[(size_t)t*DMv + c] = __float2bfloat16(v);
}

// ---------------- epilogue activation ----------------
template<int ACT> __device__ __forceinline__ float actf(float v){
    if (ACT == 1) return tanhf(v);
    if (ACT == 2) return (v > 20.f) ? v : log1pf(expf(v));
    if (ACT == 3) return (v > 0.f) ? v : expm1f(v);
    return v;
}

// ---------------- bf16 mma.sync GEMM, ldmatrix + 3-stage cp.async ----------------
// C = act(A[M,K](bf16) @ W[N,K](bf16)^T (+bias)); outputs f32 Cf and/or bf16 Cb.
// CTA tile 128xBN, BK=32, 256 threads (8 warps).
// BN=128: warp grid 4(m)x2(n), warp tile 32x64 (MF=2). BN=64: 8(m)x1, 16x64 (MF=1).
// Smem row stride 40 bf16 (80B): LDSM phases conflict-free (banks 20r+{0..3}).
#define SBK 40

template<int ACT, int BN>
__global__ void __launch_bounds__(256) k_bgemm(
    const bf16* __restrict__ A, int lda,
    const bf16* __restrict__ W, int ldw,
    const float* __restrict__ bias,
    float* __restrict__ Cf, int ldc,
    bf16* __restrict__ Cb, int ldcb,
    int M, int N, int K)
{
    constexpr int MF = (BN == 128) ? 2 : 1;
    __shared__ __align__(16) uint16_t As[3][128][SBK];
    __shared__ __align__(16) uint16_t Bs[3][BN][SBK];
    const u32 BUFA = 128*SBK*2, BUFB = BN*SBK*2;

    int tid  = threadIdx.x;
    int lane = tid & 31, w = tid >> 5;
    int wm = (BN == 128) ? ((w & 3) * 32) : (w * 16);
    int wn = (BN == 128) ? ((w >> 2) * 64) : 0;
    int g = lane >> 2, ti = lane & 3;
    int bm0 = blockIdx.y * 128, bn0 = blockIdx.x * BN;

    // ldmatrix per-lane base addresses (buf 0, ks 0)
    int lr  = lane & 7;
    int lb1 = (lane >> 3) & 1;
    int lb2 = (lane >> 4) & 1;
    u32 aoff[MF];
    #pragma unroll
    for (int mf = 0; mf < MF; mf++)
        aoff[mf] = sptr(&As[0][wm + mf*16 + lr + 8*lb1][8*lb2]);
    u32 boff[4];
    #pragma unroll
    for (int nf2 = 0; nf2 < 4; nf2++)
        boff[nf2] = sptr(&Bs[0][wn + nf2*16 + lr + 8*lb2][8*lb1]);

    float acc[MF][8][4];
    #pragma unroll
    for (int i = 0; i < MF; i++)
        #pragma unroll
        for (int j = 0; j < 8; j++)
            #pragma unroll
            for (int r = 0; r < 4; r++) acc[i][j][r] = 0.f;

    int nit = (K + 31) / 32;

    // staging: each thread owns one row and a 32B segment (2 chunks)
    int srow = tid >> 1, scc = (tid & 1) * 2;
    const bf16* arow = A + (size_t)(bm0 + srow) * lda;
    int brn = srow;                       // B row this thread stages
    int gn = bn0 + brn;
    int bvalid = (brn < BN) && (gn < N);
    const bf16* brow = bvalid ? (W + (size_t)gn * ldw) : W;

    auto stage = [&](int it){
        int buf = it % 3;
        int k0 = it * 32;
        int kb = (k0 < K) ? k0 : 0;       // safe base when fully OOB
        int remB = (K - k0) * 2;
        u32 adst = sptr(&As[buf][srow][0]) + scc*16;
        #pragma unroll
        for (int c = 0; c < 2; c++) {
            int sv = remB - (scc + c)*16; sv = sv < 0 ? 0 : (sv > 16 ? 16 : sv);
            cpa16(adst + c*16, arow + kb + (scc + c)*8, sv);
        }
        if (brn < BN) {
            u32 bdst = sptr(&Bs[buf][brn][0]) + scc*16;
            #pragma unroll
            for (int c = 0; c < 2; c++) {
                int sv = remB - (scc + c)*16; sv = sv < 0 ? 0 : (sv > 16 ? 16 : sv);
                cpa16(bdst + c*16, brow + kb + (scc + c)*8, bvalid ? sv : 0);
            }
        }
        CP_COMMIT();
    };

    stage(0);
    stage(1);

    for (int it = 0; it < nit; it++) {
        int buf = it % 3;
        u32 bufA = buf * BUFA, bufB = buf * BUFB;
        CP_WAIT1();                 // group 'it' complete
        __syncthreads();

        if (it + 2 < nit) stage(it + 2);
        else CP_COMMIT();           // dummy group keeps numbering

        #pragma unroll
        for (int ks = 0; ks < 2; ks++) {
            u32 kadd = ks * 32;     // +16 cols * 2B
            u32 afr[MF][4];
            #pragma unroll
            for (int mf = 0; mf < MF; mf++)
                ldsm4(afr[mf][0], afr[mf][1], afr[mf][2], afr[mf][3],
                      aoff[mf] + bufA + kadd);
            u32 bfr[8][2];
            #pragma unroll
            for (int nf2 = 0; nf2 < 4; nf2++)
                ldsm4(bfr[2*nf2][0], bfr[2*nf2][1], bfr[2*nf2+1][0], bfr[2*nf2+1][1],
                      boff[nf2] + bufB + kadd);
            #pragma unroll
            for (int mf = 0; mf < MF; mf++)
                #pragma unroll
                for (int nf = 0; nf < 8; nf++)
                    mma16(acc[mf][nf], afr[mf], bfr[nf]);
        }
    }

    // ---- epilogue: bias + act + dual store ----
    #pragma unroll
    for (int mf = 0; mf < MF; mf++) {
        int mrow0 = bm0 + wm + mf*16 + g;       // and +8
        #pragma unroll
        for (int nf = 0; nf < 8; nf++) {
            int col = bn0 + wn + nf*8 + 2*ti;
            float b0 = 0.f, b1 = 0.f;
            if (bias) {
                if (col   < N) b0 = bias[col];
                if (col+1 < N) b1 = bias[col+1];
            }
            #pragma unroll
            for (int h = 0; h < 2; h++) {
                int m = mrow0 + h*8;
                float v0 = actf<ACT>(acc[mf][nf][2*h+0] + b0);
                float v1 = actf<ACT>(acc[mf][nf][2*h+1] + b1);
                if (Cf) {
                    float* crow = Cf + (size_t)m * ldc;
                    if (col + 1 < N)      *(float2*)(crow + col) = make_float2(v0, v1);
                    else if (col < N)     crow[col] = v0;
                }
                if (Cb) {
                    bf16* brow2 = Cb + (size_t)m * ldcb;
                    if (col + 1 < N)      *(__nv_bfloat162*)(brow2 + col) = __floats2bfloat162_rn(v0, v1);
                    else if (col < N)     brow2[col] = __float2bfloat16(v0);
                }
            }
        }
    }
}

// ---------------- depthwise causal conv (k=8) + bias + silu ----------------
__global__ void k_conv(const float* __restrict__ cw, const float* __restrict__ cb){
    int ch = blockIdx.y * 256 + threadIdx.x;
    int t0 = blockIdx.x * 16;
    int l0 = t0 & (Lq - 1);
    int tb = t0 - l0;

    float w[8];
    #pragma unroll
    for (int j = 0; j < 8; j++) w[j] = cw[ch*8 + j];
    float bv = cb[ch];

    float v[23];
    #pragma unroll
    for (int j = 0; j < 23; j++) {
        int l = l0 - 7 + j;
        v[j] = (l >= 0) ? __bfloat162float(g_xzbf[(size_t)(tb + l) * (2*DIv) + ch]) : 0.f;
    }
    #pragma unroll
    for (int o = 0; o < 16; o++) {
        float s = bv;
        #pragma unroll
        for (int j = 0; j < 8; j++) s = fmaf(v[o + j], w[j], s);
        float sil = s / (1.f + __expf(-s));
        g_xconvbf[(size_t)(t0 + o) * DIv + ch] = __float2bfloat16(sil);
    }
}

// ---------------- selective scan (serial over L, 3-stage smem windows) ----------------
#define SW 8
__global__ void __launch_bounds__(128) k_scan(const float* __restrict__ Alog,
                                              const float* __restrict__ Dw){
    int b   = blockIdx.y;
    int ch0 = blockIdx.x * 128;
    int tid = threadIdx.x;
    int ch  = ch0 + tid;

    __shared__ float    sD[3][SW][128];
    __shared__ __align__(16) uint16_t sXh[3][SW][128];
    __shared__ __align__(16) uint16_t sZh[3][SW][128];
    __shared__ __align__(16) float sBC[3][SW][32];

    float a[NST];
    bool fast = true;
    #pragma unroll
    for (int n = 0; n < NST; n++) {
        a[n] = -expf(Alog[ch*NST + n]);
        fast = fast && (fabsf(a[n] + (float)(n+1)) < 1e-4f * (float)(n+1));
    }
    float Dd = Dw[ch];

    float h[NST];
    #pragma unroll
    for (int n = 0; n < NST; n++) h[n] = 0.f;

    const size_t tb0 = (size_t)b * Lq;

    auto stage = [&](int wnd){
        int buf = wnd % 3;
        int t0 = wnd * SW;
        #pragma unroll
        for (int q = 0; q < 2; q++) {
            int idx = tid + q*128;
            int s = idx >> 5, cc = (idx & 31) * 4;
            cpa16(sptr(&sD[buf][s][cc]), &g_delta[(tb0 + t0 + s)*DIv + cc + ch0], 16);
        }
        {
            int s = tid >> 4, cc = (tid & 15) * 8;
            cpa16(sptr(&sXh[buf][s][cc]), &g_xconvbf[(tb0 + t0 + s)*DIv + cc + ch0], 16);
            cpa16(sptr(&sZh[buf][s][cc]),
                  &g_xzbf[(tb0 + t0 + s)*(2*DIv) + DIv + cc + ch0], 16);
        }
        if (tid < SW*8) {
            int s = tid >> 3, cc = (tid & 7) * 4;
            cpa16(sptr(&sBC[buf][s][cc]),
                  &g_dbc[(tb0 + t0 + s)*XDv + DTRANK + cc], 16);
        }
        CP_COMMIT();
    };

    stage(0);
    stage(1);

    for (int wnd = 0; wnd < Lq/SW; wnd++) {
        int buf = wnd % 3;
        CP_WAIT1();
        __syncthreads();
        if (wnd + 2 < Lq/SW) stage(wnd + 2);
        else CP_COMMIT();

        #pragma unroll
        for (int s = 0; s < SW; s++) {
            float delta = sD[buf][s][tid];
            float xv, zv;
            {
                __nv_bfloat16 xb, zb;
                *(uint16_t*)&xb = sXh[buf][s][tid];
                *(uint16_t*)&zb = sZh[buf][s][tid];
                xv = __bfloat162float(xb);
                zv = __bfloat162float(zb);
            }
            const float4* bcq = (const float4*)&sBC[buf][s][0];
            float4 q0 = bcq[0], q1 = bcq[1], q2 = bcq[2], q3 = bcq[3];
            float4 q4 = bcq[4], q5 = bcq[5], q6 = bcq[6], q7 = bcq[7];
            float Bv[NST] = {q0.x,q0.y,q0.z,q0.w, q1.x,q1.y,q1.z,q1.w,
                             q2.x,q2.y,q2.z,q2.w, q3.x,q3.y,q3.z,q3.w};
            float Cv[NST] = {q4.x,q4.y,q4.z,q4.w, q5.x,q5.y,q5.z,q5.w,
                             q6.x,q6.y,q6.z,q6.w, q7.x,q7.y,q7.z,q7.w};

            float dx = delta * xv;
            float y0 = 0.f, y1 = 0.f;
            if (fast) {
                float p  = __expf(-delta);
                float p2 = p*p, p4 = p2*p2, p8 = p4*p4;
                float p3 = p2*p, p5 = p4*p, p6 = p4*p2, p7 = p4*p3;
                float pw[NST] = {p, p2, p3, p4, p5, p6, p7, p8,
                                 p8*p, p8*p2, p8*p3, p8*p4, p8*p5, p8*p6, p8*p7, p8*p8};
                #pragma unroll
                for (int n = 0; n < NST; n += 2) {
                    h[n]   = fmaf(pw[n],   h[n],   dx * Bv[n]);
                    h[n+1] = fmaf(pw[n+1], h[n+1], dx * Bv[n+1]);
                    y0 = fmaf(h[n],   Cv[n],   y0);
                    y1 = fmaf(h[n+1], Cv[n+1], y1);
                }
            } else {
                #pragma unroll
                for (int n = 0; n < NST; n += 2) {
                    float dA0 = __expf(delta * a[n]);
                    float dA1 = __expf(delta * a[n+1]);
                    h[n]   = fmaf(dA0, h[n],   dx * Bv[n]);
                    h[n+1] = fmaf(dA1, h[n+1], dx * Bv[n+1]);
                    y0 = fmaf(h[n],   Cv[n],   y0);
                    y1 = fmaf(h[n+1], Cv[n+1], y1);
                }
            }
            float yy = fmaf(xv, Dd, y0 + y1);
            float sil = zv / (1.f + __expf(-zv));
            g_ybf[(tb0 + wnd*SW + s)*DIv + ch] = __float2bfloat16(yy * sil);
        }
    }
}

// ---------------- head MLP (M=8): 320 -> 512 -> 512 -> 1 ----------------
__global__ void __launch_bounds__(512) k_head(
    const float* __restrict__ w1, const float* __restrict__ b1,
    const float* __restrict__ w2, const float* __restrict__ b2,
    const float* __restrict__ w3, const float* __restrict__ b3,
    float* __restrict__ out)
{
    __shared__ float sh [8][320];
    __shared__ float sh1[8][512];
    __shared__ float sh2[8][512];
    int tid = threadIdx.x;

    for (int idx = tid; idx < 8*320; idx += 512) {
        int bb = idx / 320, c = idx % 320;
        sh[bb][c] = g_bufA[((size_t)bb * Lq + Lq - 1) * DMv + c];
    }
    __syncthreads();

    {
        int n = tid;
        float acc[8];
        #pragma unroll
        for (int bb = 0; bb < 8; bb++) acc[bb] = 0.f;
        const float* wr = w1 + (size_t)n * 320;
        for (int k = 0; k < 320; k++) {
            float wv = wr[k];
            #pragma unroll
            for (int bb = 0; bb < 8; bb++) acc[bb] = fmaf(wv, sh[bb][k], acc[bb]);
        }
        #pragma unroll
        for (int bb = 0; bb < 8; bb++) sh1[bb][n] = fmaxf(acc[bb] + b1[n], 0.f);
    }
    __syncthreads();

    {
        int n = tid;
        float acc[8];
        #pragma unroll
        for (int bb = 0; bb < 8; bb++) acc[bb] = 0.f;
        const float* wr = w2 + (size_t)n * 512;
        for (int k = 0; k < 512; k++) {
            float wv = wr[k];
            #pragma unroll
            for (int bb = 0; bb < 8; bb++) acc[bb] = fmaf(wv, sh1[bb][k], acc[bb]);
        }
        #pragma unroll
        for (int bb = 0; bb < 8; bb++) sh2[bb][n] = fmaxf(acc[bb] + b2[n], 0.f);
    }
    __syncthreads();

    if (tid < 8) {
        float acc = 0.f;
        for (int k = 0; k < 512; k++) acc = fmaf(w3[k], sh2[tid][k], acc);
        acc += b3[0];
        float scale = g_startmax / (1.f + logf((float)Lq));
        out[tid] = fmaxf(acc * scale, 0.f);
    }
}

// ---------------- host launch ----------------
extern "C" void kernel_launch(void* const* d_in, const int* in_sizes, int n_in,
                              void* d_out, int out_size)
{
    const float* x            = (const float*)d_in[0];
    const float* fc_w         = (const float*)d_in[1];
    const float* fc_b         = (const float*)d_in[2];
    const float* blk_lin_w    = (const float*)d_in[3];
    const float* blk_lin_b    = (const float*)d_in[4];
    const float* blk_inproj_w = (const float*)d_in[5];
    const float* blk_conv_w   = (const float*)d_in[6];
    const float* blk_conv_b   = (const float*)d_in[7];
    const float* blk_xproj_w  = (const float*)d_in[8];
    const float* blk_dtproj_w = (const float*)d_in[9];
    const float* blk_dtproj_b = (const float*)d_in[10];
    const float* blk_A_log    = (const float*)d_in[11];
    const float* blk_D        = (const float*)d_in[12];
    const float* blk_outproj_w= (const float*)d_in[13];
    const float* s1_w1        = (const float*)d_in[14];
    const float* s1_b1        = (const float*)d_in[15];
    const float* s1_w2        = (const float*)d_in[16];
    const float* s1_b2        = (const float*)d_in[17];
    const float* s1_w3        = (const float*)d_in[18];
    const float* s1_b3        = (const float*)d_in[19];

    void* p;
    cudaGetSymbolAddress(&p, g_dbc);     float* dbc     = (float*)p;
    cudaGetSymbolAddress(&p, g_delta);   float* delta   = (float*)p;
    cudaGetSymbolAddress(&p, g_bufA);    float* bufA    = (float*)p;
    cudaGetSymbolAddress(&p, g_bufAbf);  bf16* bufAbf   = (bf16*)p;
    cudaGetSymbolAddress(&p, g_ubf);     bf16* ubf      = (bf16*)p;
    cudaGetSymbolAddress(&p, g_xzbf);    bf16* xzbf     = (bf16*)p;
    cudaGetSymbolAddress(&p, g_xconvbf); bf16* xconvbf  = (bf16*)p;
    cudaGetSymbolAddress(&p, g_dbcbf);   bf16* dbcbf    = (bf16*)p;
    cudaGetSymbolAddress(&p, g_ybf);     bf16* ybf      = (bf16*)p;
    cudaGetSymbolAddress(&p, g_wlin);    bf16* wlin     = (bf16*)p;
    cudaGetSymbolAddress(&p, g_win);     bf16* win      = (bf16*)p;
    cudaGetSymbolAddress(&p, g_wxp);     bf16* wxp      = (bf16*)p;
    cudaGetSymbolAddress(&p, g_wdt);     bf16* wdt      = (bf16*)p;
    cudaGetSymbolAddress(&p, g_wout);    bf16* wout     = (bf16*)p;

    // merged weight conversion (1 launch)
    k_cvtall<<<(NQA + NDT + 255)/256, 256>>>(blk_lin_w, blk_inproj_w, blk_xproj_w,
                                             blk_dtproj_w, blk_outproj_w);
    k_startmax<<<1, 256>>>(x);
    k_embed<<<Tq, DMv>>>(x, fc_w, fc_b);

    for (int i = 0; i < NBLK; i++) {
        // lin: tanh(bufA @ lin_w^T + b) -> u(bf16)   [Tq,320] K=320
        k_bgemm<1,128><<<dim3(3, Tq/128), 256>>>(
            bufAbf, DMv, wlin + (size_t)i*DMv*DMv, DMv,
            blk_lin_b + (size_t)i*DMv,
            (float*)nullptr, 0, ubf, DMv, Tq, DMv, DMv);

        // inproj: u @ inproj_w^T -> xz(bf16)   [Tq,2560] K=320
        k_bgemm<0,128><<<dim3(20, Tq/128), 256>>>(
            ubf, DMv, win + (size_t)i*2*DIv*DMv, DMv,
            (const float*)nullptr,
            (float*)nullptr, 0, xzbf, 2*DIv, Tq, 2*DIv, DMv);

        // depthwise causal conv + silu -> xconv(bf16)
        k_conv<<<dim3(Tq/16, DIv/256), 256>>>(
            blk_conv_w + (size_t)i*DIv*DCONVK, blk_conv_b + (size_t)i*DIv);

        // xproj: xconv @ xproj_w^T -> dbc (f32) + dbcbf (bf16)   [Tq,52] K=1280
        k_bgemm<0,64><<<dim3(1, Tq/128), 256>>>(
            xconvbf, DIv, wxp + (size_t)i*XDv*DIv, DIv,
            (const float*)nullptr,
            dbc, XDv, dbcbf, 56, Tq, XDv, DIv);

        // dtproj: softplus(dbc[:, :20] @ dtproj_w^T + b) -> delta(f32)   [Tq,1280] K=20
        k_bgemm<2,128><<<dim3(10, Tq/128), 256>>>(
            dbcbf, 56, wdt + (size_t)i*DIv*24, 24,
            blk_dtproj_b + (size_t)i*DIv,
            delta, DIv, (bf16*)nullptr, 0, Tq, DIv, DTRANK);

        // selective scan -> y(bf16)
        k_scan<<<dim3(DIv/128, Bq), 128>>>(
            blk_A_log + (size_t)i*DIv*NST, blk_D + (size_t)i*DIv);

        // outproj: elu(y @ outproj_w^T) -> bufA (f32 + bf16)   [Tq,320] K=1280
        k_bgemm<3,128><<<dim3(3, Tq/128), 256>>>(
            ybf, DIv, wout + (size_t)i*DMv*DIv, DIv,
            (const float*)nullptr,
            bufA, DMv, bufAbf, DMv, Tq, DMv, DIv);
    }

    k_head<<<1, 512>>>(s1_w1, s1_b1, s1_w2, s1_b2, s1_w3, s1_b3, (float*)d_out);
}

// round 10
// speedup vs baseline: 5.2455x; 1.2966x over previous
#include <cuda_runtime.h>
#include <cuda_bf16.h>
#include <math.h>
#include <stdint.h>

// ---------------- problem constants ----------------
#define Bq      8
#define Lq      2048
#define Tq      (Bq*Lq)        // 16384 tokens
#define DMv     320
#define DIv     1280
#define NST     16
#define DCONVK  8
#define DTRANK  20
#define XDv     52             // DTRANK + 2*NST
#define NBLK    4

typedef uint32_t u32;
typedef __nv_bfloat16 bf16;

// ---------------- static device scratch (no allocations) ----------------
__device__ __align__(256) float g_bufA [Tq*DMv];          // fp32 (head input)
__device__ __align__(256) float g_dbc  [Tq*XDv];
__device__ __align__(256) float g_delta[(size_t)Tq*DIv];
__device__ float g_startmax;

// bf16 activations
__device__ __align__(256) bf16 g_bufAbf [Tq*DMv];
__device__ __align__(256) bf16 g_ubf    [Tq*DMv];
__device__ __align__(256) bf16 g_xzbf   [(size_t)Tq*2*DIv];  // inproj out (x | z)
__device__ __align__(256) bf16 g_xconvbf[(size_t)Tq*DIv];
__device__ __align__(256) bf16 g_dbcbf  [Tq*56];             // stride 56
__device__ __align__(256) bf16 g_ybf    [(size_t)Tq*DIv];

// bf16 weights (converted once per launch)
__device__ __align__(256) bf16 g_wlin[NBLK*320*320];
__device__ __align__(256) bf16 g_win [NBLK*2560*320];
__device__ __align__(256) bf16 g_wxp [NBLK*52*1280];
__device__ __align__(256) bf16 g_wdt [NBLK*1280*24];         // stride 24 (K=20 padded)
__device__ __align__(256) bf16 g_wout[NBLK*320*1280];

// ---------------- helpers ----------------
__device__ __forceinline__ u32 sptr(const void* p){
    return (u32)__cvta_generic_to_shared(p);
}
__device__ __forceinline__ void cpa16(u32 dst, const void* src, int sz){
    asm volatile("cp.async.ca.shared.global [%0], [%1], 16, %2;"
                 :: "r"(dst), "l"(src), "r"(sz) : "memory");
}
#define CP_COMMIT() asm volatile("cp.async.commit_group;" ::: "memory")
#define CP_WAIT1()  asm volatile("cp.async.wait_group 1;" ::: "memory")

__device__ __forceinline__ void mma16(float* c, const u32* a, const u32* b){
    asm volatile("mma.sync.aligned.m16n8k16.row.col.f32.bf16.bf16.f32 "
        "{%0,%1,%2,%3}, {%4,%5,%6,%7}, {%8,%9}, {%0,%1,%2,%3};"
        : "+f"(c[0]), "+f"(c[1]), "+f"(c[2]), "+f"(c[3])
        : "r"(a[0]), "r"(a[1]), "r"(a[2]), "r"(a[3]), "r"(b[0]), "r"(b[1]));
}
__device__ __forceinline__ void ldsm4(u32& r0, u32& r1, u32& r2, u32& r3, u32 addr){
    asm volatile("ldmatrix.sync.aligned.m8n8.x4.shared.b16 {%0,%1,%2,%3}, [%4];"
        : "=r"(r0), "=r"(r1), "=r"(r2), "=r"(r3) : "r"(addr));
}

// ---------------- merged weight conversion ----------------
#define NQ1 (NBLK*320*320/4)      // wlin quads
#define NQ2 (NBLK*2560*320/4)     // win
#define NQ3 (NBLK*52*1280/4)      // wxp
#define NQ5 (NBLK*320*1280/4)     // wout
#define NQA (NQ1+NQ2+NQ3+NQ5)
#define NDT (NBLK*1280*24)        // wdt padded elems
__global__ void k_cvtall(const float* __restrict__ lw, const float* __restrict__ iw,
                         const float* __restrict__ xw, const float* __restrict__ dw,
                         const float* __restrict__ ow){
    int i = blockIdx.x * 256 + threadIdx.x;
    if (i < NQA) {
        const float* s; bf16* d; int q = i;
        if (q < NQ1)                { s = lw; d = g_wlin; }
        else if ((q -= NQ1) < NQ2)  { s = iw; d = g_win;  }
        else if ((q -= NQ2) < NQ3)  { s = xw; d = g_wxp;  }
        else                        { q -= NQ3; s = ow; d = g_wout; }
        float4 v = *(const float4*)(s + q*4);
        d[q*4+0] = __float2bfloat16(v.x);
        d[q*4+1] = __float2bfloat16(v.y);
        d[q*4+2] = __float2bfloat16(v.z);
        d[q*4+3] = __float2bfloat16(v.w);
    } else if (i < NQA + NDT) {
        int idx = i - NQA;
        int r = idx / 24, c = idx % 24;
        g_wdt[idx] = (c < 20) ? __float2bfloat16(dw[r*20 + c]) : __float2bfloat16(0.f);
    }
}

// ---------------- start_max reduction ----------------
__global__ void k_startmax(const float* __restrict__ x){
    __shared__ float red[256];
    float m = -1e30f;
    for (int i = threadIdx.x; i < Tq; i += 256) m = fmaxf(m, x[i*4 + 2]);
    red[threadIdx.x] = m; __syncthreads();
    for (int s = 128; s > 0; s >>= 1){
        if (threadIdx.x < s) red[threadIdx.x] = fmaxf(red[threadIdx.x], red[threadIdx.x + s]);
        __syncthreads();
    }
    if (threadIdx.x == 0) g_startmax = red[0];
}

// ---------------- embedding: normalize + fc (K=4) -> bf16 ----------------
__global__ void k_embed(const float* __restrict__ x, const float* __restrict__ fcw,
                        const float* __restrict__ fcb){
    int t = blockIdx.x, c = threadIdx.x;      // grid Tq, block DMv
    float x0 = x[t*4+0], x1 = x[t*4+1], x2 = x[t*4+2], x3 = x[t*4+3];
    float n0 = x0 * (1.0f/255.0f), n1 = x1 * (1.0f/255.0f), n2 = x2 / g_startmax, n3 = x3;
    const float* w = fcw + c*4;
    float v = fcb[c] + n0*w[0] + n1*w[1] + n2*w[2] + n3*w[3];
    g_bufAbf[(size_t)t*DMv + c] = __float2bfloat16(v);
}

// ---------------- epilogue activation (fast; outputs land in bf16) ----------------
template<int ACT> __device__ __forceinline__ float actf(float v){
    if (ACT == 1) {                       // tanh = 1 - 2/(e^{2v}+1)
        float e = __expf(2.f * v);
        return 1.f - __fdividef(2.f, e + 1.f);
    }
    if (ACT == 2) {                       // softplus
        return (v > 20.f) ? v : __logf(1.f + __expf(v));
    }
    if (ACT == 3) {                       // elu
        return (v > 0.f) ? v : (__expf(v) - 1.f);
    }
    return v;
}

// ---------------- bf16 mma.sync GEMM, ldmatrix + 3-stage cp.async ----------------
// C = act(A[M,K](bf16) @ W[N,K](bf16)^T (+bias)); outputs f32 Cf and/or bf16 Cb.
// CTA tile 128x64, BK=32, 256 threads (8 warps, 4m x 2n, warp tile 32x32).
// 3 CTAs/SM target (launch_bounds minBlocks=3 caps regs).
#define SBK 40
#define BN  64

template<int ACT>
__global__ void __launch_bounds__(256, 3) k_bgemm(
    const bf16* __restrict__ A, int lda,
    const bf16* __restrict__ W, int ldw,
    const float* __restrict__ bias,
    float* __restrict__ Cf, int ldc,
    bf16* __restrict__ Cb, int ldcb,
    int M, int N, int K)
{
    __shared__ __align__(16) uint16_t As[3][128][SBK];
    __shared__ __align__(16) uint16_t Bs[3][BN][SBK];
    const u32 BUFA = 128*SBK*2, BUFB = BN*SBK*2;

    int tid  = threadIdx.x;
    int lane = tid & 31, w = tid >> 5;
    int wm = (w & 3) * 32;
    int wn = (w >> 2) * 32;
    int g = lane >> 2, ti = lane & 3;
    int bm0 = blockIdx.y * 128, bn0 = blockIdx.x * BN;

    // ldmatrix per-lane base addresses (buf 0, ks 0)
    int lr  = lane & 7;
    int lb1 = (lane >> 3) & 1;
    int lb2 = (lane >> 4) & 1;
    u32 aoff[2];
    #pragma unroll
    for (int mf = 0; mf < 2; mf++)
        aoff[mf] = sptr(&As[0][wm + mf*16 + lr + 8*lb1][8*lb2]);
    u32 boff[2];
    #pragma unroll
    for (int nf2 = 0; nf2 < 2; nf2++)
        boff[nf2] = sptr(&Bs[0][wn + nf2*16 + lr + 8*lb2][8*lb1]);

    float acc[2][4][4];
    #pragma unroll
    for (int i = 0; i < 2; i++)
        #pragma unroll
        for (int j = 0; j < 4; j++)
            #pragma unroll
            for (int r = 0; r < 4; r++) acc[i][j][r] = 0.f;

    int nit = (K + 31) / 32;

    // staging: A row per 2 threads (2 chunks each); B row per 4 threads (1 chunk)
    int srow = tid >> 1, scc = (tid & 1) * 2;
    int brn  = tid >> 2, bcc = tid & 3;
    const bf16* arow = A + (size_t)(bm0 + srow) * lda;
    int gn = bn0 + brn;
    int bvalid = (gn < N);
    const bf16* brow = bvalid ? (W + (size_t)gn * ldw) : W;

    auto stage = [&](int it){
        int buf = it % 3;
        int k0 = it * 32;
        int kb = (k0 < K) ? k0 : 0;
        int remB = (K - k0) * 2;
        u32 adst = sptr(&As[buf][srow][0]) + scc*16;
        #pragma unroll
        for (int c = 0; c < 2; c++) {
            int sv = remB - (scc + c)*16; sv = sv < 0 ? 0 : (sv > 16 ? 16 : sv);
            cpa16(adst + c*16, arow + kb + (scc + c)*8, sv);
        }
        {
            u32 bdst = sptr(&Bs[buf][brn][0]) + bcc*16;
            int sv = remB - bcc*16; sv = sv < 0 ? 0 : (sv > 16 ? 16 : sv);
            cpa16(bdst, brow + kb + bcc*8, bvalid ? sv : 0);
        }
        CP_COMMIT();
    };

    stage(0);
    stage(1);

    for (int it = 0; it < nit; it++) {
        int buf = it % 3;
        u32 bufA = buf * BUFA, bufB = buf * BUFB;
        CP_WAIT1();                 // group 'it' complete
        __syncthreads();

        if (it + 2 < nit) stage(it + 2);
        else CP_COMMIT();           // dummy group keeps numbering

        #pragma unroll
        for (int ks = 0; ks < 2; ks++) {
            u32 kadd = ks * 32;     // +16 cols * 2B
            u32 afr[2][4];
            #pragma unroll
            for (int mf = 0; mf < 2; mf++)
                ldsm4(afr[mf][0], afr[mf][1], afr[mf][2], afr[mf][3],
                      aoff[mf] + bufA + kadd);
            u32 bfr[4][2];
            #pragma unroll
            for (int nf2 = 0; nf2 < 2; nf2++)
                ldsm4(bfr[2*nf2][0], bfr[2*nf2][1], bfr[2*nf2+1][0], bfr[2*nf2+1][1],
                      boff[nf2] + bufB + kadd);
            #pragma unroll
            for (int mf = 0; mf < 2; mf++)
                #pragma unroll
                for (int nf = 0; nf < 4; nf++)
                    mma16(acc[mf][nf], afr[mf], bfr[nf]);
        }
    }

    // ---- epilogue: bias + act + dual store ----
    #pragma unroll
    for (int mf = 0; mf < 2; mf++) {
        int mrow0 = bm0 + wm + mf*16 + g;       // and +8
        #pragma unroll
        for (int nf = 0; nf < 4; nf++) {
            int col = bn0 + wn + nf*8 + 2*ti;
            float b0 = 0.f, b1 = 0.f;
            if (bias) {
                if (col   < N) b0 = bias[col];
                if (col+1 < N) b1 = bias[col+1];
            }
            #pragma unroll
            for (int h = 0; h < 2; h++) {
                int m = mrow0 + h*8;
                float v0 = actf<ACT>(acc[mf][nf][2*h+0] + b0);
                float v1 = actf<ACT>(acc[mf][nf][2*h+1] + b1);
                if (Cf) {
                    float* crow = Cf + (size_t)m * ldc;
                    if (col + 1 < N)      *(float2*)(crow + col) = make_float2(v0, v1);
                    else if (col < N)     crow[col] = v0;
                }
                if (Cb) {
                    bf16* brow2 = Cb + (size_t)m * ldcb;
                    if (col + 1 < N)      *(__nv_bfloat162*)(brow2 + col) = __floats2bfloat162_rn(v0, v1);
                    else if (col < N)     brow2[col] = __float2bfloat16(v0);
                }
            }
        }
    }
}

// ---------------- depthwise causal conv (k=8) + bias + silu ----------------
__global__ void k_conv(const float* __restrict__ cw, const float* __restrict__ cb){
    int ch = blockIdx.y * 256 + threadIdx.x;
    int t0 = blockIdx.x * 16;
    int l0 = t0 & (Lq - 1);
    int tb = t0 - l0;

    float w[8];
    #pragma unroll
    for (int j = 0; j < 8; j++) w[j] = cw[ch*8 + j];
    float bv = cb[ch];

    float v[23];
    #pragma unroll
    for (int j = 0; j < 23; j++) {
        int l = l0 - 7 + j;
        v[j] = (l >= 0) ? __bfloat162float(g_xzbf[(size_t)(tb + l) * (2*DIv) + ch]) : 0.f;
    }
    #pragma unroll
    for (int o = 0; o < 16; o++) {
        float s = bv;
        #pragma unroll
        for (int j = 0; j < 8; j++) s = fmaf(v[o + j], w[j], s);
        float sil = s * __fdividef(1.f, 1.f + __expf(-s));
        g_xconvbf[(size_t)(t0 + o) * DIv + ch] = __float2bfloat16(sil);
    }
}

// ---------------- selective scan (serial over L, 3-stage smem windows, 64 thr) ----------------
#define SW 8
#define SCH 64
__global__ void __launch_bounds__(SCH) k_scan(const float* __restrict__ Alog,
                                              const float* __restrict__ Dw){
    int b   = blockIdx.y;
    int ch0 = blockIdx.x * SCH;
    int tid = threadIdx.x;
    int ch  = ch0 + tid;

    __shared__ float    sD[3][SW][SCH];
    __shared__ __align__(16) uint16_t sXh[3][SW][SCH];
    __shared__ __align__(16) uint16_t sZh[3][SW][SCH];
    __shared__ __align__(16) float sBC[3][SW][32];

    float a[NST];
    bool fast = true;
    #pragma unroll
    for (int n = 0; n < NST; n++) {
        a[n] = -expf(Alog[ch*NST + n]);
        fast = fast && (fabsf(a[n] + (float)(n+1)) < 1e-4f * (float)(n+1));
    }
    float Dd = Dw[ch];

    float h[NST];
    #pragma unroll
    for (int n = 0; n < NST; n++) h[n] = 0.f;

    const size_t tb0 = (size_t)b * Lq;

    auto stage = [&](int wnd){
        int buf = wnd % 3;
        int t0 = wnd * SW;
        // delta: SW x 64 floats = 128 chunks, 2/thread
        #pragma unroll
        for (int q = 0; q < 2; q++) {
            int idx = tid + q*SCH;
            int s = idx >> 4, cc = (idx & 15) * 4;
            cpa16(sptr(&sD[buf][s][cc]), &g_delta[(tb0 + t0 + s)*DIv + cc + ch0], 16);
        }
        // x, z: SW x 64 bf16 = 64 chunks, 1/thread each
        {
            int s = tid >> 3, cc = (tid & 7) * 8;
            cpa16(sptr(&sXh[buf][s][cc]), &g_xconvbf[(tb0 + t0 + s)*DIv + cc + ch0], 16);
            cpa16(sptr(&sZh[buf][s][cc]),
                  &g_xzbf[(tb0 + t0 + s)*(2*DIv) + DIv + cc + ch0], 16);
        }
        // BC: SW x 32 floats = 64 chunks, 1/thread
        {
            int s = tid >> 3, cc = (tid & 7) * 4;
            cpa16(sptr(&sBC[buf][s][cc]),
                  &g_dbc[(tb0 + t0 + s)*XDv + DTRANK + cc], 16);
        }
        CP_COMMIT();
    };

    stage(0);
    stage(1);

    for (int wnd = 0; wnd < Lq/SW; wnd++) {
        int buf = wnd % 3;
        CP_WAIT1();
        __syncthreads();
        if (wnd + 2 < Lq/SW) stage(wnd + 2);
        else CP_COMMIT();

        #pragma unroll
        for (int s = 0; s < SW; s++) {
            float delta = sD[buf][s][tid];
            float xv, zv;
            {
                __nv_bfloat16 xb, zb;
                *(uint16_t*)&xb = sXh[buf][s][tid];
                *(uint16_t*)&zb = sZh[buf][s][tid];
                xv = __bfloat162float(xb);
                zv = __bfloat162float(zb);
            }
            const float4* bcq = (const float4*)&sBC[buf][s][0];
            float4 q0 = bcq[0], q1 = bcq[1], q2 = bcq[2], q3 = bcq[3];
            float4 q4 = bcq[4], q5 = bcq[5], q6 = bcq[6], q7 = bcq[7];
            float Bv[NST] = {q0.x,q0.y,q0.z,q0.w, q1.x,q1.y,q1.z,q1.w,
                             q2.x,q2.y,q2.z,q2.w, q3.x,q3.y,q3.z,q3.w};
            float Cv[NST] = {q4.x,q4.y,q4.z,q4.w, q5.x,q5.y,q5.z,q5.w,
                             q6.x,q6.y,q6.z,q6.w, q7.x,q7.y,q7.z,q7.w};

            float dx = delta * xv;
            float y0 = 0.f, y1 = 0.f;
            if (fast) {
                float p  = __expf(-delta);
                float p2 = p*p, p4 = p2*p2, p8 = p4*p4;
                float p3 = p2*p, p5 = p4*p, p6 = p4*p2, p7 = p4*p3;
                float pw[NST] = {p, p2, p3, p4, p5, p6, p7, p8,
                                 p8*p, p8*p2, p8*p3, p8*p4, p8*p5, p8*p6, p8*p7, p8*p8};
                #pragma unroll
                for (int n = 0; n < NST; n += 2) {
                    h[n]   = fmaf(pw[n],   h[n],   dx * Bv[n]);
                    h[n+1] = fmaf(pw[n+1], h[n+1], dx * Bv[n+1]);
                    y0 = fmaf(h[n],   Cv[n],   y0);
                    y1 = fmaf(h[n+1], Cv[n+1], y1);
                }
            } else {
                #pragma unroll
                for (int n = 0; n < NST; n += 2) {
                    float dA0 = __expf(delta * a[n]);
                    float dA1 = __expf(delta * a[n+1]);
                    h[n]   = fmaf(dA0, h[n],   dx * Bv[n]);
                    h[n+1] = fmaf(dA1, h[n+1], dx * Bv[n+1]);
                    y0 = fmaf(h[n],   Cv[n],   y0);
                    y1 = fmaf(h[n+1], Cv[n+1], y1);
                }
            }
            float yy = fmaf(xv, Dd, y0 + y1);
            float sil = zv * __fdividef(1.f, 1.f + __expf(-zv));
            g_ybf[(tb0 + wnd*SW + s)*DIv + ch] = __float2bfloat16(yy * sil);
        }
    }
}

// ---------------- head MLP (M=8): 320 -> 512 -> 512 -> 1 ----------------
__global__ void __launch_bounds__(512) k_head(
    const float* __restrict__ w1, const float* __restrict__ b1,
    const float* __restrict__ w2, const float* __restrict__ b2,
    const float* __restrict__ w3, const float* __restrict__ b3,
    float* __restrict__ out)
{
    __shared__ float sh [8][320];
    __shared__ float sh1[8][512];
    __shared__ float sh2[8][512];
    int tid = threadIdx.x;

    for (int idx = tid; idx < 8*320; idx += 512) {
        int bb = idx / 320, c = idx % 320;
        sh[bb][c] = g_bufA[((size_t)bb * Lq + Lq - 1) * DMv + c];
    }
    __syncthreads();

    {
        int n = tid;
        float acc[8];
        #pragma unroll
        for (int bb = 0; bb < 8; bb++) acc[bb] = 0.f;
        const float* wr = w1 + (size_t)n * 320;
        for (int k = 0; k < 320; k++) {
            float wv = wr[k];
            #pragma unroll
            for (int bb = 0; bb < 8; bb++) acc[bb] = fmaf(wv, sh[bb][k], acc[bb]);
        }
        #pragma unroll
        for (int bb = 0; bb < 8; bb++) sh1[bb][n] = fmaxf(acc[bb] + b1[n], 0.f);
    }
    __syncthreads();

    {
        int n = tid;
        float acc[8];
        #pragma unroll
        for (int bb = 0; bb < 8; bb++) acc[bb] = 0.f;
        const float* wr = w2 + (size_t)n * 512;
        for (int k = 0; k < 512; k++) {
            float wv = wr[k];
            #pragma unroll
            for (int bb = 0; bb < 8; bb++) acc[bb] = fmaf(wv, sh1[bb][k], acc[bb]);
        }
        #pragma unroll
        for (int bb = 0; bb < 8; bb++) sh2[bb][n] = fmaxf(acc[bb] + b2[n], 0.f);
    }
    __syncthreads();

    if (tid < 8) {
        float acc = 0.f;
        for (int k = 0; k < 512; k++) acc = fmaf(w3[k], sh2[tid][k], acc);
        acc += b3[0];
        float scale = g_startmax / (1.f + logf((float)Lq));
        out[tid] = fmaxf(acc * scale, 0.f);
    }
}

// ---------------- host launch ----------------
extern "C" void kernel_launch(void* const* d_in, const int* in_sizes, int n_in,
                              void* d_out, int out_size)
{
    const float* x            = (const float*)d_in[0];
    const float* fc_w         = (const float*)d_in[1];
    const float* fc_b         = (const float*)d_in[2];
    const float* blk_lin_w    = (const float*)d_in[3];
    const float* blk_lin_b    = (const float*)d_in[4];
    const float* blk_inproj_w = (const float*)d_in[5];
    const float* blk_conv_w   = (const float*)d_in[6];
    const float* blk_conv_b   = (const float*)d_in[7];
    const float* blk_xproj_w  = (const float*)d_in[8];
    const float* blk_dtproj_w = (const float*)d_in[9];
    const float* blk_dtproj_b = (const float*)d_in[10];
    const float* blk_A_log    = (const float*)d_in[11];
    const float* blk_D        = (const float*)d_in[12];
    const float* blk_outproj_w= (const float*)d_in[13];
    const float* s1_w1        = (const float*)d_in[14];
    const float* s1_b1        = (const float*)d_in[15];
    const float* s1_w2        = (const float*)d_in[16];
    const float* s1_b2        = (const float*)d_in[17];
    const float* s1_w3        = (const float*)d_in[18];
    const float* s1_b3        = (const float*)d_in[19];

    void* p;
    cudaGetSymbolAddress(&p, g_dbc);     float* dbc     = (float*)p;
    cudaGetSymbolAddress(&p, g_delta);   float* delta   = (float*)p;
    cudaGetSymbolAddress(&p, g_bufA);    float* bufA    = (float*)p;
    cudaGetSymbolAddress(&p, g_bufAbf);  bf16* bufAbf   = (bf16*)p;
    cudaGetSymbolAddress(&p, g_ubf);     bf16* ubf      = (bf16*)p;
    cudaGetSymbolAddress(&p, g_xzbf);    bf16* xzbf     = (bf16*)p;
    cudaGetSymbolAddress(&p, g_xconvbf); bf16* xconvbf  = (bf16*)p;
    cudaGetSymbolAddress(&p, g_dbcbf);   bf16* dbcbf    = (bf16*)p;
    cudaGetSymbolAddress(&p, g_ybf);     bf16* ybf      = (bf16*)p;
    cudaGetSymbolAddress(&p, g_wlin);    bf16* wlin     = (bf16*)p;
    cudaGetSymbolAddress(&p, g_win);     bf16* win      = (bf16*)p;
    cudaGetSymbolAddress(&p, g_wxp);     bf16* wxp      = (bf16*)p;
    cudaGetSymbolAddress(&p, g_wdt);     bf16* wdt      = (bf16*)p;
    cudaGetSymbolAddress(&p, g_wout);    bf16* wout     = (bf16*)p;

    // merged weight conversion (1 launch)
    k_cvtall<<<(NQA + NDT + 255)/256, 256>>>(blk_lin_w, blk_inproj_w, blk_xproj_w,
                                             blk_dtproj_w, blk_outproj_w);
    k_startmax<<<1, 256>>>(x);
    k_embed<<<Tq, DMv>>>(x, fc_w, fc_b);

    for (int i = 0; i < NBLK; i++) {
        // lin: tanh(bufA @ lin_w^T + b) -> u(bf16)   [Tq,320] K=320
        k_bgemm<1><<<dim3(5, Tq/128), 256>>>(
            bufAbf, DMv, wlin + (size_t)i*DMv*DMv, DMv,
            blk_lin_b + (size_t)i*DMv,
            (float*)nullptr, 0, ubf, DMv, Tq, DMv, DMv);

        // inproj: u @ inproj_w^T -> xz(bf16)   [Tq,2560] K=320
        k_bgemm<0><<<dim3(40, Tq/128), 256>>>(
            ubf, DMv, win + (size_t)i*2*DIv*DMv, DMv,
            (const float*)nullptr,
            (float*)nullptr, 0, xzbf, 2*DIv, Tq, 2*DIv, DMv);

        // depthwise causal conv + silu -> xconv(bf16)
        k_conv<<<dim3(Tq/16, DIv/256), 256>>>(
            blk_conv_w + (size_t)i*DIv*DCONVK, blk_conv_b + (size_t)i*DIv);

        // xproj: xconv @ xproj_w^T -> dbc (f32) + dbcbf (bf16)   [Tq,52] K=1280
        k_bgemm<0><<<dim3(1, Tq/128), 256>>>(
            xconvbf, DIv, wxp + (size_t)i*XDv*DIv, DIv,
            (const float*)nullptr,
            dbc, XDv, dbcbf, 56, Tq, XDv, DIv);

        // dtproj: softplus(dbc[:, :20] @ dtproj_w^T + b) -> delta(f32)   [Tq,1280] K=20
        k_bgemm<2><<<dim3(20, Tq/128), 256>>>(
            dbcbf, 56, wdt + (size_t)i*DIv*24, 24,
            blk_dtproj_b + (size_t)i*DIv,
            delta, DIv, (bf16*)nullptr, 0, Tq, DIv, DTRANK);

        // selective scan -> y(bf16)
        k_scan<<<dim3(DIv/SCH, Bq), SCH>>>(
            blk_A_log + (size_t)i*DIv*NST, blk_D + (size_t)i*DIv);

        // outproj: elu(y @ outproj_w^T) -> bufA (f32 + bf16)   [Tq,320] K=1280
        k_bgemm<3><<<dim3(5, Tq/128), 256>>>(
            ybf, DIv, wout + (size_t)i*DMv*DIv, DIv,
            (const float*)nullptr,
            bufA, DMv, bufAbf, DMv, Tq, DMv, DIv);
    }

    k_head<<<1, 512>>>(s1_w1, s1_b1, s1_w2, s1_b2, s1_w3, s1_b3, (float*)d_out);
}

// round 11
// speedup vs baseline: 5.5570x; 1.0594x over previous
#include <cuda_runtime.h>
#include <cuda_bf16.h>
#include <math.h>
#include <stdint.h>

// ---------------- problem constants ----------------
#define Bq      8
#define Lq      2048
#define Tq      (Bq*Lq)        // 16384 tokens
#define DMv     320
#define DIv     1280
#define NST     16
#define DCONVK  8
#define DTRANK  20
#define XDv     52             // DTRANK + 2*NST
#define NBLK    4

typedef uint32_t u32;
typedef __nv_bfloat16 bf16;

// ---------------- static device scratch (no allocations) ----------------
__device__ __align__(256) float g_bufA [Tq*DMv];          // fp32 (head input)
__device__ __align__(256) float g_dbc  [Tq*XDv];
__device__ float g_startmax;

// bf16 activations
__device__ __align__(256) bf16 g_bufAbf [Tq*DMv];
__device__ __align__(256) bf16 g_ubf    [Tq*DMv];
__device__ __align__(256) bf16 g_xzbf   [(size_t)Tq*2*DIv];  // inproj out (x | silu(z))
__device__ __align__(256) bf16 g_xconvbf[(size_t)Tq*DIv];
__device__ __align__(256) bf16 g_dbcbf  [Tq*56];             // stride 56
__device__ __align__(256) bf16 g_deltabf[(size_t)Tq*DIv];
__device__ __align__(256) bf16 g_ybf    [(size_t)Tq*DIv];

// bf16 weights (converted once per launch)
__device__ __align__(256) bf16 g_wlin[NBLK*320*320];
__device__ __align__(256) bf16 g_win [NBLK*2560*320];
__device__ __align__(256) bf16 g_wxp [NBLK*52*1280];
__device__ __align__(256) bf16 g_wdt [NBLK*1280*24];         // stride 24 (K=20 padded)
__device__ __align__(256) bf16 g_wout[NBLK*320*1280];

// ---------------- helpers ----------------
__device__ __forceinline__ u32 sptr(const void* p){
    return (u32)__cvta_generic_to_shared(p);
}
__device__ __forceinline__ void cpa16(u32 dst, const void* src, int sz){
    asm volatile("cp.async.ca.shared.global [%0], [%1], 16, %2;"
                 :: "r"(dst), "l"(src), "r"(sz) : "memory");
}
#define CP_COMMIT() asm volatile("cp.async.commit_group;" ::: "memory")
#define CP_WAIT1()  asm volatile("cp.async.wait_group 1;" ::: "memory")

__device__ __forceinline__ void mma16(float* c, const u32* a, const u32* b){
    asm volatile("mma.sync.aligned.m16n8k16.row.col.f32.bf16.bf16.f32 "
        "{%0,%1,%2,%3}, {%4,%5,%6,%7}, {%8,%9}, {%0,%1,%2,%3};"
        : "+f"(c[0]), "+f"(c[1]), "+f"(c[2]), "+f"(c[3])
        : "r"(a[0]), "r"(a[1]), "r"(a[2]), "r"(a[3]), "r"(b[0]), "r"(b[1]));
}
__device__ __forceinline__ void ldsm4(u32& r0, u32& r1, u32& r2, u32& r3, u32 addr){
    asm volatile("ldmatrix.sync.aligned.m8n8.x4.shared.b16 {%0,%1,%2,%3}, [%4];"
        : "=r"(r0), "=r"(r1), "=r"(r2), "=r"(r3) : "r"(addr));
}

// ---------------- merged weight conversion ----------------
#define NQ1 (NBLK*320*320/4)      // wlin quads
#define NQ2 (NBLK*2560*320/4)     // win
#define NQ3 (NBLK*52*1280/4)      // wxp
#define NQ5 (NBLK*320*1280/4)     // wout
#define NQA (NQ1+NQ2+NQ3+NQ5)
#define NDT (NBLK*1280*24)        // wdt padded elems
__global__ void k_cvtall(const float* __restrict__ lw, const float* __restrict__ iw,
                         const float* __restrict__ xw, const float* __restrict__ dw,
                         const float* __restrict__ ow){
    int i = blockIdx.x * 256 + threadIdx.x;
    if (i < NQA) {
        const float* s; bf16* d; int q = i;
        if (q < NQ1)                { s = lw; d = g_wlin; }
        else if ((q -= NQ1) < NQ2)  { s = iw; d = g_win;  }
        else if ((q -= NQ2) < NQ3)  { s = xw; d = g_wxp;  }
        else                        { q -= NQ3; s = ow; d = g_wout; }
        float4 v = *(const float4*)(s + q*4);
        d[q*4+0] = __float2bfloat16(v.x);
        d[q*4+1] = __float2bfloat16(v.y);
        d[q*4+2] = __float2bfloat16(v.z);
        d[q*4+3] = __float2bfloat16(v.w);
    } else if (i < NQA + NDT) {
        int idx = i - NQA;
        int r = idx / 24, c = idx % 24;
        g_wdt[idx] = (c < 20) ? __float2bfloat16(dw[r*20 + c]) : __float2bfloat16(0.f);
    }
}

// ---------------- start_max reduction ----------------
__global__ void k_startmax(const float* __restrict__ x){
    __shared__ float red[256];
    float m = -1e30f;
    for (int i = threadIdx.x; i < Tq; i += 256) m = fmaxf(m, x[i*4 + 2]);
    red[threadIdx.x] = m; __syncthreads();
    for (int s = 128; s > 0; s >>= 1){
        if (threadIdx.x < s) red[threadIdx.x] = fmaxf(red[threadIdx.x], red[threadIdx.x + s]);
        __syncthreads();
    }
    if (threadIdx.x == 0) g_startmax = red[0];
}

// ---------------- embedding: normalize + fc (K=4) -> bf16 ----------------
__global__ void k_embed(const float* __restrict__ x, const float* __restrict__ fcw,
                        const float* __restrict__ fcb){
    int t = blockIdx.x, c = threadIdx.x;      // grid Tq, block DMv
    float x0 = x[t*4+0], x1 = x[t*4+1], x2 = x[t*4+2], x3 = x[t*4+3];
    float n0 = x0 * (1.0f/255.0f), n1 = x1 * (1.0f/255.0f), n2 = x2 / g_startmax, n3 = x3;
    const float* w = fcw + c*4;
    float v = fcb[c] + n0*w[0] + n1*w[1] + n2*w[2] + n3*w[3];
    g_bufAbf[(size_t)t*DMv + c] = __float2bfloat16(v);
}

// ---------------- epilogue activation (fast; outputs land in bf16) ----------------
// ACT: 0 none, 1 tanh, 2 softplus, 3 elu, 4 silu-on-z-half (col >= DIv)
template<int ACT> __device__ __forceinline__ float actf(float v, int col){
    if (ACT == 1) {                       // tanh = 1 - 2/(e^{2v}+1)
        float e = __expf(2.f * v);
        return 1.f - __fdividef(2.f, e + 1.f);
    }
    if (ACT == 2) {                       // softplus
        return (v > 20.f) ? v : __logf(1.f + __expf(v));
    }
    if (ACT == 3) {                       // elu
        return (v > 0.f) ? v : (__expf(v) - 1.f);
    }
    if (ACT == 4) {                       // silu on z half only
        if (col >= DIv) return v * __fdividef(1.f, 1.f + __expf(-v));
        return v;
    }
    return v;
}

// ---------------- bf16 mma.sync GEMM, ldmatrix + 3-stage cp.async ----------------
// C = act(A[M,K](bf16) @ W[N,K](bf16)^T (+bias)); outputs f32 Cf and/or bf16 Cb.
// CTA tile 128x64, BK=32, 256 threads (8 warps, 4m x 2n, warp tile 32x32).
// Mainloop unrolled by 3 so buffer indices are compile-time constants.
#define SBK 40
#define BN  64

template<int ACT>
__global__ void __launch_bounds__(256, 3) k_bgemm(
    const bf16* __restrict__ A, int lda,
    const bf16* __restrict__ W, int ldw,
    const float* __restrict__ bias,
    float* __restrict__ Cf, int ldc,
    bf16* __restrict__ Cb, int ldcb,
    int M, int N, int K)
{
    __shared__ __align__(16) uint16_t As[3][128][SBK];
    __shared__ __align__(16) uint16_t Bs[3][BN][SBK];
    const u32 BUFA = 128*SBK*2, BUFB = BN*SBK*2;

    int tid  = threadIdx.x;
    int lane = tid & 31, w = tid >> 5;
    int wm = (w & 3) * 32;
    int wn = (w >> 2) * 32;
    int g = lane >> 2, ti = lane & 3;
    int bm0 = blockIdx.y * 128, bn0 = blockIdx.x * BN;

    // ldmatrix per-lane base addresses (buf 0, ks 0)
    int lr  = lane & 7;
    int lb1 = (lane >> 3) & 1;
    int lb2 = (lane >> 4) & 1;
    u32 aoff[2];
    #pragma unroll
    for (int mf = 0; mf < 2; mf++)
        aoff[mf] = sptr(&As[0][wm + mf*16 + lr + 8*lb1][8*lb2]);
    u32 boff[2];
    #pragma unroll
    for (int nf2 = 0; nf2 < 2; nf2++)
        boff[nf2] = sptr(&Bs[0][wn + nf2*16 + lr + 8*lb2][8*lb1]);

    float acc[2][4][4];
    #pragma unroll
    for (int i = 0; i < 2; i++)
        #pragma unroll
        for (int j = 0; j < 4; j++)
            #pragma unroll
            for (int r = 0; r < 4; r++) acc[i][j][r] = 0.f;

    int nit = (K + 31) / 32;

    // staging: A row per 2 threads (2 chunks each); B row per 4 threads (1 chunk)
    int srow = tid >> 1, scc = (tid & 1) * 2;
    int brn  = tid >> 2, bcc = tid & 3;
    const bf16* arow = A + (size_t)(bm0 + srow) * lda;
    int gn = bn0 + brn;
    int bvalid = (gn < N);
    const bf16* brow = bvalid ? (W + (size_t)gn * ldw) : W;

    u32 adst0 = sptr(&As[0][srow][0]) + scc*16;
    u32 bdst0 = sptr(&Bs[0][brn][0]) + bcc*16;

    auto stage = [&](int it, int buf){
        int k0 = it * 32;
        int kb = (k0 < K) ? k0 : 0;
        int remB = (K - k0) * 2;
        u32 adst = adst0 + buf*BUFA;
        #pragma unroll
        for (int c = 0; c < 2; c++) {
            int sv = remB - (scc + c)*16; sv = sv < 0 ? 0 : (sv > 16 ? 16 : sv);
            cpa16(adst + c*16, arow + kb + (scc + c)*8, sv);
        }
        {
            int sv = remB - bcc*16; sv = sv < 0 ? 0 : (sv > 16 ? 16 : sv);
            cpa16(bdst0 + buf*BUFB, brow + kb + bcc*8, bvalid ? sv : 0);
        }
        CP_COMMIT();
    };

    stage(0, 0);
    stage(1, 1);

    for (int itb = 0; itb < nit; itb += 3) {
        #pragma unroll
        for (int u = 0; u < 3; u++) {           // buf == u (itb multiple of 3)
            int it = itb + u;
            if (it >= nit) break;
            CP_WAIT1();
            __syncthreads();
            if (it + 2 < nit) stage(it + 2, (u + 2) % 3);
            else CP_COMMIT();

            u32 bufA = u * BUFA, bufB = u * BUFB;
            #pragma unroll
            for (int ks = 0; ks < 2; ks++) {
                u32 kadd = ks * 32;
                u32 afr[2][4];
                #pragma unroll
                for (int mf = 0; mf < 2; mf++)
                    ldsm4(afr[mf][0], afr[mf][1], afr[mf][2], afr[mf][3],
                          aoff[mf] + bufA + kadd);
                u32 bfr[4][2];
                #pragma unroll
                for (int nf2 = 0; nf2 < 2; nf2++)
                    ldsm4(bfr[2*nf2][0], bfr[2*nf2][1], bfr[2*nf2+1][0], bfr[2*nf2+1][1],
                          boff[nf2] + bufB + kadd);
                #pragma unroll
                for (int mf = 0; mf < 2; mf++)
                    #pragma unroll
                    for (int nf = 0; nf < 4; nf++)
                        mma16(acc[mf][nf], afr[mf], bfr[nf]);
            }
        }
    }

    // ---- epilogue: bias + act + dual store ----
    #pragma unroll
    for (int mf = 0; mf < 2; mf++) {
        int mrow0 = bm0 + wm + mf*16 + g;       // and +8
        #pragma unroll
        for (int nf = 0; nf < 4; nf++) {
            int col = bn0 + wn + nf*8 + 2*ti;
            float b0 = 0.f, b1 = 0.f;
            if (bias) {
                if (col   < N) b0 = bias[col];
                if (col+1 < N) b1 = bias[col+1];
            }
            #pragma unroll
            for (int h = 0; h < 2; h++) {
                int m = mrow0 + h*8;
                float v0 = actf<ACT>(acc[mf][nf][2*h+0] + b0, col);
                float v1 = actf<ACT>(acc[mf][nf][2*h+1] + b1, col+1);
                if (Cf) {
                    float* crow = Cf + (size_t)m * ldc;
                    if (col + 1 < N)      *(float2*)(crow + col) = make_float2(v0, v1);
                    else if (col < N)     crow[col] = v0;
                }
                if (Cb) {
                    bf16* brow2 = Cb + (size_t)m * ldcb;
                    if (col + 1 < N)      *(__nv_bfloat162*)(brow2 + col) = __floats2bfloat162_rn(v0, v1);
                    else if (col < N)     brow2[col] = __float2bfloat16(v0);
                }
            }
        }
    }
}

// ---------------- depthwise causal conv (k=8) + bias + silu ----------------
__global__ void k_conv(const float* __restrict__ cw, const float* __restrict__ cb){
    int ch = blockIdx.y * 256 + threadIdx.x;
    int t0 = blockIdx.x * 16;
    int l0 = t0 & (Lq - 1);
    int tb = t0 - l0;

    float w[8];
    #pragma unroll
    for (int j = 0; j < 8; j++) w[j] = cw[ch*8 + j];
    float bv = cb[ch];

    float v[23];
    #pragma unroll
    for (int j = 0; j < 23; j++) {
        int l = l0 - 7 + j;
        v[j] = (l >= 0) ? __bfloat162float(g_xzbf[(size_t)(tb + l) * (2*DIv) + ch]) : 0.f;
    }
    #pragma unroll
    for (int o = 0; o < 16; o++) {
        float s = bv;
        #pragma unroll
        for (int j = 0; j < 8; j++) s = fmaf(v[o + j], w[j], s);
        float sil = s * __fdividef(1.f, 1.f + __expf(-s));
        g_xconvbf[(size_t)(t0 + o) * DIv + ch] = __float2bfloat16(sil);
    }
}

// ---------------- selective scan (serial over L, 3-stage smem windows, 64 thr) ----------------
#define SW 8
#define SCH 64
__global__ void __launch_bounds__(SCH) k_scan(const float* __restrict__ Alog,
                                              const float* __restrict__ Dw){
    int b   = blockIdx.y;
    int ch0 = blockIdx.x * SCH;
    int tid = threadIdx.x;
    int ch  = ch0 + tid;

    __shared__ __align__(16) uint16_t sDh[3][SW][SCH];
    __shared__ __align__(16) uint16_t sXh[3][SW][SCH];
    __shared__ __align__(16) uint16_t sZh[3][SW][SCH];
    __shared__ __align__(16) float sBC[3][SW][32];

    float a[NST];
    bool fast = true;
    #pragma unroll
    for (int n = 0; n < NST; n++) {
        a[n] = -expf(Alog[ch*NST + n]);
        fast = fast && (fabsf(a[n] + (float)(n+1)) < 1e-4f * (float)(n+1));
    }
    float Dd = Dw[ch];

    float h[NST];
    #pragma unroll
    for (int n = 0; n < NST; n++) h[n] = 0.f;

    const size_t tb0 = (size_t)b * Lq;

    auto stage = [&](int wnd){
        int buf = wnd % 3;
        int t0 = wnd * SW;
        // delta/x/z (bf16): SW x 64 = 64 chunks each, 1/thread
        {
            int s = tid >> 3, cc = (tid & 7) * 8;
            cpa16(sptr(&sDh[buf][s][cc]), &g_deltabf[(tb0 + t0 + s)*DIv + cc + ch0], 16);
            cpa16(sptr(&sXh[buf][s][cc]), &g_xconvbf[(tb0 + t0 + s)*DIv + cc + ch0], 16);
            cpa16(sptr(&sZh[buf][s][cc]),
                  &g_xzbf[(tb0 + t0 + s)*(2*DIv) + DIv + cc + ch0], 16);
        }
        // BC (f32): SW x 32 floats = 64 chunks, 1/thread
        {
            int s = tid >> 3, cc = (tid & 7) * 4;
            cpa16(sptr(&sBC[buf][s][cc]),
                  &g_dbc[(tb0 + t0 + s)*XDv + DTRANK + cc], 16);
        }
        CP_COMMIT();
    };

    stage(0);
    stage(1);

    for (int wnd = 0; wnd < Lq/SW; wnd++) {
        int buf = wnd % 3;
        CP_WAIT1();
        __syncthreads();
        if (wnd + 2 < Lq/SW) stage(wnd + 2);
        else CP_COMMIT();

        #pragma unroll
        for (int s = 0; s < SW; s++) {
            float delta, xv, zv;
            {
                __nv_bfloat16 db, xb, zb;
                *(uint16_t*)&db = sDh[buf][s][tid];
                *(uint16_t*)&xb = sXh[buf][s][tid];
                *(uint16_t*)&zb = sZh[buf][s][tid];
                delta = __bfloat162float(db);
                xv = __bfloat162float(xb);
                zv = __bfloat162float(zb);        // already silu(z)
            }
            const float4* bcq = (const float4*)&sBC[buf][s][0];
            float4 q0 = bcq[0], q1 = bcq[1], q2 = bcq[2], q3 = bcq[3];
            float4 q4 = bcq[4], q5 = bcq[5], q6 = bcq[6], q7 = bcq[7];
            float Bv[NST] = {q0.x,q0.y,q0.z,q0.w, q1.x,q1.y,q1.z,q1.w,
                             q2.x,q2.y,q2.z,q2.w, q3.x,q3.y,q3.z,q3.w};
            float Cv[NST] = {q4.x,q4.y,q4.z,q4.w, q5.x,q5.y,q5.z,q5.w,
                             q6.x,q6.y,q6.z,q6.w, q7.x,q7.y,q7.z,q7.w};

            float dx = delta * xv;
            float y0 = 0.f, y1 = 0.f;
            if (fast) {
                float p  = __expf(-delta);
                float p2 = p*p, p4 = p2*p2, p8 = p4*p4;
                float p3 = p2*p, p5 = p4*p, p6 = p4*p2, p7 = p4*p3;
                float pw[NST] = {p, p2, p3, p4, p5, p6, p7, p8,
                                 p8*p, p8*p2, p8*p3, p8*p4, p8*p5, p8*p6, p8*p7, p8*p8};
                #pragma unroll
                for (int n = 0; n < NST; n += 2) {
                    h[n]   = fmaf(pw[n],   h[n],   dx * Bv[n]);
                    h[n+1] = fmaf(pw[n+1], h[n+1], dx * Bv[n+1]);
                    y0 = fmaf(h[n],   Cv[n],   y0);
                    y1 = fmaf(h[n+1], Cv[n+1], y1);
                }
            } else {
                #pragma unroll
                for (int n = 0; n < NST; n += 2) {
                    float dA0 = __expf(delta * a[n]);
                    float dA1 = __expf(delta * a[n+1]);
                    h[n]   = fmaf(dA0, h[n],   dx * Bv[n]);
                    h[n+1] = fmaf(dA1, h[n+1], dx * Bv[n+1]);
                    y0 = fmaf(h[n],   Cv[n],   y0);
                    y1 = fmaf(h[n+1], Cv[n+1], y1);
                }
            }
            float yy = fmaf(xv, Dd, y0 + y1);
            g_ybf[(tb0 + wnd*SW + s)*DIv + ch] = __float2bfloat16(yy * zv);
        }
    }
}

// ---------------- head MLP (M=8): 320 -> 512 -> 512 -> 1 ----------------
__global__ void __launch_bounds__(512) k_head(
    const float* __restrict__ w1, const float* __restrict__ b1,
    const float* __restrict__ w2, const float* __restrict__ b2,
    const float* __restrict__ w3, const float* __restrict__ b3,
    float* __restrict__ out)
{
    __shared__ float sh [8][320];
    __shared__ float sh1[8][512];
    __shared__ float sh2[8][512];
    int tid = threadIdx.x;

    for (int idx = tid; idx < 8*320; idx += 512) {
        int bb = idx / 320, c = idx % 320;
        sh[bb][c] = g_bufA[((size_t)bb * Lq + Lq - 1) * DMv + c];
    }
    __syncthreads();

    {
        int n = tid;
        float acc[8];
        #pragma unroll
        for (int bb = 0; bb < 8; bb++) acc[bb] = 0.f;
        const float* wr = w1 + (size_t)n * 320;
        for (int k = 0; k < 320; k++) {
            float wv = wr[k];
            #pragma unroll
            for (int bb = 0; bb < 8; bb++) acc[bb] = fmaf(wv, sh[bb][k], acc[bb]);
        }
        #pragma unroll
        for (int bb = 0; bb < 8; bb++) sh1[bb][n] = fmaxf(acc[bb] + b1[n], 0.f);
    }
    __syncthreads();

    {
        int n = tid;
        float acc[8];
        #pragma unroll
        for (int bb = 0; bb < 8; bb++) acc[bb] = 0.f;
        const float* wr = w2 + (size_t)n * 512;
        for (int k = 0; k < 512; k++) {
            float wv = wr[k];
            #pragma unroll
            for (int bb = 0; bb < 8; bb++) acc[bb] = fmaf(wv, sh1[bb][k], acc[bb]);
        }
        #pragma unroll
        for (int bb = 0; bb < 8; bb++) sh2[bb][n] = fmaxf(acc[bb] + b2[n], 0.f);
    }
    __syncthreads();

    if (tid < 8) {
        float acc = 0.f;
        for (int k = 0; k < 512; k++) acc = fmaf(w3[k], sh2[tid][k], acc);
        acc += b3[0];
        float scale = g_startmax / (1.f + logf((float)Lq));
        out[tid] = fmaxf(acc * scale, 0.f);
    }
}

// ---------------- host launch ----------------
extern "C" void kernel_launch(void* const* d_in, const int* in_sizes, int n_in,
                              void* d_out, int out_size)
{
    const float* x            = (const float*)d_in[0];
    const float* fc_w         = (const float*)d_in[1];
    const float* fc_b         = (const float*)d_in[2];
    const float* blk_lin_w    = (const float*)d_in[3];
    const float* blk_lin_b    = (const float*)d_in[4];
    const float* blk_inproj_w = (const float*)d_in[5];
    const float* blk_conv_w   = (const float*)d_in[6];
    const float* blk_conv_b   = (const float*)d_in[7];
    const float* blk_xproj_w  = (const float*)d_in[8];
    const float* blk_dtproj_w = (const float*)d_in[9];
    const float* blk_dtproj_b = (const float*)d_in[10];
    const float* blk_A_log    = (const float*)d_in[11];
    const float* blk_D        = (const float*)d_in[12];
    const float* blk_outproj_w= (const float*)d_in[13];
    const float* s1_w1        = (const float*)d_in[14];
    const float* s1_b1        = (const float*)d_in[15];
    const float* s1_w2        = (const float*)d_in[16];
    const float* s1_b2        = (const float*)d_in[17];
    const float* s1_w3        = (const float*)d_in[18];
    const float* s1_b3        = (const float*)d_in[19];

    void* p;
    cudaGetSymbolAddress(&p, g_dbc);     float* dbc     = (float*)p;
    cudaGetSymbolAddress(&p, g_bufA);    float* bufA    = (float*)p;
    cudaGetSymbolAddress(&p, g_bufAbf);  bf16* bufAbf   = (bf16*)p;
    cudaGetSymbolAddress(&p, g_ubf);     bf16* ubf      = (bf16*)p;
    cudaGetSymbolAddress(&p, g_xzbf);    bf16* xzbf     = (bf16*)p;
    cudaGetSymbolAddress(&p, g_xconvbf); bf16* xconvbf  = (bf16*)p;
    cudaGetSymbolAddress(&p, g_dbcbf);   bf16* dbcbf    = (bf16*)p;
    cudaGetSymbolAddress(&p, g_deltabf); bf16* deltabf  = (bf16*)p;
    cudaGetSymbolAddress(&p, g_ybf);     bf16* ybf      = (bf16*)p;
    cudaGetSymbolAddress(&p, g_wlin);    bf16* wlin     = (bf16*)p;
    cudaGetSymbolAddress(&p, g_win);     bf16* win      = (bf16*)p;
    cudaGetSymbolAddress(&p, g_wxp);     bf16* wxp      = (bf16*)p;
    cudaGetSymbolAddress(&p, g_wdt);     bf16* wdt      = (bf16*)p;
    cudaGetSymbolAddress(&p, g_wout);    bf16* wout     = (bf16*)p;

    // merged weight conversion (1 launch)
    k_cvtall<<<(NQA + NDT + 255)/256, 256>>>(blk_lin_w, blk_inproj_w, blk_xproj_w,
                                             blk_dtproj_w, blk_outproj_w);
    k_startmax<<<1, 256>>>(x);
    k_embed<<<Tq, DMv>>>(x, fc_w, fc_b);

    for (int i = 0; i < NBLK; i++) {
        // lin: tanh(bufA @ lin_w^T + b) -> u(bf16)   [Tq,320] K=320
        k_bgemm<1><<<dim3(5, Tq/128), 256>>>(
            bufAbf, DMv, wlin + (size_t)i*DMv*DMv, DMv,
            blk_lin_b + (size_t)i*DMv,
            (float*)nullptr, 0, ubf, DMv, Tq, DMv, DMv);

        // inproj: u @ inproj_w^T -> xz(bf16, silu on z half)   [Tq,2560] K=320
        k_bgemm<4><<<dim3(40, Tq/128), 256>>>(
            ubf, DMv, win + (size_t)i*2*DIv*DMv, DMv,
            (const float*)nullptr,
            (float*)nullptr, 0, xzbf, 2*DIv, Tq, 2*DIv, DMv);

        // depthwise causal conv + silu -> xconv(bf16)
        k_conv<<<dim3(Tq/16, DIv/256), 256>>>(
            blk_conv_w + (size_t)i*DIv*DCONVK, blk_conv_b + (size_t)i*DIv);

        // xproj: xconv @ xproj_w^T -> dbc (f32) + dbcbf (bf16)   [Tq,52] K=1280
        k_bgemm<0><<<dim3(1, Tq/128), 256>>>(
            xconvbf, DIv, wxp + (size_t)i*XDv*DIv, DIv,
            (const float*)nullptr,
            dbc, XDv, dbcbf, 56, Tq, XDv, DIv);

        // dtproj: softplus(dbc[:, :20] @ dtproj_w^T + b) -> delta(bf16)   [Tq,1280] K=20
        k_bgemm<2><<<dim3(20, Tq/128), 256>>>(
            dbcbf, 56, wdt + (size_t)i*DIv*24, 24,
            blk_dtproj_b + (size_t)i*DIv,
            (float*)nullptr, 0, deltabf, DIv, Tq, DIv, DTRANK);

        // selective scan -> y(bf16)
        k_scan<<<dim3(DIv/SCH, Bq), SCH>>>(
            blk_A_log + (size_t)i*DIv*NST, blk_D + (size_t)i*DIv);

        // outproj: elu(y @ outproj_w^T) -> bufA (f32 + bf16)   [Tq,320] K=1280
        k_bgemm<3><<<dim3(5, Tq/128), 256>>>(
            ybf, DIv, wout + (size_t)i*DMv*DIv, DIv,
            (const float*)nullptr,
            bufA, DMv, bufAbf, DMv, Tq, DMv, DIv);
    }

    k_head<<<1, 512>>>(s1_w1, s1_b1, s1_w2, s1_b2, s1_w3, s1_b3, (float*)d_out);
}

// round 12
// speedup vs baseline: 6.5755x; 1.1833x over previous
#include <cuda_runtime.h>
#include <cuda_bf16.h>
#include <math.h>
#include <stdint.h>

// ---------------- problem constants ----------------
#define Bq      8
#define Lq      2048
#define Tq      (Bq*Lq)        // 16384 tokens
#define DMv     320
#define DIv     1280
#define NST     16
#define DCONVK  8
#define DTRANK  20
#define XDv     52             // DTRANK + 2*NST
#define NBLK    4
#define NCH     16             // scan chunks
#define CL      (Lq/NCH)       // 128 steps per chunk

typedef uint32_t u32;
typedef __nv_bfloat16 bf16;

// ---------------- static device scratch (no allocations) ----------------
__device__ __align__(256) float g_bufA [Tq*DMv];          // fp32 (head input)
__device__ __align__(256) float g_dbc  [Tq*XDv];
__device__ __align__(256) float g_hc   [(size_t)Bq*NCH*NST*DIv];  // chunk-final local states
__device__ __align__(256) float g_h0   [(size_t)Bq*NCH*NST*DIv];  // chunk initial states
__device__ __align__(256) float g_sumd [Bq*NCH*DIv];              // chunk delta sums
__device__ float g_startmax;

// bf16 activations
__device__ __align__(256) bf16 g_bufAbf [Tq*DMv];
__device__ __align__(256) bf16 g_ubf    [Tq*DMv];
__device__ __align__(256) bf16 g_xzbf   [(size_t)Tq*2*DIv];  // inproj out (x | silu(z))
__device__ __align__(256) bf16 g_xconvbf[(size_t)Tq*DIv];
__device__ __align__(256) bf16 g_dbcbf  [Tq*56];             // stride 56
__device__ __align__(256) bf16 g_deltabf[(size_t)Tq*DIv];
__device__ __align__(256) bf16 g_ybf    [(size_t)Tq*DIv];

// bf16 weights (converted once per launch)
__device__ __align__(256) bf16 g_wlin[NBLK*320*320];
__device__ __align__(256) bf16 g_win [NBLK*2560*320];
__device__ __align__(256) bf16 g_wxp [NBLK*52*1280];
__device__ __align__(256) bf16 g_wdt [NBLK*1280*24];         // stride 24 (K=20 padded)
__device__ __align__(256) bf16 g_wout[NBLK*320*1280];

// ---------------- helpers ----------------
__device__ __forceinline__ u32 sptr(const void* p){
    return (u32)__cvta_generic_to_shared(p);
}
__device__ __forceinline__ void cpa16(u32 dst, const void* src, int sz){
    asm volatile("cp.async.ca.shared.global [%0], [%1], 16, %2;"
                 :: "r"(dst), "l"(src), "r"(sz) : "memory");
}
#define CP_COMMIT() asm volatile("cp.async.commit_group;" ::: "memory")
#define CP_WAIT1()  asm volatile("cp.async.wait_group 1;" ::: "memory")

__device__ __forceinline__ void mma16(float* c, const u32* a, const u32* b){
    asm volatile("mma.sync.aligned.m16n8k16.row.col.f32.bf16.bf16.f32 "
        "{%0,%1,%2,%3}, {%4,%5,%6,%7}, {%8,%9}, {%0,%1,%2,%3};"
        : "+f"(c[0]), "+f"(c[1]), "+f"(c[2]), "+f"(c[3])
        : "r"(a[0]), "r"(a[1]), "r"(a[2]), "r"(a[3]), "r"(b[0]), "r"(b[1]));
}
__device__ __forceinline__ void ldsm4(u32& r0, u32& r1, u32& r2, u32& r3, u32 addr){
    asm volatile("ldmatrix.sync.aligned.m8n8.x4.shared.b16 {%0,%1,%2,%3}, [%4];"
        : "=r"(r0), "=r"(r1), "=r"(r2), "=r"(r3) : "r"(addr));
}

// ---------------- merged weight conversion ----------------
#define NQ1 (NBLK*320*320/4)      // wlin quads
#define NQ2 (NBLK*2560*320/4)     // win
#define NQ3 (NBLK*52*1280/4)      // wxp
#define NQ5 (NBLK*320*1280/4)     // wout
#define NQA (NQ1+NQ2+NQ3+NQ5)
#define NDT (NBLK*1280*24)        // wdt padded elems
__global__ void k_cvtall(const float* __restrict__ lw, const float* __restrict__ iw,
                         const float* __restrict__ xw, const float* __restrict__ dw,
                         const float* __restrict__ ow){
    int i = blockIdx.x * 256 + threadIdx.x;
    if (i < NQA) {
        const float* s; bf16* d; int q = i;
        if (q < NQ1)                { s = lw; d = g_wlin; }
        else if ((q -= NQ1) < NQ2)  { s = iw; d = g_win;  }
        else if ((q -= NQ2) < NQ3)  { s = xw; d = g_wxp;  }
        else                        { q -= NQ3; s = ow; d = g_wout; }
        float4 v = *(const float4*)(s + q*4);
        d[q*4+0] = __float2bfloat16(v.x);
        d[q*4+1] = __float2bfloat16(v.y);
        d[q*4+2] = __float2bfloat16(v.z);
        d[q*4+3] = __float2bfloat16(v.w);
    } else if (i < NQA + NDT) {
        int idx = i - NQA;
        int r = idx / 24, c = idx % 24;
        g_wdt[idx] = (c < 20) ? __float2bfloat16(dw[r*20 + c]) : __float2bfloat16(0.f);
    }
}

// ---------------- start_max reduction ----------------
__global__ void k_startmax(const float* __restrict__ x){
    __shared__ float red[256];
    float m = -1e30f;
    for (int i = threadIdx.x; i < Tq; i += 256) m = fmaxf(m, x[i*4 + 2]);
    red[threadIdx.x] = m; __syncthreads();
    for (int s = 128; s > 0; s >>= 1){
        if (threadIdx.x < s) red[threadIdx.x] = fmaxf(red[threadIdx.x], red[threadIdx.x + s]);
        __syncthreads();
    }
    if (threadIdx.x == 0) g_startmax = red[0];
}

// ---------------- embedding: normalize + fc (K=4) -> bf16 ----------------
__global__ void k_embed(const float* __restrict__ x, const float* __restrict__ fcw,
                        const float* __restrict__ fcb){
    int t = blockIdx.x, c = threadIdx.x;      // grid Tq, block DMv
    float x0 = x[t*4+0], x1 = x[t*4+1], x2 = x[t*4+2], x3 = x[t*4+3];
    float n0 = x0 * (1.0f/255.0f), n1 = x1 * (1.0f/255.0f), n2 = x2 / g_startmax, n3 = x3;
    const float* w = fcw + c*4;
    float v = fcb[c] + n0*w[0] + n1*w[1] + n2*w[2] + n3*w[3];
    g_bufAbf[(size_t)t*DMv + c] = __float2bfloat16(v);
}

// ---------------- epilogue activation (fast; outputs land in bf16) ----------------
// ACT: 0 none, 1 tanh, 2 softplus, 3 elu, 4 silu-on-z-half (col >= DIv)
template<int ACT> __device__ __forceinline__ float actf(float v, int col){
    if (ACT == 1) {                       // tanh = 1 - 2/(e^{2v}+1)
        float e = __expf(2.f * v);
        return 1.f - __fdividef(2.f, e + 1.f);
    }
    if (ACT == 2) {                       // softplus
        return (v > 20.f) ? v : __logf(1.f + __expf(v));
    }
    if (ACT == 3) {                       // elu
        return (v > 0.f) ? v : (__expf(v) - 1.f);
    }
    if (ACT == 4) {                       // silu on z half only
        if (col >= DIv) return v * __fdividef(1.f, 1.f + __expf(-v));
        return v;
    }
    return v;
}

// ---------------- bf16 mma.sync GEMM, ldmatrix + 3-stage cp.async ----------------
#define SBK 40
#define BN  64

template<int ACT>
__global__ void __launch_bounds__(256, 3) k_bgemm(
    const bf16* __restrict__ A, int lda,
    const bf16* __restrict__ W, int ldw,
    const float* __restrict__ bias,
    float* __restrict__ Cf, int ldc,
    bf16* __restrict__ Cb, int ldcb,
    int M, int N, int K)
{
    __shared__ __align__(16) uint16_t As[3][128][SBK];
    __shared__ __align__(16) uint16_t Bs[3][BN][SBK];
    const u32 BUFA = 128*SBK*2, BUFB = BN*SBK*2;

    int tid  = threadIdx.x;
    int lane = tid & 31, w = tid >> 5;
    int wm = (w & 3) * 32;
    int wn = (w >> 2) * 32;
    int g = lane >> 2, ti = lane & 3;
    int bm0 = blockIdx.y * 128, bn0 = blockIdx.x * BN;

    int lr  = lane & 7;
    int lb1 = (lane >> 3) & 1;
    int lb2 = (lane >> 4) & 1;
    u32 aoff[2];
    #pragma unroll
    for (int mf = 0; mf < 2; mf++)
        aoff[mf] = sptr(&As[0][wm + mf*16 + lr + 8*lb1][8*lb2]);
    u32 boff[2];
    #pragma unroll
    for (int nf2 = 0; nf2 < 2; nf2++)
        boff[nf2] = sptr(&Bs[0][wn + nf2*16 + lr + 8*lb2][8*lb1]);

    float acc[2][4][4];
    #pragma unroll
    for (int i = 0; i < 2; i++)
        #pragma unroll
        for (int j = 0; j < 4; j++)
            #pragma unroll
            for (int r = 0; r < 4; r++) acc[i][j][r] = 0.f;

    int nit = (K + 31) / 32;

    int srow = tid >> 1, scc = (tid & 1) * 2;
    int brn  = tid >> 2, bcc = tid & 3;
    const bf16* arow = A + (size_t)(bm0 + srow) * lda;
    int gn = bn0 + brn;
    int bvalid = (gn < N);
    const bf16* brow = bvalid ? (W + (size_t)gn * ldw) : W;

    u32 adst0 = sptr(&As[0][srow][0]) + scc*16;
    u32 bdst0 = sptr(&Bs[0][brn][0]) + bcc*16;

    auto stage = [&](int it, int buf){
        int k0 = it * 32;
        int kb = (k0 < K) ? k0 : 0;
        int remB = (K - k0) * 2;
        u32 adst = adst0 + buf*BUFA;
        #pragma unroll
        for (int c = 0; c < 2; c++) {
            int sv = remB - (scc + c)*16; sv = sv < 0 ? 0 : (sv > 16 ? 16 : sv);
            cpa16(adst + c*16, arow + kb + (scc + c)*8, sv);
        }
        {
            int sv = remB - bcc*16; sv = sv < 0 ? 0 : (sv > 16 ? 16 : sv);
            cpa16(bdst0 + buf*BUFB, brow + kb + bcc*8, bvalid ? sv : 0);
        }
        CP_COMMIT();
    };

    stage(0, 0);
    stage(1, 1);

    for (int itb = 0; itb < nit; itb += 3) {
        #pragma unroll
        for (int u = 0; u < 3; u++) {           // buf == u (itb multiple of 3)
            int it = itb + u;
            if (it >= nit) break;
            CP_WAIT1();
            __syncthreads();
            if (it + 2 < nit) stage(it + 2, (u + 2) % 3);
            else CP_COMMIT();

            u32 bufA = u * BUFA, bufB = u * BUFB;
            #pragma unroll
            for (int ks = 0; ks < 2; ks++) {
                u32 kadd = ks * 32;
                u32 afr[2][4];
                #pragma unroll
                for (int mf = 0; mf < 2; mf++)
                    ldsm4(afr[mf][0], afr[mf][1], afr[mf][2], afr[mf][3],
                          aoff[mf] + bufA + kadd);
                u32 bfr[4][2];
                #pragma unroll
                for (int nf2 = 0; nf2 < 2; nf2++)
                    ldsm4(bfr[2*nf2][0], bfr[2*nf2][1], bfr[2*nf2+1][0], bfr[2*nf2+1][1],
                          boff[nf2] + bufB + kadd);
                #pragma unroll
                for (int mf = 0; mf < 2; mf++)
                    #pragma unroll
                    for (int nf = 0; nf < 4; nf++)
                        mma16(acc[mf][nf], afr[mf], bfr[nf]);
            }
        }
    }

    // ---- epilogue: bias + act + dual store ----
    #pragma unroll
    for (int mf = 0; mf < 2; mf++) {
        int mrow0 = bm0 + wm + mf*16 + g;
        #pragma unroll
        for (int nf = 0; nf < 4; nf++) {
            int col = bn0 + wn + nf*8 + 2*ti;
            float b0 = 0.f, b1 = 0.f;
            if (bias) {
                if (col   < N) b0 = bias[col];
                if (col+1 < N) b1 = bias[col+1];
            }
            #pragma unroll
            for (int h = 0; h < 2; h++) {
                int m = mrow0 + h*8;
                float v0 = actf<ACT>(acc[mf][nf][2*h+0] + b0, col);
                float v1 = actf<ACT>(acc[mf][nf][2*h+1] + b1, col+1);
                if (Cf) {
                    float* crow = Cf + (size_t)m * ldc;
                    if (col + 1 < N)      *(float2*)(crow + col) = make_float2(v0, v1);
                    else if (col < N)     crow[col] = v0;
                }
                if (Cb) {
                    bf16* brow2 = Cb + (size_t)m * ldcb;
                    if (col + 1 < N)      *(__nv_bfloat162*)(brow2 + col) = __floats2bfloat162_rn(v0, v1);
                    else if (col < N)     brow2[col] = __float2bfloat16(v0);
                }
            }
        }
    }
}

// ---------------- depthwise causal conv (k=8) + bias + silu ----------------
__global__ void k_conv(const float* __restrict__ cw, const float* __restrict__ cb){
    int ch = blockIdx.y * 256 + threadIdx.x;
    int t0 = blockIdx.x * 16;
    int l0 = t0 & (Lq - 1);
    int tb = t0 - l0;

    float w[8];
    #pragma unroll
    for (int j = 0; j < 8; j++) w[j] = cw[ch*8 + j];
    float bv = cb[ch];

    float v[23];
    #pragma unroll
    for (int j = 0; j < 23; j++) {
        int l = l0 - 7 + j;
        v[j] = (l >= 0) ? __bfloat162float(g_xzbf[(size_t)(tb + l) * (2*DIv) + ch]) : 0.f;
    }
    #pragma unroll
    for (int o = 0; o < 16; o++) {
        float s = bv;
        #pragma unroll
        for (int j = 0; j < 8; j++) s = fmaf(v[o + j], w[j], s);
        float sil = s * __fdividef(1.f, 1.f + __expf(-s));
        g_xconvbf[(size_t)(t0 + o) * DIv + ch] = __float2bfloat16(sil);
    }
}

// ---------------- chunked selective scan ----------------
// Pass A: zero-seeded local recurrence per chunk; outputs chunk-final states + sum(delta).
// Pass B: serial chain over chunks (trivial).
// Pass C: exact scan per chunk seeded with h0 (same math as the serial scan).
#define SW 8
#define SCH 64

// ---- Pass A: grid (DIv/SCH, Bq*NCH), block SCH ----
__global__ void __launch_bounds__(SCH) k_scanA(const float* __restrict__ Alog){
    int b   = blockIdx.y / NCH;
    int c   = blockIdx.y % NCH;
    int ch0 = blockIdx.x * SCH;
    int tid = threadIdx.x;
    int ch  = ch0 + tid;

    __shared__ __align__(16) uint16_t sDh[3][SW][SCH];
    __shared__ __align__(16) uint16_t sXh[3][SW][SCH];
    __shared__ __align__(16) float sB[3][SW][16];

    float a[NST];
    bool fast = true;
    #pragma unroll
    for (int n = 0; n < NST; n++) {
        a[n] = -expf(Alog[ch*NST + n]);
        fast = fast && (fabsf(a[n] + (float)(n+1)) < 1e-4f * (float)(n+1));
    }

    float h[NST];
    #pragma unroll
    for (int n = 0; n < NST; n++) h[n] = 0.f;
    float cum = 0.f;

    const size_t tc0 = (size_t)b * Lq + (size_t)c * CL;

    auto stage = [&](int wnd){
        int buf = wnd % 3;
        int t0 = wnd * SW;
        {
            int s = tid >> 3, cc = (tid & 7) * 8;
            cpa16(sptr(&sDh[buf][s][cc]), &g_deltabf[(tc0 + t0 + s)*DIv + cc + ch0], 16);
            cpa16(sptr(&sXh[buf][s][cc]), &g_xconvbf[(tc0 + t0 + s)*DIv + cc + ch0], 16);
        }
        if (tid < SW*4) {
            int s = tid >> 2, cc = (tid & 3) * 4;
            cpa16(sptr(&sB[buf][s][cc]),
                  &g_dbc[(tc0 + t0 + s)*XDv + DTRANK + cc], 16);
        }
        CP_COMMIT();
    };

    stage(0);
    stage(1);

    for (int wnd = 0; wnd < CL/SW; wnd++) {
        int buf = wnd % 3;
        CP_WAIT1();
        __syncthreads();
        if (wnd + 2 < CL/SW) stage(wnd + 2);
        else CP_COMMIT();

        #pragma unroll
        for (int s = 0; s < SW; s++) {
            float delta, xv;
            {
                __nv_bfloat16 db, xb;
                *(uint16_t*)&db = sDh[buf][s][tid];
                *(uint16_t*)&xb = sXh[buf][s][tid];
                delta = __bfloat162float(db);
                xv = __bfloat162float(xb);
            }
            const float4* bq = (const float4*)&sB[buf][s][0];
            float4 q0 = bq[0], q1 = bq[1], q2 = bq[2], q3 = bq[3];
            float Bv[NST] = {q0.x,q0.y,q0.z,q0.w, q1.x,q1.y,q1.z,q1.w,
                             q2.x,q2.y,q2.z,q2.w, q3.x,q3.y,q3.z,q3.w};
            float dx = delta * xv;
            cum += delta;
            if (fast) {
                float p  = __expf(-delta);
                float p2 = p*p, p4 = p2*p2, p8 = p4*p4;
                float p3 = p2*p, p5 = p4*p, p6 = p4*p2, p7 = p4*p3;
                float pw[NST] = {p, p2, p3, p4, p5, p6, p7, p8,
                                 p8*p, p8*p2, p8*p3, p8*p4, p8*p5, p8*p6, p8*p7, p8*p8};
                #pragma unroll
                for (int n = 0; n < NST; n++)
                    h[n] = fmaf(pw[n], h[n], dx * Bv[n]);
            } else {
                #pragma unroll
                for (int n = 0; n < NST; n++)
                    h[n] = fmaf(__expf(delta * a[n]), h[n], dx * Bv[n]);
            }
        }
    }

    // store chunk-final states + sum(delta)
    size_t base = ((size_t)(b*NCH + c) * NST) * DIv + ch;
    #pragma unroll
    for (int n = 0; n < NST; n++)
        g_hc[base + (size_t)n * DIv] = h[n];
    g_sumd[(b*NCH + c)*DIv + ch] = cum;
}

// ---- Pass B: chain. 1 thread per (b, n, ch). ----
__global__ void k_scanB(const float* __restrict__ Alog){
    int id = blockIdx.x * 256 + threadIdx.x;      // (b*NST + n)*DIv + ch
    if (id >= Bq*NST*DIv) return;
    int ch = id % DIv;
    int r  = id / DIv;
    int n  = r % NST;
    int b  = r / NST;
    float an = -expf(Alog[ch*NST + n]);
    float h0 = 0.f;
    for (int c = 0; c < NCH; c++) {
        size_t idx = ((size_t)(b*NCH + c) * NST + n) * DIv + ch;
        g_h0[idx] = h0;
        h0 = g_hc[idx] + __expf(an * g_sumd[(b*NCH + c)*DIv + ch]) * h0;
    }
}

// ---- Pass C: exact scan per chunk seeded with h0 ----
__global__ void __launch_bounds__(SCH) k_scanC(const float* __restrict__ Alog,
                                               const float* __restrict__ Dw){
    int b   = blockIdx.y / NCH;
    int c   = blockIdx.y % NCH;
    int ch0 = blockIdx.x * SCH;
    int tid = threadIdx.x;
    int ch  = ch0 + tid;

    __shared__ __align__(16) uint16_t sDh[3][SW][SCH];
    __shared__ __align__(16) uint16_t sXh[3][SW][SCH];
    __shared__ __align__(16) uint16_t sZh[3][SW][SCH];
    __shared__ __align__(16) float sBC[3][SW][32];

    float a[NST];
    bool fast = true;
    #pragma unroll
    for (int n = 0; n < NST; n++) {
        a[n] = -expf(Alog[ch*NST + n]);
        fast = fast && (fabsf(a[n] + (float)(n+1)) < 1e-4f * (float)(n+1));
    }
    float Dd = Dw[ch];

    float h[NST];
    {
        size_t base = ((size_t)(b*NCH + c) * NST) * DIv + ch;
        #pragma unroll
        for (int n = 0; n < NST; n++)
            h[n] = g_h0[base + (size_t)n * DIv];
    }

    const size_t tc0 = (size_t)b * Lq + (size_t)c * CL;

    auto stage = [&](int wnd){
        int buf = wnd % 3;
        int t0 = wnd * SW;
        {
            int s = tid >> 3, cc = (tid & 7) * 8;
            cpa16(sptr(&sDh[buf][s][cc]), &g_deltabf[(tc0 + t0 + s)*DIv + cc + ch0], 16);
            cpa16(sptr(&sXh[buf][s][cc]), &g_xconvbf[(tc0 + t0 + s)*DIv + cc + ch0], 16);
            cpa16(sptr(&sZh[buf][s][cc]),
                  &g_xzbf[(tc0 + t0 + s)*(2*DIv) + DIv + cc + ch0], 16);
        }
        {
            int s = tid >> 3, cc = (tid & 7) * 4;
            cpa16(sptr(&sBC[buf][s][cc]),
                  &g_dbc[(tc0 + t0 + s)*XDv + DTRANK + cc], 16);
        }
        CP_COMMIT();
    };

    stage(0);
    stage(1);

    for (int wnd = 0; wnd < CL/SW; wnd++) {
        int buf = wnd % 3;
        CP_WAIT1();
        __syncthreads();
        if (wnd + 2 < CL/SW) stage(wnd + 2);
        else CP_COMMIT();

        #pragma unroll
        for (int s = 0; s < SW; s++) {
            float delta, xv, zv;
            {
                __nv_bfloat16 db, xb, zb;
                *(uint16_t*)&db = sDh[buf][s][tid];
                *(uint16_t*)&xb = sXh[buf][s][tid];
                *(uint16_t*)&zb = sZh[buf][s][tid];
                delta = __bfloat162float(db);
                xv = __bfloat162float(xb);
                zv = __bfloat162float(zb);        // already silu(z)
            }
            const float4* bcq = (const float4*)&sBC[buf][s][0];
            float4 q0 = bcq[0], q1 = bcq[1], q2 = bcq[2], q3 = bcq[3];
            float4 q4 = bcq[4], q5 = bcq[5], q6 = bcq[6], q7 = bcq[7];
            float Bv[NST] = {q0.x,q0.y,q0.z,q0.w, q1.x,q1.y,q1.z,q1.w,
                             q2.x,q2.y,q2.z,q2.w, q3.x,q3.y,q3.z,q3.w};
            float Cv[NST] = {q4.x,q4.y,q4.z,q4.w, q5.x,q5.y,q5.z,q5.w,
                             q6.x,q6.y,q6.z,q6.w, q7.x,q7.y,q7.z,q7.w};

            float dx = delta * xv;
            float y0 = 0.f, y1 = 0.f;
            if (fast) {
                float p  = __expf(-delta);
                float p2 = p*p, p4 = p2*p2, p8 = p4*p4;
                float p3 = p2*p, p5 = p4*p, p6 = p4*p2, p7 = p4*p3;
                float pw[NST] = {p, p2, p3, p4, p5, p6, p7, p8,
                                 p8*p, p8*p2, p8*p3, p8*p4, p8*p5, p8*p6, p8*p7, p8*p8};
                #pragma unroll
                for (int n = 0; n < NST; n += 2) {
                    h[n]   = fmaf(pw[n],   h[n],   dx * Bv[n]);
                    h[n+1] = fmaf(pw[n+1], h[n+1], dx * Bv[n+1]);
                    y0 = fmaf(h[n],   Cv[n],   y0);
                    y1 = fmaf(h[n+1], Cv[n+1], y1);
                }
            } else {
                #pragma unroll
                for (int n = 0; n < NST; n += 2) {
                    float dA0 = __expf(delta * a[n]);
                    float dA1 = __expf(delta * a[n+1]);
                    h[n]   = fmaf(dA0, h[n],   dx * Bv[n]);
                    h[n+1] = fmaf(dA1, h[n+1], dx * Bv[n+1]);
                    y0 = fmaf(h[n],   Cv[n],   y0);
                    y1 = fmaf(h[n+1], Cv[n+1], y1);
                }
            }
            float yy = fmaf(xv, Dd, y0 + y1);
            g_ybf[(tc0 + wnd*SW + s)*DIv + ch] = __float2bfloat16(yy * zv);
        }
    }
}

// ---------------- head MLP (M=8): 320 -> 512 -> 512 -> 1 ----------------
__global__ void __launch_bounds__(512) k_head(
    const float* __restrict__ w1, const float* __restrict__ b1,
    const float* __restrict__ w2, const float* __restrict__ b2,
    const float* __restrict__ w3, const float* __restrict__ b3,
    float* __restrict__ out)
{
    __shared__ float sh [8][320];
    __shared__ float sh1[8][512];
    __shared__ float sh2[8][512];
    int tid = threadIdx.x;

    for (int idx = tid; idx < 8*320; idx += 512) {
        int bb = idx / 320, c = idx % 320;
        sh[bb][c] = g_bufA[((size_t)bb * Lq + Lq - 1) * DMv + c];
    }
    __syncthreads();

    {
        int n = tid;
        float acc[8];
        #pragma unroll
        for (int bb = 0; bb < 8; bb++) acc[bb] = 0.f;
        const float* wr = w1 + (size_t)n * 320;
        for (int k = 0; k < 320; k++) {
            float wv = wr[k];
            #pragma unroll
            for (int bb = 0; bb < 8; bb++) acc[bb] = fmaf(wv, sh[bb][k], acc[bb]);
        }
        #pragma unroll
        for (int bb = 0; bb < 8; bb++) sh1[bb][n] = fmaxf(acc[bb] + b1[n], 0.f);
    }
    __syncthreads();

    {
        int n = tid;
        float acc[8];
        #pragma unroll
        for (int bb = 0; bb < 8; bb++) acc[bb] = 0.f;
        const float* wr = w2 + (size_t)n * 512;
        for (int k = 0; k < 512; k++) {
            float wv = wr[k];
            #pragma unroll
            for (int bb = 0; bb < 8; bb++) acc[bb] = fmaf(wv, sh1[bb][k], acc[bb]);
        }
        #pragma unroll
        for (int bb = 0; bb < 8; bb++) sh2[bb][n] = fmaxf(acc[bb] + b2[n], 0.f);
    }
    __syncthreads();

    if (tid < 8) {
        float acc = 0.f;
        for (int k = 0; k < 512; k++) acc = fmaf(w3[k], sh2[tid][k], acc);
        acc += b3[0];
        float scale = g_startmax / (1.f + logf((float)Lq));
        out[tid] = fmaxf(acc * scale, 0.f);
    }
}

// ---------------- host launch ----------------
extern "C" void kernel_launch(void* const* d_in, const int* in_sizes, int n_in,
                              void* d_out, int out_size)
{
    const float* x            = (const float*)d_in[0];
    const float* fc_w         = (const float*)d_in[1];
    const float* fc_b         = (const float*)d_in[2];
    const float* blk_lin_w    = (const float*)d_in[3];
    const float* blk_lin_b    = (const float*)d_in[4];
    const float* blk_inproj_w = (const float*)d_in[5];
    const float* blk_conv_w   = (const float*)d_in[6];
    const float* blk_conv_b   = (const float*)d_in[7];
    const float* blk_xproj_w  = (const float*)d_in[8];
    const float* blk_dtproj_w = (const float*)d_in[9];
    const float* blk_dtproj_b = (const float*)d_in[10];
    const float* blk_A_log    = (const float*)d_in[11];
    const float* blk_D        = (const float*)d_in[12];
    const float* blk_outproj_w= (const float*)d_in[13];
    const float* s1_w1        = (const float*)d_in[14];
    const float* s1_b1        = (const float*)d_in[15];
    const float* s1_w2        = (const float*)d_in[16];
    const float* s1_b2        = (const float*)d_in[17];
    const float* s1_w3        = (const float*)d_in[18];
    const float* s1_b3        = (const float*)d_in[19];

    void* p;
    cudaGetSymbolAddress(&p, g_dbc);     float* dbc     = (float*)p;
    cudaGetSymbolAddress(&p, g_bufA);    float* bufA    = (float*)p;
    cudaGetSymbolAddress(&p, g_bufAbf);  bf16* bufAbf   = (bf16*)p;
    cudaGetSymbolAddress(&p, g_ubf);     bf16* ubf      = (bf16*)p;
    cudaGetSymbolAddress(&p, g_xzbf);    bf16* xzbf     = (bf16*)p;
    cudaGetSymbolAddress(&p, g_xconvbf); bf16* xconvbf  = (bf16*)p;
    cudaGetSymbolAddress(&p, g_dbcbf);   bf16* dbcbf    = (bf16*)p;
    cudaGetSymbolAddress(&p, g_deltabf); bf16* deltabf  = (bf16*)p;
    cudaGetSymbolAddress(&p, g_ybf);     bf16* ybf      = (bf16*)p;
    cudaGetSymbolAddress(&p, g_wlin);    bf16* wlin     = (bf16*)p;
    cudaGetSymbolAddress(&p, g_win);     bf16* win      = (bf16*)p;
    cudaGetSymbolAddress(&p, g_wxp);     bf16* wxp      = (bf16*)p;
    cudaGetSymbolAddress(&p, g_wdt);     bf16* wdt      = (bf16*)p;
    cudaGetSymbolAddress(&p, g_wout);    bf16* wout     = (bf16*)p;

    // merged weight conversion (1 launch)
    k_cvtall<<<(NQA + NDT + 255)/256, 256>>>(blk_lin_w, blk_inproj_w, blk_xproj_w,
                                             blk_dtproj_w, blk_outproj_w);
    k_startmax<<<1, 256>>>(x);
    k_embed<<<Tq, DMv>>>(x, fc_w, fc_b);

    for (int i = 0; i < NBLK; i++) {
        const float* Alog = blk_A_log + (size_t)i*DIv*NST;

        // lin: tanh(bufA @ lin_w^T + b) -> u(bf16)   [Tq,320] K=320
        k_bgemm<1><<<dim3(5, Tq/128), 256>>>(
            bufAbf, DMv, wlin + (size_t)i*DMv*DMv, DMv,
            blk_lin_b + (size_t)i*DMv,
            (float*)nullptr, 0, ubf, DMv, Tq, DMv, DMv);

        // inproj: u @ inproj_w^T -> xz(bf16, silu on z half)   [Tq,2560] K=320
        k_bgemm<4><<<dim3(40, Tq/128), 256>>>(
            ubf, DMv, win + (size_t)i*2*DIv*DMv, DMv,
            (const float*)nullptr,
            (float*)nullptr, 0, xzbf, 2*DIv, Tq, 2*DIv, DMv);

        // depthwise causal conv + silu -> xconv(bf16)
        k_conv<<<dim3(Tq/16, DIv/256), 256>>>(
            blk_conv_w + (size_t)i*DIv*DCONVK, blk_conv_b + (size_t)i*DIv);

        // xproj: xconv @ xproj_w^T -> dbc (f32) + dbcbf (bf16)   [Tq,52] K=1280
        k_bgemm<0><<<dim3(1, Tq/128), 256>>>(
            xconvbf, DIv, wxp + (size_t)i*XDv*DIv, DIv,
            (const float*)nullptr,
            dbc, XDv, dbcbf, 56, Tq, XDv, DIv);

        // dtproj: softplus(dbc[:, :20] @ dtproj_w^T + b) -> delta(bf16)   [Tq,1280] K=20
        k_bgemm<2><<<dim3(20, Tq/128), 256>>>(
            dbcbf, 56, wdt + (size_t)i*DIv*24, 24,
            blk_dtproj_b + (size_t)i*DIv,
            (float*)nullptr, 0, deltabf, DIv, Tq, DIv, DTRANK);

        // chunked selective scan -> y(bf16)
        k_scanA<<<dim3(DIv/SCH, Bq*NCH), SCH>>>(Alog);
        k_scanB<<<(Bq*NST*DIv + 255)/256, 256>>>(Alog);
        k_scanC<<<dim3(DIv/SCH, Bq*NCH), SCH>>>(Alog, blk_D + (size_t)i*DIv);

        // outproj: elu(y @ outproj_w^T) -> bufA (f32 + bf16)   [Tq,320] K=1280
        k_bgemm<3><<<dim3(5, Tq/128), 256>>>(
            ybf, DIv, wout + (size_t)i*DMv*DIv, DIv,
            (const float*)nullptr,
            bufA, DMv, bufAbf, DMv, Tq, DMv, DIv);
    }

    k_head<<<1, 512>>>(s1_w1, s1_b1, s1_w2, s1_b2, s1_w3, s1_b3, (float*)d_out);
}